// round 1
// baseline (speedup 1.0000x reference)
#include <cuda_runtime.h>
#include <cmath>

// Problem constants
constexpr int Bc  = 2;
constexpr int Sc  = 2048;
constexpr int Ec  = 1024;
constexpr int Hc  = 16;
constexpr int HDc = 64;
constexpr int Mc  = Bc * Sc;        // 4096 rows
constexpr int NQKV = 3 * Ec;        // 3072
constexpr int RHALF = 32;           // rotary pairs per head (ROT=64)

// Scratch (static device globals; no allocation)
__device__ float g_qkv[(size_t)Mc * NQKV];              // 50.3 MB
__device__ float g_q[(size_t)Bc * Hc * Sc * HDc];
__device__ float g_k[(size_t)Bc * Hc * Sc * HDc];
__device__ float g_v[(size_t)Bc * Hc * Sc * HDc];
__device__ float g_ctx[(size_t)Mc * Ec];
__device__ float g_cos[Sc * RHALF];
__device__ float g_sin[Sc * RHALF];

// ---------------------------------------------------------------------------
// RoPE cos/sin table (double precision to match jax fp32 reference closely)
// ---------------------------------------------------------------------------
__global__ void rope_table_kernel() {
    int idx = blockIdx.x * blockDim.x + threadIdx.x;
    if (idx >= Sc * RHALF) return;
    int s = idx / RHALF;
    int i = idx % RHALF;
    double inv_freq = exp(-(double)(2 * i) / 64.0 * log(10000.0));
    double ang = (double)s * inv_freq;
    g_cos[idx] = (float)cos(ang);
    g_sin[idx] = (float)sin(ang);
}

// ---------------------------------------------------------------------------
// SGEMM NT + bias: C[M,N] = A[M,K] @ W[N,K]^T + bias[N]
// 128x128 block tile, BK=8, 256 threads, 8x8 per thread.
// M,N,K all multiples of 128/8 here -> no bounds checks.
// ---------------------------------------------------------------------------
__global__ __launch_bounds__(256) void sgemm_nt_bias(
    const float* __restrict__ A, const float* __restrict__ W,
    const float* __restrict__ bias, float* __restrict__ C,
    int Mdim, int Ndim, int Kdim)
{
    __shared__ float As[8][128];
    __shared__ float Bs[8][128];

    const int tid = threadIdx.x;
    const int ty = tid >> 4;       // 0..15
    const int tx = tid & 15;       // 0..15
    const int rowBase = blockIdx.y * 128;
    const int colBase = blockIdx.x * 128;

    float acc[8][8];
#pragma unroll
    for (int i = 0; i < 8; i++)
#pragma unroll
        for (int j = 0; j < 8; j++) acc[i][j] = 0.f;

    const int lr = tid >> 1;          // 0..127
    const int lc = (tid & 1) * 4;     // 0 or 4
    const float* Ap = A + (size_t)(rowBase + lr) * Kdim + lc;
    const float* Wp = W + (size_t)(colBase + lr) * Kdim + lc;

    for (int k0 = 0; k0 < Kdim; k0 += 8) {
        float4 av = *(const float4*)(Ap + k0);
        float4 wv = *(const float4*)(Wp + k0);
        __syncthreads();
        As[lc + 0][lr] = av.x; As[lc + 1][lr] = av.y;
        As[lc + 2][lr] = av.z; As[lc + 3][lr] = av.w;
        Bs[lc + 0][lr] = wv.x; Bs[lc + 1][lr] = wv.y;
        Bs[lc + 2][lr] = wv.z; Bs[lc + 3][lr] = wv.w;
        __syncthreads();
#pragma unroll
        for (int kk = 0; kk < 8; kk++) {
            float a[8], b[8];
            *(float4*)&a[0] = *(const float4*)&As[kk][ty * 8];
            *(float4*)&a[4] = *(const float4*)&As[kk][ty * 8 + 4];
            *(float4*)&b[0] = *(const float4*)&Bs[kk][tx * 8];
            *(float4*)&b[4] = *(const float4*)&Bs[kk][tx * 8 + 4];
#pragma unroll
            for (int i = 0; i < 8; i++)
#pragma unroll
                for (int j = 0; j < 8; j++)
                    acc[i][j] += a[i] * b[j];
        }
    }

    // Epilogue: add bias, store
    float bvals[8];
#pragma unroll
    for (int j = 0; j < 8; j++) bvals[j] = bias[colBase + tx * 8 + j];
#pragma unroll
    for (int i = 0; i < 8; i++) {
        int m = rowBase + ty * 8 + i;
        float4 o0, o1;
        o0.x = acc[i][0] + bvals[0]; o0.y = acc[i][1] + bvals[1];
        o0.z = acc[i][2] + bvals[2]; o0.w = acc[i][3] + bvals[3];
        o1.x = acc[i][4] + bvals[4]; o1.y = acc[i][5] + bvals[5];
        o1.z = acc[i][6] + bvals[6]; o1.w = acc[i][7] + bvals[7];
        float* cp = C + (size_t)m * Ndim + colBase + tx * 8;
        *(float4*)cp = o0;
        *(float4*)(cp + 4) = o1;
    }
}

// ---------------------------------------------------------------------------
// Split QKV -> [B,H,S,HD] layout, with RoPE applied to Q and K (full head).
// One thread per rotary pair.
// ---------------------------------------------------------------------------
__global__ void split_rope_kernel() {
    int idx = blockIdx.x * blockDim.x + threadIdx.x;   // B*S*H*32 total
    int i = idx & 31;
    int h = (idx >> 5) & 15;
    int s = (idx >> 9) & (Sc - 1);
    int b = idx >> 20;                                  // 32*16*2048 = 2^20

    int row = b * Sc + s;
    const float* src = g_qkv + (size_t)row * NQKV + h * HDc + 2 * i;
    float q0 = src[0],        q1 = src[1];
    float k0 = src[Ec],       k1 = src[Ec + 1];
    float v0 = src[2 * Ec],   v1 = src[2 * Ec + 1];

    float c  = g_cos[s * RHALF + i];
    float sn = g_sin[s * RHALF + i];

    size_t dst = (((size_t)(b * Hc + h)) * Sc + s) * HDc + 2 * i;
    g_q[dst]     = q0 * c - q1 * sn;
    g_q[dst + 1] = q1 * c + q0 * sn;
    g_k[dst]     = k0 * c - k1 * sn;
    g_k[dst + 1] = k1 * c + k0 * sn;
    g_v[dst]     = v0;
    g_v[dst + 1] = v1;
}

// ---------------------------------------------------------------------------
// Flash attention, fp32. 64 q-rows per block, 64-wide k tiles, HD=64.
// 256 threads as 16x16; each thread owns a 4(q) x 4(k or d) microtile.
// Smem: QsT/KsT d-major [64][64], Vs k-major [64][64],
//       Ps XOR-swizzled float4 (k, q4) to keep both store & load conflict-low.
// ---------------------------------------------------------------------------
__global__ __launch_bounds__(256) void attn_kernel(const int* __restrict__ mask)
{
    extern __shared__ float sm[];
    float* QsT = sm;                 // [d][q]
    float* KsT = sm + 4096;          // [d][k]
    float* Vs  = sm + 8192;          // [k][d]
    float* Ps  = sm + 12288;         // swizzled [k][q]
    float* mb  = sm + 16384;         // [64] mask bias

    const int tid = threadIdx.x;
    const int ty = tid >> 4;         // q group
    const int tx = tid & 15;         // k / d group
    const int bh = blockIdx.y;
    const int b = bh >> 4, h = bh & 15;
    const int q0 = blockIdx.x * 64;

    const float* Qg = g_q + (size_t)bh * Sc * HDc + (size_t)q0 * HDc;
    const float* Kg = g_k + (size_t)bh * Sc * HDc;
    const float* Vg = g_v + (size_t)bh * Sc * HDc;
    const int* mg = mask + b * Sc;

    // Load Q tile, transposed to d-major
#pragma unroll
    for (int u = 0; u < 4; u++) {
        int lin = u * 256 + tid;
        int r = lin >> 4, d4 = (lin & 15) * 4;
        float4 v = *(const float4*)(Qg + r * HDc + d4);
        QsT[(d4 + 0) * 64 + r] = v.x;
        QsT[(d4 + 1) * 64 + r] = v.y;
        QsT[(d4 + 2) * 64 + r] = v.z;
        QsT[(d4 + 3) * 64 + r] = v.w;
    }

    float o[4][4];
    float mo[4], l[4];
#pragma unroll
    for (int qi = 0; qi < 4; qi++) {
        mo[qi] = -1e30f; l[qi] = 0.f;
#pragma unroll
        for (int dj = 0; dj < 4; dj++) o[qi][dj] = 0.f;
    }
    const float scale = 0.125f;  // 1/sqrt(64)

    for (int k0 = 0; k0 < Sc; k0 += 64) {
        __syncthreads();  // previous iteration's Ps/Vs reads done (also Q load)
#pragma unroll
        for (int u = 0; u < 4; u++) {
            int lin = u * 256 + tid;
            int r = lin >> 4, d4 = (lin & 15) * 4;
            float4 kv4 = *(const float4*)(Kg + (size_t)(k0 + r) * HDc + d4);
            KsT[(d4 + 0) * 64 + r] = kv4.x;
            KsT[(d4 + 1) * 64 + r] = kv4.y;
            KsT[(d4 + 2) * 64 + r] = kv4.z;
            KsT[(d4 + 3) * 64 + r] = kv4.w;
            float4 vv4 = *(const float4*)(Vg + (size_t)(k0 + r) * HDc + d4);
            *(float4*)&Vs[r * 64 + d4] = vv4;
        }
        if (tid < 64) mb[tid] = mg[k0 + tid] ? 0.f : -1e30f;
        __syncthreads();

        // S = Q K^T (thread: 4 q-rows x 4 k-cols)
        float s[4][4];
#pragma unroll
        for (int qi = 0; qi < 4; qi++)
#pragma unroll
            for (int kj = 0; kj < 4; kj++) s[qi][kj] = 0.f;
#pragma unroll 8
        for (int kk = 0; kk < 64; kk++) {
            float4 qa = *(const float4*)&QsT[kk * 64 + ty * 4];
            float4 kb = *(const float4*)&KsT[kk * 64 + tx * 4];
            float qar[4] = {qa.x, qa.y, qa.z, qa.w};
            float kbr[4] = {kb.x, kb.y, kb.z, kb.w};
#pragma unroll
            for (int qi = 0; qi < 4; qi++)
#pragma unroll
                for (int kj = 0; kj < 4; kj++)
                    s[qi][kj] += qar[qi] * kbr[kj];
        }
#pragma unroll
        for (int qi = 0; qi < 4; qi++)
#pragma unroll
            for (int kj = 0; kj < 4; kj++)
                s[qi][kj] = s[qi][kj] * scale + mb[tx * 4 + kj];

        // Online softmax (row stats reduced over the 16 tx lanes)
        float p[4][4];
#pragma unroll
        for (int qi = 0; qi < 4; qi++) {
            float mx = fmaxf(fmaxf(s[qi][0], s[qi][1]), fmaxf(s[qi][2], s[qi][3]));
#pragma unroll
            for (int off = 8; off > 0; off >>= 1)
                mx = fmaxf(mx, __shfl_xor_sync(0xffffffffu, mx, off));
            float mn = fmaxf(mo[qi], mx);
            float al = __expf(mo[qi] - mn);
            float rs = 0.f;
#pragma unroll
            for (int kj = 0; kj < 4; kj++) {
                p[qi][kj] = __expf(s[qi][kj] - mn);
                rs += p[qi][kj];
            }
#pragma unroll
            for (int off = 8; off > 0; off >>= 1)
                rs += __shfl_xor_sync(0xffffffffu, rs, off);
            l[qi] = l[qi] * al + rs;
            mo[qi] = mn;
#pragma unroll
            for (int dj = 0; dj < 4; dj++) o[qi][dj] *= al;
        }

        // Store P, swizzled: element (k,q) -> float4 slot k*16 + (q4 ^ (k&15))
#pragma unroll
        for (int kj = 0; kj < 4; kj++) {
            int kcol = tx * 4 + kj;
            int slot = ty ^ (kcol & 15);
            *(float4*)&Ps[(kcol * 16 + slot) * 4] =
                make_float4(p[0][kj], p[1][kj], p[2][kj], p[3][kj]);
        }
        __syncthreads();

        // O += P V (thread: 4 q-rows x 4 dims)
#pragma unroll 8
        for (int kk = 0; kk < 64; kk++) {
            int slot = ty ^ (kk & 15);
            float4 pa = *(const float4*)&Ps[(kk * 16 + slot) * 4];
            float4 vb = *(const float4*)&Vs[kk * 64 + tx * 4];
            float par[4] = {pa.x, pa.y, pa.z, pa.w};
            float vbr[4] = {vb.x, vb.y, vb.z, vb.w};
#pragma unroll
            for (int qi = 0; qi < 4; qi++)
#pragma unroll
                for (int dj = 0; dj < 4; dj++)
                    o[qi][dj] += par[qi] * vbr[dj];
        }
    }

    // Write context in [b, s, h*64+d] layout (rows of the out-proj GEMM)
#pragma unroll
    for (int qi = 0; qi < 4; qi++) {
        float inv = 1.f / l[qi];
        int q = q0 + ty * 4 + qi;
        float4 ov = make_float4(o[qi][0] * inv, o[qi][1] * inv,
                                o[qi][2] * inv, o[qi][3] * inv);
        *(float4*)&g_ctx[((size_t)(b * Sc + q)) * Ec + h * HDc + tx * 4] = ov;
    }
}

// ---------------------------------------------------------------------------
extern "C" void kernel_launch(void* const* d_in, const int* in_sizes, int n_in,
                              void* d_out, int out_size)
{
    const float* x     = (const float*)d_in[0];
    const int*   mask  = (const int*)d_in[1];
    const float* qkv_w = (const float*)d_in[2];
    const float* qkv_b = (const float*)d_in[3];
    const float* out_w = (const float*)d_in[4];
    const float* out_b = (const float*)d_in[5];
    float* out = (float*)d_out;

    float *qkv_ptr = nullptr, *ctx_ptr = nullptr;
    cudaGetSymbolAddress((void**)&qkv_ptr, g_qkv);
    cudaGetSymbolAddress((void**)&ctx_ptr, g_ctx);

    // 1. RoPE tables
    rope_table_kernel<<<(Sc * RHALF + 255) / 256, 256>>>();

    // 2. QKV projection: [4096,3072] = x[4096,1024] @ qkv_w^T + b
    sgemm_nt_bias<<<dim3(NQKV / 128, Mc / 128), 256>>>(
        x, qkv_w, qkv_b, qkv_ptr, Mc, NQKV, Ec);

    // 3. Split + RoPE into [B,H,S,HD]
    split_rope_kernel<<<(Bc * Sc * Hc * RHALF) / 256, 256>>>();

    // 4. Flash attention
    int smem_bytes = (16384 + 64) * sizeof(float);   // 65792
    cudaFuncSetAttribute(attn_kernel,
                         cudaFuncAttributeMaxDynamicSharedMemorySize, smem_bytes);
    attn_kernel<<<dim3(Sc / 64, Bc * Hc), 256, smem_bytes>>>(mask);

    // 5. Output projection: out[4096,1024] = ctx @ out_w^T + out_b
    sgemm_nt_bias<<<dim3(Ec / 128, Mc / 128), 256>>>(
        ctx_ptr, out_w, out_b, out, Mc, Ec, Ec);
}

// round 3
// speedup vs baseline: 1.3525x; 1.3525x over previous
#include <cuda_runtime.h>
#include <cuda_bf16.h>
#include <cstdint>
#include <cmath>

// Problem constants
constexpr int Bc  = 2;
constexpr int Sc  = 2048;
constexpr int Ec  = 1024;
constexpr int Hc  = 16;
constexpr int HDc = 64;
constexpr int Mc  = Bc * Sc;        // 4096 rows
constexpr int NQKV = 3 * Ec;        // 3072
constexpr int RHALF = 32;           // rotary pairs per head (ROT=64)
constexpr int GK = 1024;            // K dim of both projection GEMMs

// Scratch (static device globals; no allocation)
__device__ float g_qkv[(size_t)Mc * NQKV];
__device__ float g_q[(size_t)Bc * Hc * Sc * HDc];
__device__ float g_k[(size_t)Bc * Hc * Sc * HDc];
__device__ float g_v[(size_t)Bc * Hc * Sc * HDc];
__device__ float g_ctx[(size_t)Mc * Ec];
__device__ float g_cos[Sc * RHALF];
__device__ float g_sin[Sc * RHALF];

// bf16 split buffers
__device__ __nv_bfloat16 g_xhi[(size_t)Mc * Ec];
__device__ __nv_bfloat16 g_xlo[(size_t)Mc * Ec];
__device__ __nv_bfloat16 g_wqkv_hi[(size_t)NQKV * Ec];
__device__ __nv_bfloat16 g_wqkv_lo[(size_t)NQKV * Ec];
__device__ __nv_bfloat16 g_wout_hi[(size_t)Ec * Ec];
__device__ __nv_bfloat16 g_wout_lo[(size_t)Ec * Ec];
__device__ __nv_bfloat16 g_ctx_hi[(size_t)Mc * Ec];
__device__ __nv_bfloat16 g_ctx_lo[(size_t)Mc * Ec];

// ---------------------------------------------------------------------------
// Portable (compute_103-safe) tensor-core helpers: ldmatrix + mma.sync + cp.async
// ---------------------------------------------------------------------------
__device__ __forceinline__ uint32_t smem_to_u32(const void* p) {
    uint32_t a;
    asm("{ .reg .u64 t; cvta.to.shared.u64 t, %1; cvt.u32.u64 %0, t; }"
        : "=r"(a) : "l"(p));
    return a;
}

__device__ __forceinline__ void cp16(uint32_t dst, const void* src) {
    asm volatile("cp.async.cg.shared.global [%0], [%1], 16;"
                 :: "r"(dst), "l"(src));
}

__device__ __forceinline__ void ldsm_x4(uint4& r, uint32_t addr) {
    asm volatile("ldmatrix.sync.aligned.m8n8.x4.shared.b16 {%0,%1,%2,%3}, [%4];"
                 : "=r"(r.x), "=r"(r.y), "=r"(r.z), "=r"(r.w) : "r"(addr));
}
__device__ __forceinline__ void ldsm_x2(uint2& r, uint32_t addr) {
    asm volatile("ldmatrix.sync.aligned.m8n8.x2.shared.b16 {%0,%1}, [%2];"
                 : "=r"(r.x), "=r"(r.y) : "r"(addr));
}

__device__ __forceinline__ void mma16816(float* d, const uint4& a, const uint2& b) {
    asm volatile(
        "mma.sync.aligned.m16n8k16.row.col.f32.bf16.bf16.f32 "
        "{%0,%1,%2,%3}, {%4,%5,%6,%7}, {%8,%9}, {%0,%1,%2,%3};"
        : "+f"(d[0]), "+f"(d[1]), "+f"(d[2]), "+f"(d[3])
        : "r"(a.x), "r"(a.y), "r"(a.z), "r"(a.w), "r"(b.x), "r"(b.y));
}

// ---------------------------------------------------------------------------
// RoPE cos/sin table
// ---------------------------------------------------------------------------
__global__ void rope_table_kernel() {
    int idx = blockIdx.x * blockDim.x + threadIdx.x;
    if (idx >= Sc * RHALF) return;
    int s = idx / RHALF;
    int i = idx % RHALF;
    double inv_freq = exp(-(double)(2 * i) / 64.0 * log(10000.0));
    double ang = (double)s * inv_freq;
    g_cos[idx] = (float)cos(ang);
    g_sin[idx] = (float)sin(ang);
}

// ---------------------------------------------------------------------------
// fp32 -> (bf16 hi, bf16 lo) split; lo = bf16(x - float(hi))
// ---------------------------------------------------------------------------
__global__ void split_bf16_kernel(const float* __restrict__ src,
                                  __nv_bfloat16* __restrict__ hi,
                                  __nv_bfloat16* __restrict__ lo, int n4) {
    int i = blockIdx.x * blockDim.x + threadIdx.x;
    if (i >= n4) return;
    float4 v = ((const float4*)src)[i];
    __nv_bfloat16 h0 = __float2bfloat16_rn(v.x);
    __nv_bfloat16 h1 = __float2bfloat16_rn(v.y);
    __nv_bfloat16 h2 = __float2bfloat16_rn(v.z);
    __nv_bfloat16 h3 = __float2bfloat16_rn(v.w);
    __nv_bfloat16 l0 = __float2bfloat16_rn(v.x - __bfloat162float(h0));
    __nv_bfloat16 l1 = __float2bfloat16_rn(v.y - __bfloat162float(h1));
    __nv_bfloat16 l2 = __float2bfloat16_rn(v.z - __bfloat162float(h2));
    __nv_bfloat16 l3 = __float2bfloat16_rn(v.w - __bfloat162float(h3));
    __nv_bfloat162* hp = (__nv_bfloat162*)hi;
    __nv_bfloat162* lp = (__nv_bfloat162*)lo;
    hp[2 * i]     = __nv_bfloat162(h0, h1);
    hp[2 * i + 1] = __nv_bfloat162(h2, h3);
    lp[2 * i]     = __nv_bfloat162(l0, l1);
    lp[2 * i + 1] = __nv_bfloat162(l2, l3);
}

// ---------------------------------------------------------------------------
// Warp-mma split-bf16 GEMM: C[M,N] = A[M,K] @ W[N,K]^T + bias
//   C = Ahi@Bhi^T + Ahi@Blo^T + Alo@Bhi^T   (fp32 accumulators)
// 128x128 CTA tile, BK=64, 8 warps (each 64x32), double-buffered cp.async.
// K fixed at 1024 -> 16 chunks x 3 passes = 48 chunks.
// Smem rows padded to 144B (64 bf16 data + 16B pad) -> ldmatrix conflict-free.
// ---------------------------------------------------------------------------
constexpr int GP_PITCH = 144;                   // bytes per smem row
constexpr int GP_TILE  = 128 * GP_PITCH;        // 18432 B per operand tile
constexpr int GP_BUF   = 2 * GP_TILE;           // A + B per buffer
constexpr int GP_SMEM  = 2 * GP_BUF;            // 73728 B

__global__ __launch_bounds__(256) void gemm_mma_bf16x3(
    const __nv_bfloat16* __restrict__ Ahi, const __nv_bfloat16* __restrict__ Alo,
    const __nv_bfloat16* __restrict__ Bhi, const __nv_bfloat16* __restrict__ Blo,
    const float* __restrict__ bias, float* __restrict__ C, int Ndim)
{
    extern __shared__ char smg[];
    const uint32_t sb = smem_to_u32(smg);
    const int tid = threadIdx.x;
    const int lane = tid & 31;
    const int wid = tid >> 5;
    const int rowBase = blockIdx.y * 128;
    const int colBase = blockIdx.x * 128;
    const int wm = (wid >> 2) * 64;     // warp m offset in tile
    const int wn = (wid & 3) * 32;      // warp n offset in tile

    float acc[4][4][4];
#pragma unroll
    for (int mi = 0; mi < 4; mi++)
#pragma unroll
        for (int ni = 0; ni < 4; ni++)
#pragma unroll
            for (int e = 0; e < 4; e++) acc[mi][ni][e] = 0.f;

    // async-copy one chunk (A and B 128x64 bf16 tiles) into buffer (c&1)
    auto issue = [&](int c) {
        const __nv_bfloat16* Asrc = (c < 32) ? Ahi : Alo;
        const __nv_bfloat16* Bsrc = (c >= 16 && c < 32) ? Blo : Bhi;
        const int k0 = (c & 15) * 64;
        const uint32_t dst = sb + (uint32_t)(c & 1) * GP_BUF;
#pragma unroll
        for (int u = 0; u < 4; u++) {
            int lin = u * 256 + tid;
            int r = lin >> 3, seg = lin & 7;
            cp16(dst + r * GP_PITCH + seg * 16,
                 Asrc + (size_t)(rowBase + r) * GK + k0 + seg * 8);
            cp16(dst + GP_TILE + r * GP_PITCH + seg * 16,
                 Bsrc + (size_t)(colBase + r) * GK + k0 + seg * 8);
        }
        asm volatile("cp.async.commit_group;" ::: "memory");
    };

    issue(0);
    for (int c = 0; c < 48; c++) {
        if (c < 47) {
            issue(c + 1);
            asm volatile("cp.async.wait_group 1;" ::: "memory");
        } else {
            asm volatile("cp.async.wait_group 0;" ::: "memory");
        }
        __syncthreads();

        const uint32_t Ab = sb + (uint32_t)(c & 1) * GP_BUF;
        const uint32_t Bb = Ab + GP_TILE;
#pragma unroll
        for (int ks = 0; ks < 4; ks++) {
            uint4 a[4];
            uint2 b[4];
#pragma unroll
            for (int mi = 0; mi < 4; mi++)
                ldsm_x4(a[mi], Ab + (wm + mi * 16 + (lane & 15)) * GP_PITCH
                               + (ks * 16 + (lane >> 4) * 8) * 2);
#pragma unroll
            for (int ni = 0; ni < 4; ni++)
                ldsm_x2(b[ni], Bb + (wn + ni * 8 + (lane & 7)) * GP_PITCH
                               + (ks * 16 + ((lane >> 3) & 1) * 8) * 2);
#pragma unroll
            for (int mi = 0; mi < 4; mi++)
#pragma unroll
                for (int ni = 0; ni < 4; ni++)
                    mma16816(acc[mi][ni], a[mi], b[ni]);
        }
        __syncthreads();
    }

    // Epilogue: bias + store (acc layout: rows lane>>2 / +8, cols 2*(lane&3))
#pragma unroll
    for (int mi = 0; mi < 4; mi++) {
#pragma unroll
        for (int ni = 0; ni < 4; ni++) {
            int r0 = rowBase + wm + mi * 16 + (lane >> 2);
            int col = colBase + wn + ni * 8 + (lane & 3) * 2;
            float b0 = bias[col], b1 = bias[col + 1];
            float2 v0 = make_float2(acc[mi][ni][0] + b0, acc[mi][ni][1] + b1);
            float2 v1 = make_float2(acc[mi][ni][2] + b0, acc[mi][ni][3] + b1);
            *(float2*)&C[(size_t)r0 * Ndim + col] = v0;
            *(float2*)&C[(size_t)(r0 + 8) * Ndim + col] = v1;
        }
    }
}

// ---------------------------------------------------------------------------
// Split QKV -> [B,H,S,HD] layout, with RoPE applied to Q and K.
// ---------------------------------------------------------------------------
__global__ void split_rope_kernel() {
    int idx = blockIdx.x * blockDim.x + threadIdx.x;
    int i = idx & 31;
    int h = (idx >> 5) & 15;
    int s = (idx >> 9) & (Sc - 1);
    int b = idx >> 20;

    int row = b * Sc + s;
    const float* src = g_qkv + (size_t)row * NQKV + h * HDc + 2 * i;
    float q0 = src[0],        q1 = src[1];
    float k0 = src[Ec],       k1 = src[Ec + 1];
    float v0 = src[2 * Ec],   v1 = src[2 * Ec + 1];

    float c  = g_cos[s * RHALF + i];
    float sn = g_sin[s * RHALF + i];

    size_t dst = (((size_t)(b * Hc + h)) * Sc + s) * HDc + 2 * i;
    g_q[dst]     = q0 * c - q1 * sn;
    g_q[dst + 1] = q1 * c + q0 * sn;
    g_k[dst]     = k0 * c - k1 * sn;
    g_k[dst + 1] = k1 * c + k0 * sn;
    g_v[dst]     = v0;
    g_v[dst + 1] = v1;
}

// ---------------------------------------------------------------------------
// Flash attention, fp32 SIMT (at SIMT roofline; mma conversion next round).
// ---------------------------------------------------------------------------
__global__ __launch_bounds__(256) void attn_kernel(const int* __restrict__ mask)
{
    extern __shared__ float sm[];
    float* QsT = sm;                 // [d][q]
    float* KsT = sm + 4096;          // [d][k]
    float* Vs  = sm + 8192;          // [k][d]
    float* Ps  = sm + 12288;         // swizzled [k][q]
    float* mb  = sm + 16384;         // [64] mask bias

    const int tid = threadIdx.x;
    const int ty = tid >> 4;
    const int tx = tid & 15;
    const int bh = blockIdx.y;
    const int b = bh >> 4;
    const int q0 = blockIdx.x * 64;

    const float* Qg = g_q + (size_t)bh * Sc * HDc + (size_t)q0 * HDc;
    const float* Kg = g_k + (size_t)bh * Sc * HDc;
    const float* Vg = g_v + (size_t)bh * Sc * HDc;
    const int* mg = mask + b * Sc;
    const int h = bh & 15;

#pragma unroll
    for (int u = 0; u < 4; u++) {
        int lin = u * 256 + tid;
        int r = lin >> 4, d4 = (lin & 15) * 4;
        float4 v = *(const float4*)(Qg + r * HDc + d4);
        QsT[(d4 + 0) * 64 + r] = v.x;
        QsT[(d4 + 1) * 64 + r] = v.y;
        QsT[(d4 + 2) * 64 + r] = v.z;
        QsT[(d4 + 3) * 64 + r] = v.w;
    }

    float o[4][4];
    float mo[4], l[4];
#pragma unroll
    for (int qi = 0; qi < 4; qi++) {
        mo[qi] = -1e30f; l[qi] = 0.f;
#pragma unroll
        for (int dj = 0; dj < 4; dj++) o[qi][dj] = 0.f;
    }
    const float scale = 0.125f;

    for (int k0 = 0; k0 < Sc; k0 += 64) {
        __syncthreads();
#pragma unroll
        for (int u = 0; u < 4; u++) {
            int lin = u * 256 + tid;
            int r = lin >> 4, d4 = (lin & 15) * 4;
            float4 kv4 = *(const float4*)(Kg + (size_t)(k0 + r) * HDc + d4);
            KsT[(d4 + 0) * 64 + r] = kv4.x;
            KsT[(d4 + 1) * 64 + r] = kv4.y;
            KsT[(d4 + 2) * 64 + r] = kv4.z;
            KsT[(d4 + 3) * 64 + r] = kv4.w;
            float4 vv4 = *(const float4*)(Vg + (size_t)(k0 + r) * HDc + d4);
            *(float4*)&Vs[r * 64 + d4] = vv4;
        }
        if (tid < 64) mb[tid] = mg[k0 + tid] ? 0.f : -1e30f;
        __syncthreads();

        float s[4][4];
#pragma unroll
        for (int qi = 0; qi < 4; qi++)
#pragma unroll
            for (int kj = 0; kj < 4; kj++) s[qi][kj] = 0.f;
#pragma unroll 8
        for (int kk = 0; kk < 64; kk++) {
            float4 qa = *(const float4*)&QsT[kk * 64 + ty * 4];
            float4 kb = *(const float4*)&KsT[kk * 64 + tx * 4];
            float qar[4] = {qa.x, qa.y, qa.z, qa.w};
            float kbr[4] = {kb.x, kb.y, kb.z, kb.w};
#pragma unroll
            for (int qi = 0; qi < 4; qi++)
#pragma unroll
                for (int kj = 0; kj < 4; kj++)
                    s[qi][kj] += qar[qi] * kbr[kj];
        }
#pragma unroll
        for (int qi = 0; qi < 4; qi++)
#pragma unroll
            for (int kj = 0; kj < 4; kj++)
                s[qi][kj] = s[qi][kj] * scale + mb[tx * 4 + kj];

        float p[4][4];
#pragma unroll
        for (int qi = 0; qi < 4; qi++) {
            float mx = fmaxf(fmaxf(s[qi][0], s[qi][1]), fmaxf(s[qi][2], s[qi][3]));
#pragma unroll
            for (int off = 8; off > 0; off >>= 1)
                mx = fmaxf(mx, __shfl_xor_sync(0xffffffffu, mx, off));
            float mn = fmaxf(mo[qi], mx);
            float al = __expf(mo[qi] - mn);
            float rs = 0.f;
#pragma unroll
            for (int kj = 0; kj < 4; kj++) {
                p[qi][kj] = __expf(s[qi][kj] - mn);
                rs += p[qi][kj];
            }
#pragma unroll
            for (int off = 8; off > 0; off >>= 1)
                rs += __shfl_xor_sync(0xffffffffu, rs, off);
            l[qi] = l[qi] * al + rs;
            mo[qi] = mn;
#pragma unroll
            for (int dj = 0; dj < 4; dj++) o[qi][dj] *= al;
        }

#pragma unroll
        for (int kj = 0; kj < 4; kj++) {
            int kcol = tx * 4 + kj;
            int slot = ty ^ (kcol & 15);
            *(float4*)&Ps[(kcol * 16 + slot) * 4] =
                make_float4(p[0][kj], p[1][kj], p[2][kj], p[3][kj]);
        }
        __syncthreads();

#pragma unroll 8
        for (int kk = 0; kk < 64; kk++) {
            int slot = ty ^ (kk & 15);
            float4 pa = *(const float4*)&Ps[(kk * 16 + slot) * 4];
            float4 vb = *(const float4*)&Vs[kk * 64 + tx * 4];
            float par[4] = {pa.x, pa.y, pa.z, pa.w};
            float vbr[4] = {vb.x, vb.y, vb.z, vb.w};
#pragma unroll
            for (int qi = 0; qi < 4; qi++)
#pragma unroll
                for (int dj = 0; dj < 4; dj++)
                    o[qi][dj] += par[qi] * vbr[dj];
        }
    }

#pragma unroll
    for (int qi = 0; qi < 4; qi++) {
        float inv = 1.f / l[qi];
        int q = q0 + ty * 4 + qi;
        float4 ov = make_float4(o[qi][0] * inv, o[qi][1] * inv,
                                o[qi][2] * inv, o[qi][3] * inv);
        *(float4*)&g_ctx[((size_t)(b * Sc + q)) * Ec + h * HDc + tx * 4] = ov;
    }
}

// ---------------------------------------------------------------------------
extern "C" void kernel_launch(void* const* d_in, const int* in_sizes, int n_in,
                              void* d_out, int out_size)
{
    const float* x     = (const float*)d_in[0];
    const int*   mask  = (const int*)d_in[1];
    const float* qkv_w = (const float*)d_in[2];
    const float* qkv_b = (const float*)d_in[3];
    const float* out_w = (const float*)d_in[4];
    const float* out_b = (const float*)d_in[5];
    float* out = (float*)d_out;

    float *qkv_ptr = nullptr, *ctx_ptr = nullptr;
    cudaGetSymbolAddress((void**)&qkv_ptr, g_qkv);
    cudaGetSymbolAddress((void**)&ctx_ptr, g_ctx);
    __nv_bfloat16 *xhi, *xlo, *whi, *wlo, *owhi, *owlo, *chi, *clo;
    cudaGetSymbolAddress((void**)&xhi,  g_xhi);
    cudaGetSymbolAddress((void**)&xlo,  g_xlo);
    cudaGetSymbolAddress((void**)&whi,  g_wqkv_hi);
    cudaGetSymbolAddress((void**)&wlo,  g_wqkv_lo);
    cudaGetSymbolAddress((void**)&owhi, g_wout_hi);
    cudaGetSymbolAddress((void**)&owlo, g_wout_lo);
    cudaGetSymbolAddress((void**)&chi,  g_ctx_hi);
    cudaGetSymbolAddress((void**)&clo,  g_ctx_lo);

    cudaFuncSetAttribute(gemm_mma_bf16x3,
                         cudaFuncAttributeMaxDynamicSharedMemorySize, GP_SMEM);
    int attn_smem = (16384 + 64) * sizeof(float);
    cudaFuncSetAttribute(attn_kernel,
                         cudaFuncAttributeMaxDynamicSharedMemorySize, attn_smem);

    // 1. RoPE tables
    rope_table_kernel<<<(Sc * RHALF + 255) / 256, 256>>>();

    // 2. Split inputs/weights into bf16 hi/lo
    split_bf16_kernel<<<(Mc * Ec / 4 + 255) / 256, 256>>>(x, xhi, xlo, Mc * Ec / 4);
    split_bf16_kernel<<<(NQKV * Ec / 4 + 255) / 256, 256>>>(qkv_w, whi, wlo, NQKV * Ec / 4);
    split_bf16_kernel<<<(Ec * Ec / 4 + 255) / 256, 256>>>(out_w, owhi, owlo, Ec * Ec / 4);

    // 3. QKV projection (warp-mma): qkv[4096,3072] = x @ qkv_w^T + b
    gemm_mma_bf16x3<<<dim3(NQKV / 128, Mc / 128), 256, GP_SMEM>>>(
        xhi, xlo, whi, wlo, qkv_b, qkv_ptr, NQKV);

    // 4. Split + RoPE into [B,H,S,HD]
    split_rope_kernel<<<(Bc * Sc * Hc * RHALF) / 256, 256>>>();

    // 5. Flash attention (fp32 SIMT)
    attn_kernel<<<dim3(Sc / 64, Bc * Hc), 256, attn_smem>>>(mask);

    // 6. Split context, output projection (warp-mma)
    split_bf16_kernel<<<(Mc * Ec / 4 + 255) / 256, 256>>>(ctx_ptr, chi, clo, Mc * Ec / 4);
    gemm_mma_bf16x3<<<dim3(Ec / 128, Mc / 128), 256, GP_SMEM>>>(
        chi, clo, owhi, owlo, out_b, out, Ec);
}

// round 4
// speedup vs baseline: 2.8254x; 2.0891x over previous
#include <cuda_runtime.h>
#include <cuda_bf16.h>
#include <cstdint>
#include <cmath>

// Problem constants
constexpr int Bc  = 2;
constexpr int Sc  = 2048;
constexpr int Ec  = 1024;
constexpr int Hc  = 16;
constexpr int HDc = 64;
constexpr int Mc  = Bc * Sc;        // 4096 rows
constexpr int NQKV = 3 * Ec;        // 3072
constexpr int RHALF = 32;           // rotary pairs per head (ROT=64)
constexpr int GK = 1024;            // K dim of both projection GEMMs

// Scratch (static device globals; no allocation)
__device__ float g_qkv[(size_t)Mc * NQKV];
__device__ float g_cos[Sc * RHALF];
__device__ float g_sin[Sc * RHALF];

// bf16 split buffers
__device__ __nv_bfloat16 g_xhi[(size_t)Mc * Ec];
__device__ __nv_bfloat16 g_xlo[(size_t)Mc * Ec];
__device__ __nv_bfloat16 g_wqkv_hi[(size_t)NQKV * Ec];
__device__ __nv_bfloat16 g_wqkv_lo[(size_t)NQKV * Ec];
__device__ __nv_bfloat16 g_wout_hi[(size_t)Ec * Ec];
__device__ __nv_bfloat16 g_wout_lo[(size_t)Ec * Ec];
__device__ __nv_bfloat16 g_ctx_hi[(size_t)Mc * Ec];
__device__ __nv_bfloat16 g_ctx_lo[(size_t)Mc * Ec];

// split q/k/v in [B,H,S,HD] layout
constexpr size_t QKV_ELEMS = (size_t)Bc * Hc * Sc * HDc;
__device__ __nv_bfloat16 g_qhi[QKV_ELEMS];
__device__ __nv_bfloat16 g_qlo[QKV_ELEMS];
__device__ __nv_bfloat16 g_khi[QKV_ELEMS];
__device__ __nv_bfloat16 g_klo[QKV_ELEMS];
__device__ __nv_bfloat16 g_vhi[QKV_ELEMS];
__device__ __nv_bfloat16 g_vlo[QKV_ELEMS];

// ---------------------------------------------------------------------------
// Portable (compute_103-safe) tensor-core helpers
// ---------------------------------------------------------------------------
__device__ __forceinline__ uint32_t smem_to_u32(const void* p) {
    uint32_t a;
    asm("{ .reg .u64 t; cvta.to.shared.u64 t, %1; cvt.u32.u64 %0, t; }"
        : "=r"(a) : "l"(p));
    return a;
}
__device__ __forceinline__ void cp16(uint32_t dst, const void* src) {
    asm volatile("cp.async.cg.shared.global [%0], [%1], 16;"
                 :: "r"(dst), "l"(src));
}
__device__ __forceinline__ void cp_commit() {
    asm volatile("cp.async.commit_group;" ::: "memory");
}
__device__ __forceinline__ void ldsm_x4(uint4& r, uint32_t addr) {
    asm volatile("ldmatrix.sync.aligned.m8n8.x4.shared.b16 {%0,%1,%2,%3}, [%4];"
                 : "=r"(r.x), "=r"(r.y), "=r"(r.z), "=r"(r.w) : "r"(addr));
}
__device__ __forceinline__ void ldsm_x2(uint2& r, uint32_t addr) {
    asm volatile("ldmatrix.sync.aligned.m8n8.x2.shared.b16 {%0,%1}, [%2];"
                 : "=r"(r.x), "=r"(r.y) : "r"(addr));
}
__device__ __forceinline__ void ldsm_x2t(uint2& r, uint32_t addr) {
    asm volatile("ldmatrix.sync.aligned.m8n8.x2.trans.shared.b16 {%0,%1}, [%2];"
                 : "=r"(r.x), "=r"(r.y) : "r"(addr));
}
__device__ __forceinline__ void mma16816(float* d, const uint4& a, const uint2& b) {
    asm volatile(
        "mma.sync.aligned.m16n8k16.row.col.f32.bf16.bf16.f32 "
        "{%0,%1,%2,%3}, {%4,%5,%6,%7}, {%8,%9}, {%0,%1,%2,%3};"
        : "+f"(d[0]), "+f"(d[1]), "+f"(d[2]), "+f"(d[3])
        : "r"(a.x), "r"(a.y), "r"(a.z), "r"(a.w), "r"(b.x), "r"(b.y));
}
__device__ __forceinline__ float ex2f(float x) {
    float r; asm("ex2.approx.f32 %0, %1;" : "=f"(r) : "f"(x)); return r;
}
__device__ __forceinline__ uint32_t packbf(float lo, float hi) {
    __nv_bfloat162 t = __floats2bfloat162_rn(lo, hi);
    return *(uint32_t*)&t;
}

// ---------------------------------------------------------------------------
// RoPE cos/sin table
// ---------------------------------------------------------------------------
__global__ void rope_table_kernel() {
    int idx = blockIdx.x * blockDim.x + threadIdx.x;
    if (idx >= Sc * RHALF) return;
    int s = idx / RHALF;
    int i = idx % RHALF;
    double inv_freq = exp(-(double)(2 * i) / 64.0 * log(10000.0));
    double ang = (double)s * inv_freq;
    g_cos[idx] = (float)cos(ang);
    g_sin[idx] = (float)sin(ang);
}

// ---------------------------------------------------------------------------
// fp32 -> (bf16 hi, bf16 lo) split
// ---------------------------------------------------------------------------
__global__ void split_bf16_kernel(const float* __restrict__ src,
                                  __nv_bfloat16* __restrict__ hi,
                                  __nv_bfloat16* __restrict__ lo, int n4) {
    int i = blockIdx.x * blockDim.x + threadIdx.x;
    if (i >= n4) return;
    float4 v = ((const float4*)src)[i];
    __nv_bfloat16 h0 = __float2bfloat16_rn(v.x);
    __nv_bfloat16 h1 = __float2bfloat16_rn(v.y);
    __nv_bfloat16 h2 = __float2bfloat16_rn(v.z);
    __nv_bfloat16 h3 = __float2bfloat16_rn(v.w);
    __nv_bfloat16 l0 = __float2bfloat16_rn(v.x - __bfloat162float(h0));
    __nv_bfloat16 l1 = __float2bfloat16_rn(v.y - __bfloat162float(h1));
    __nv_bfloat16 l2 = __float2bfloat16_rn(v.z - __bfloat162float(h2));
    __nv_bfloat16 l3 = __float2bfloat16_rn(v.w - __bfloat162float(h3));
    __nv_bfloat162* hp = (__nv_bfloat162*)hi;
    __nv_bfloat162* lp = (__nv_bfloat162*)lo;
    hp[2 * i]     = __nv_bfloat162(h0, h1);
    hp[2 * i + 1] = __nv_bfloat162(h2, h3);
    lp[2 * i]     = __nv_bfloat162(l0, l1);
    lp[2 * i + 1] = __nv_bfloat162(l2, l3);
}

// ---------------------------------------------------------------------------
// Warp-mma split-bf16 GEMM (unchanged from round 3)
// ---------------------------------------------------------------------------
constexpr int GP_PITCH = 144;
constexpr int GP_TILE  = 128 * GP_PITCH;
constexpr int GP_BUF   = 2 * GP_TILE;
constexpr int GP_SMEM  = 2 * GP_BUF;

__global__ __launch_bounds__(256) void gemm_mma_bf16x3(
    const __nv_bfloat16* __restrict__ Ahi, const __nv_bfloat16* __restrict__ Alo,
    const __nv_bfloat16* __restrict__ Bhi, const __nv_bfloat16* __restrict__ Blo,
    const float* __restrict__ bias, float* __restrict__ C, int Ndim)
{
    extern __shared__ char smg[];
    const uint32_t sb = smem_to_u32(smg);
    const int tid = threadIdx.x;
    const int lane = tid & 31;
    const int wid = tid >> 5;
    const int rowBase = blockIdx.y * 128;
    const int colBase = blockIdx.x * 128;
    const int wm = (wid >> 2) * 64;
    const int wn = (wid & 3) * 32;

    float acc[4][4][4];
#pragma unroll
    for (int mi = 0; mi < 4; mi++)
#pragma unroll
        for (int ni = 0; ni < 4; ni++)
#pragma unroll
            for (int e = 0; e < 4; e++) acc[mi][ni][e] = 0.f;

    auto issue = [&](int c) {
        const __nv_bfloat16* Asrc = (c < 32) ? Ahi : Alo;
        const __nv_bfloat16* Bsrc = (c >= 16 && c < 32) ? Blo : Bhi;
        const int k0 = (c & 15) * 64;
        const uint32_t dst = sb + (uint32_t)(c & 1) * GP_BUF;
#pragma unroll
        for (int u = 0; u < 4; u++) {
            int lin = u * 256 + tid;
            int r = lin >> 3, seg = lin & 7;
            cp16(dst + r * GP_PITCH + seg * 16,
                 Asrc + (size_t)(rowBase + r) * GK + k0 + seg * 8);
            cp16(dst + GP_TILE + r * GP_PITCH + seg * 16,
                 Bsrc + (size_t)(colBase + r) * GK + k0 + seg * 8);
        }
        cp_commit();
    };

    issue(0);
    for (int c = 0; c < 48; c++) {
        if (c < 47) {
            issue(c + 1);
            asm volatile("cp.async.wait_group 1;" ::: "memory");
        } else {
            asm volatile("cp.async.wait_group 0;" ::: "memory");
        }
        __syncthreads();

        const uint32_t Ab = sb + (uint32_t)(c & 1) * GP_BUF;
        const uint32_t Bb = Ab + GP_TILE;
#pragma unroll
        for (int ks = 0; ks < 4; ks++) {
            uint4 a[4];
            uint2 b[4];
#pragma unroll
            for (int mi = 0; mi < 4; mi++)
                ldsm_x4(a[mi], Ab + (wm + mi * 16 + (lane & 15)) * GP_PITCH
                               + (ks * 16 + (lane >> 4) * 8) * 2);
#pragma unroll
            for (int ni = 0; ni < 4; ni++)
                ldsm_x2(b[ni], Bb + (wn + ni * 8 + (lane & 7)) * GP_PITCH
                               + (ks * 16 + ((lane >> 3) & 1) * 8) * 2);
#pragma unroll
            for (int mi = 0; mi < 4; mi++)
#pragma unroll
                for (int ni = 0; ni < 4; ni++)
                    mma16816(acc[mi][ni], a[mi], b[ni]);
        }
        __syncthreads();
    }

#pragma unroll
    for (int mi = 0; mi < 4; mi++) {
#pragma unroll
        for (int ni = 0; ni < 4; ni++) {
            int r0 = rowBase + wm + mi * 16 + (lane >> 2);
            int col = colBase + wn + ni * 8 + (lane & 3) * 2;
            float b0 = bias[col], b1 = bias[col + 1];
            float2 v0 = make_float2(acc[mi][ni][0] + b0, acc[mi][ni][1] + b1);
            float2 v1 = make_float2(acc[mi][ni][2] + b0, acc[mi][ni][3] + b1);
            *(float2*)&C[(size_t)r0 * Ndim + col] = v0;
            *(float2*)&C[(size_t)(r0 + 8) * Ndim + col] = v1;
        }
    }
}

// ---------------------------------------------------------------------------
// Split QKV -> [B,H,S,HD], RoPE on Q/K, emit bf16 hi/lo directly.
// ---------------------------------------------------------------------------
__global__ void split_rope_kernel() {
    int idx = blockIdx.x * blockDim.x + threadIdx.x;
    int i = idx & 31;
    int h = (idx >> 5) & 15;
    int s = (idx >> 9) & (Sc - 1);
    int b = idx >> 20;

    int row = b * Sc + s;
    const float* src = g_qkv + (size_t)row * NQKV + h * HDc + 2 * i;
    float q0 = src[0],        q1 = src[1];
    float k0 = src[Ec],       k1 = src[Ec + 1];
    float v0 = src[2 * Ec],   v1 = src[2 * Ec + 1];

    float c  = g_cos[s * RHALF + i];
    float sn = g_sin[s * RHALF + i];

    float qa = q0 * c - q1 * sn, qb = q1 * c + q0 * sn;
    float ka = k0 * c - k1 * sn, kb = k1 * c + k0 * sn;

    size_t dst = (((size_t)(b * Hc + h)) * Sc + s) * HDc + 2 * i;

    __nv_bfloat162 qh = __floats2bfloat162_rn(qa, qb);
    __nv_bfloat162 kh = __floats2bfloat162_rn(ka, kb);
    __nv_bfloat162 vh = __floats2bfloat162_rn(v0, v1);
    __nv_bfloat162 ql = __floats2bfloat162_rn(qa - __low2float(qh), qb - __high2float(qh));
    __nv_bfloat162 kl = __floats2bfloat162_rn(ka - __low2float(kh), kb - __high2float(kh));
    __nv_bfloat162 vl = __floats2bfloat162_rn(v0 - __low2float(vh), v1 - __high2float(vh));

    *(__nv_bfloat162*)&g_qhi[dst] = qh;  *(__nv_bfloat162*)&g_qlo[dst] = ql;
    *(__nv_bfloat162*)&g_khi[dst] = kh;  *(__nv_bfloat162*)&g_klo[dst] = kl;
    *(__nv_bfloat162*)&g_vhi[dst] = vh;  *(__nv_bfloat162*)&g_vlo[dst] = vl;
}

// ---------------------------------------------------------------------------
// Tensor-core flash attention (split bf16, fp32 softmax).
// 128 q-rows/CTA, 64-key tiles, 8 warps (16 q-rows each), HD=64.
// S = Qhi*Khi + Qhi*Klo + Qlo*Khi ; O += Phi*Vhi + Plo*Vhi + Phi*Vlo.
// Epilogue writes ctx directly as bf16 hi/lo for the out-projection.
// ---------------------------------------------------------------------------
constexpr int AT_PITCH = 144;
constexpr int AT_QHI = 0;
constexpr int AT_QLO = 128 * AT_PITCH;            // 18432
constexpr int AT_KV  = 2 * 128 * AT_PITCH;        // 36864
constexpr int AT_KVBUF = 4 * 64 * AT_PITCH;       // 36864 per buffer
constexpr int AT_KLO = 64 * AT_PITCH;             // offsets within buffer
constexpr int AT_VHI = 2 * 64 * AT_PITCH;
constexpr int AT_VLO = 3 * 64 * AT_PITCH;
constexpr int AT_MSK = AT_KV + 2 * AT_KVBUF;      // 110592
constexpr int AT_SMEM = AT_MSK + 2 * 64 * 4;      // 111104

__global__ __launch_bounds__(256) void attn_mma_kernel(const int* __restrict__ mask)
{
    extern __shared__ char smA[];
    const uint32_t sb = smem_to_u32(smA);
    float* smask = (float*)(smA + AT_MSK);

    const int tid = threadIdx.x;
    const int lane = tid & 31;
    const int wid = tid >> 5;
    const int bh = blockIdx.y;
    const int b = bh >> 4, h = bh & 15;
    const int q0 = blockIdx.x * 128;

    const size_t base = (size_t)bh * Sc * HDc;
    const __nv_bfloat16* Qh = g_qhi + base + (size_t)q0 * HDc;
    const __nv_bfloat16* Ql = g_qlo + base + (size_t)q0 * HDc;
    const __nv_bfloat16* Kh = g_khi + base;
    const __nv_bfloat16* Kl = g_klo + base;
    const __nv_bfloat16* Vh = g_vhi + base;
    const __nv_bfloat16* Vl = g_vlo + base;
    const int* mg = mask + b * Sc;

    // Q tiles -> smem (group with KV0)
#pragma unroll
    for (int u = 0; u < 4; u++) {
        int lin = u * 256 + tid;
        int r = lin >> 3, seg = lin & 7;
        cp16(sb + AT_QHI + r * AT_PITCH + seg * 16, Qh + (size_t)r * HDc + seg * 8);
        cp16(sb + AT_QLO + r * AT_PITCH + seg * 16, Ql + (size_t)r * HDc + seg * 8);
    }

    auto issueKV = [&](int it) {
        const uint32_t dst = sb + AT_KV + (uint32_t)(it & 1) * AT_KVBUF;
        const size_t koff = (size_t)it * 64 * HDc;
#pragma unroll
        for (int u = 0; u < 2; u++) {
            int lin = u * 256 + tid;
            int r = lin >> 3, seg = lin & 7;
            size_t off = koff + (size_t)r * HDc + seg * 8;
            uint32_t so = r * AT_PITCH + seg * 16;
            cp16(dst + so, Kh + off);
            cp16(dst + AT_KLO + so, Kl + off);
            cp16(dst + AT_VHI + so, Vh + off);
            cp16(dst + AT_VLO + so, Vl + off);
        }
        if (tid < 64) smask[(it & 1) * 64 + tid] = mg[it * 64 + tid] ? 0.f : -1e30f;
        cp_commit();
    };

    issueKV(0);   // group0: Q + KV0
    issueKV(1);   // group1: KV1
    asm volatile("cp.async.wait_group 1;" ::: "memory");
    __syncthreads();

    // Q fragments (A operand, m16k16 x4 steps) held in registers
    uint4 qh[4], ql[4];
#pragma unroll
    for (int ks = 0; ks < 4; ks++) {
        uint32_t ro = (wid * 16 + (lane & 15)) * AT_PITCH + (ks * 16 + (lane >> 4) * 8) * 2;
        ldsm_x4(qh[ks], sb + AT_QHI + ro);
        ldsm_x4(ql[ks], sb + AT_QLO + ro);
    }

    float accO[8][4];
#pragma unroll
    for (int nd = 0; nd < 8; nd++)
#pragma unroll
        for (int e = 0; e < 4; e++) accO[nd][e] = 0.f;
    float m0 = -1e30f, m1 = -1e30f, l0 = 0.f, l1 = 0.f;
    const float scale = 0.125f;
    const float LOG2E = 1.4426950408889634f;

    for (int it = 0; it < 32; it++) {
        if (it > 0) {
            if (it == 31) asm volatile("cp.async.wait_group 0;" ::: "memory");
            else          asm volatile("cp.async.wait_group 1;" ::: "memory");
            __syncthreads();
        }
        const uint32_t Kb = sb + AT_KV + (uint32_t)(it & 1) * AT_KVBUF;
        const int mbuf = (it & 1) * 64;

        // ---- S = Q K^T (split 3-pass) ----
        float s[8][4];
#pragma unroll
        for (int ni = 0; ni < 8; ni++)
#pragma unroll
            for (int e = 0; e < 4; e++) s[ni][e] = 0.f;
#pragma unroll
        for (int ks = 0; ks < 4; ks++) {
            uint2 bkh[8], bkl[8];
            uint32_t co = (ks * 16 + ((lane >> 3) & 1) * 8) * 2;
#pragma unroll
            for (int ni = 0; ni < 8; ni++) {
                uint32_t ro = (ni * 8 + (lane & 7)) * AT_PITCH + co;
                ldsm_x2(bkh[ni], Kb + ro);
                ldsm_x2(bkl[ni], Kb + AT_KLO + ro);
            }
#pragma unroll
            for (int ni = 0; ni < 8; ni++) {
                mma16816(s[ni], qh[ks], bkh[ni]);
                mma16816(s[ni], qh[ks], bkl[ni]);
                mma16816(s[ni], ql[ks], bkh[ni]);
            }
        }

        // ---- scale + mask ----
#pragma unroll
        for (int ni = 0; ni < 8; ni++) {
            float b0 = smask[mbuf + ni * 8 + (lane & 3) * 2];
            float b1 = smask[mbuf + ni * 8 + (lane & 3) * 2 + 1];
            s[ni][0] = s[ni][0] * scale + b0;
            s[ni][1] = s[ni][1] * scale + b1;
            s[ni][2] = s[ni][2] * scale + b0;
            s[ni][3] = s[ni][3] * scale + b1;
        }

        // ---- online softmax (rows lane>>2 and +8) ----
        float mx0 = -1e30f, mx1 = -1e30f;
#pragma unroll
        for (int ni = 0; ni < 8; ni++) {
            mx0 = fmaxf(mx0, fmaxf(s[ni][0], s[ni][1]));
            mx1 = fmaxf(mx1, fmaxf(s[ni][2], s[ni][3]));
        }
        mx0 = fmaxf(mx0, __shfl_xor_sync(0xffffffffu, mx0, 1));
        mx0 = fmaxf(mx0, __shfl_xor_sync(0xffffffffu, mx0, 2));
        mx1 = fmaxf(mx1, __shfl_xor_sync(0xffffffffu, mx1, 1));
        mx1 = fmaxf(mx1, __shfl_xor_sync(0xffffffffu, mx1, 2));
        float mn0 = fmaxf(m0, mx0), mn1 = fmaxf(m1, mx1);
        float al0 = ex2f((m0 - mn0) * LOG2E);
        float al1 = ex2f((m1 - mn1) * LOG2E);
        float sum0 = 0.f, sum1 = 0.f;
#pragma unroll
        for (int ni = 0; ni < 8; ni++) {
            s[ni][0] = ex2f((s[ni][0] - mn0) * LOG2E);
            s[ni][1] = ex2f((s[ni][1] - mn0) * LOG2E);
            s[ni][2] = ex2f((s[ni][2] - mn1) * LOG2E);
            s[ni][3] = ex2f((s[ni][3] - mn1) * LOG2E);
            sum0 += s[ni][0] + s[ni][1];
            sum1 += s[ni][2] + s[ni][3];
        }
        sum0 += __shfl_xor_sync(0xffffffffu, sum0, 1);
        sum0 += __shfl_xor_sync(0xffffffffu, sum0, 2);
        sum1 += __shfl_xor_sync(0xffffffffu, sum1, 1);
        sum1 += __shfl_xor_sync(0xffffffffu, sum1, 2);
        l0 = l0 * al0 + sum0;
        l1 = l1 * al1 + sum1;
        m0 = mn0; m1 = mn1;
#pragma unroll
        for (int nd = 0; nd < 8; nd++) {
            accO[nd][0] *= al0; accO[nd][1] *= al0;
            accO[nd][2] *= al1; accO[nd][3] *= al1;
        }

        // ---- P fragments (hi/lo) from S accumulators (register identity) ----
        uint4 aph[4], apl[4];
#pragma unroll
        for (int ks2 = 0; ks2 < 4; ks2++) {
            const float* p0 = s[2 * ks2];
            const float* p1 = s[2 * ks2 + 1];
            aph[ks2].x = packbf(p0[0], p0[1]);
            aph[ks2].y = packbf(p0[2], p0[3]);
            aph[ks2].z = packbf(p1[0], p1[1]);
            aph[ks2].w = packbf(p1[2], p1[3]);
            __nv_bfloat162 h;
            h = *(__nv_bfloat162*)&aph[ks2].x;
            apl[ks2].x = packbf(p0[0] - __low2float(h), p0[1] - __high2float(h));
            h = *(__nv_bfloat162*)&aph[ks2].y;
            apl[ks2].y = packbf(p0[2] - __low2float(h), p0[3] - __high2float(h));
            h = *(__nv_bfloat162*)&aph[ks2].z;
            apl[ks2].z = packbf(p1[0] - __low2float(h), p1[1] - __high2float(h));
            h = *(__nv_bfloat162*)&aph[ks2].w;
            apl[ks2].w = packbf(p1[2] - __low2float(h), p1[3] - __high2float(h));
        }

        // ---- O += P V (split 3-pass), V^T via ldmatrix.trans ----
#pragma unroll
        for (int ks2 = 0; ks2 < 4; ks2++) {
            uint2 bvh[8], bvl[8];
            uint32_t rbase = (ks2 * 16 + (lane & 15)) * AT_PITCH;
#pragma unroll
            for (int nd = 0; nd < 8; nd++) {
                ldsm_x2t(bvh[nd], Kb + AT_VHI + rbase + nd * 16);
                ldsm_x2t(bvl[nd], Kb + AT_VLO + rbase + nd * 16);
            }
#pragma unroll
            for (int nd = 0; nd < 8; nd++) {
                mma16816(accO[nd], aph[ks2], bvh[nd]);
                mma16816(accO[nd], apl[ks2], bvh[nd]);
                mma16816(accO[nd], aph[ks2], bvl[nd]);
            }
        }

        __syncthreads();
        if (it + 2 < 32) issueKV(it + 2);
    }

    // ---- epilogue: normalize, split to bf16 hi/lo ctx ----
    float inv0 = 1.f / l0, inv1 = 1.f / l1;
    int r0 = q0 + wid * 16 + (lane >> 2);
    int colb = h * HDc + (lane & 3) * 2;
#pragma unroll
    for (int nd = 0; nd < 8; nd++) {
        float c00 = accO[nd][0] * inv0, c01 = accO[nd][1] * inv0;
        float c10 = accO[nd][2] * inv1, c11 = accO[nd][3] * inv1;
        size_t i0 = (size_t)(b * Sc + r0) * Ec + colb + nd * 8;
        size_t i1 = (size_t)(b * Sc + r0 + 8) * Ec + colb + nd * 8;
        __nv_bfloat162 h0 = __floats2bfloat162_rn(c00, c01);
        __nv_bfloat162 h1 = __floats2bfloat162_rn(c10, c11);
        __nv_bfloat162 l0v = __floats2bfloat162_rn(c00 - __low2float(h0), c01 - __high2float(h0));
        __nv_bfloat162 l1v = __floats2bfloat162_rn(c10 - __low2float(h1), c11 - __high2float(h1));
        *(__nv_bfloat162*)&g_ctx_hi[i0] = h0;
        *(__nv_bfloat162*)&g_ctx_lo[i0] = l0v;
        *(__nv_bfloat162*)&g_ctx_hi[i1] = h1;
        *(__nv_bfloat162*)&g_ctx_lo[i1] = l1v;
    }
}

// ---------------------------------------------------------------------------
extern "C" void kernel_launch(void* const* d_in, const int* in_sizes, int n_in,
                              void* d_out, int out_size)
{
    const float* x     = (const float*)d_in[0];
    const int*   mask  = (const int*)d_in[1];
    const float* qkv_w = (const float*)d_in[2];
    const float* qkv_b = (const float*)d_in[3];
    const float* out_w = (const float*)d_in[4];
    const float* out_b = (const float*)d_in[5];
    float* out = (float*)d_out;

    float* qkv_ptr = nullptr;
    cudaGetSymbolAddress((void**)&qkv_ptr, g_qkv);
    __nv_bfloat16 *xhi, *xlo, *whi, *wlo, *owhi, *owlo, *chi, *clo;
    cudaGetSymbolAddress((void**)&xhi,  g_xhi);
    cudaGetSymbolAddress((void**)&xlo,  g_xlo);
    cudaGetSymbolAddress((void**)&whi,  g_wqkv_hi);
    cudaGetSymbolAddress((void**)&wlo,  g_wqkv_lo);
    cudaGetSymbolAddress((void**)&owhi, g_wout_hi);
    cudaGetSymbolAddress((void**)&owlo, g_wout_lo);
    cudaGetSymbolAddress((void**)&chi,  g_ctx_hi);
    cudaGetSymbolAddress((void**)&clo,  g_ctx_lo);

    cudaFuncSetAttribute(gemm_mma_bf16x3,
                         cudaFuncAttributeMaxDynamicSharedMemorySize, GP_SMEM);
    cudaFuncSetAttribute(attn_mma_kernel,
                         cudaFuncAttributeMaxDynamicSharedMemorySize, AT_SMEM);

    // 1. RoPE tables
    rope_table_kernel<<<(Sc * RHALF + 255) / 256, 256>>>();

    // 2. Split inputs/weights into bf16 hi/lo
    split_bf16_kernel<<<(Mc * Ec / 4 + 255) / 256, 256>>>(x, xhi, xlo, Mc * Ec / 4);
    split_bf16_kernel<<<(NQKV * Ec / 4 + 255) / 256, 256>>>(qkv_w, whi, wlo, NQKV * Ec / 4);
    split_bf16_kernel<<<(Ec * Ec / 4 + 255) / 256, 256>>>(out_w, owhi, owlo, Ec * Ec / 4);

    // 3. QKV projection (warp-mma)
    gemm_mma_bf16x3<<<dim3(NQKV / 128, Mc / 128), 256, GP_SMEM>>>(
        xhi, xlo, whi, wlo, qkv_b, qkv_ptr, NQKV);

    // 4. Split + RoPE -> bf16 hi/lo q/k/v
    split_rope_kernel<<<(Bc * Sc * Hc * RHALF) / 256, 256>>>();

    // 5. Tensor-core flash attention -> ctx hi/lo
    attn_mma_kernel<<<dim3(Sc / 128, Bc * Hc), 256, AT_SMEM>>>(mask);

    // 6. Output projection (warp-mma)
    gemm_mma_bf16x3<<<dim3(Ec / 128, Mc / 128), 256, GP_SMEM>>>(
        chi, clo, owhi, owlo, out_b, out, Ec);
}

// round 5
// speedup vs baseline: 2.9214x; 1.0340x over previous
#include <cuda_runtime.h>
#include <cuda_bf16.h>
#include <cstdint>
#include <cmath>

// Problem constants
constexpr int Bc  = 2;
constexpr int Sc  = 2048;
constexpr int Ec  = 1024;
constexpr int Hc  = 16;
constexpr int HDc = 64;
constexpr int Mc  = Bc * Sc;        // 4096 rows
constexpr int NQKV = 3 * Ec;        // 3072
constexpr int RHALF = 32;           // rotary pairs per head (ROT=64)
constexpr int GK = 1024;            // K dim of both projection GEMMs

// Scratch (static device globals; no allocation)
__device__ float g_qkv[(size_t)Mc * NQKV];
__device__ float g_cos[Sc * RHALF];
__device__ float g_sin[Sc * RHALF];

// bf16 split buffers
__device__ __nv_bfloat16 g_xhi[(size_t)Mc * Ec];
__device__ __nv_bfloat16 g_xlo[(size_t)Mc * Ec];
__device__ __nv_bfloat16 g_wqkv_hi[(size_t)NQKV * Ec];
__device__ __nv_bfloat16 g_wqkv_lo[(size_t)NQKV * Ec];
__device__ __nv_bfloat16 g_wout_hi[(size_t)Ec * Ec];
__device__ __nv_bfloat16 g_wout_lo[(size_t)Ec * Ec];
__device__ __nv_bfloat16 g_ctx_hi[(size_t)Mc * Ec];
__device__ __nv_bfloat16 g_ctx_lo[(size_t)Mc * Ec];

// split q/k/v in [B,H,S,HD] layout
constexpr size_t QKV_ELEMS = (size_t)Bc * Hc * Sc * HDc;
__device__ __nv_bfloat16 g_qhi[QKV_ELEMS];
__device__ __nv_bfloat16 g_qlo[QKV_ELEMS];
__device__ __nv_bfloat16 g_khi[QKV_ELEMS];
__device__ __nv_bfloat16 g_klo[QKV_ELEMS];
__device__ __nv_bfloat16 g_vhi[QKV_ELEMS];
__device__ __nv_bfloat16 g_vlo[QKV_ELEMS];

// ---------------------------------------------------------------------------
// Portable (compute_103-safe) tensor-core helpers
// ---------------------------------------------------------------------------
__device__ __forceinline__ uint32_t smem_to_u32(const void* p) {
    uint32_t a;
    asm("{ .reg .u64 t; cvta.to.shared.u64 t, %1; cvt.u32.u64 %0, t; }"
        : "=r"(a) : "l"(p));
    return a;
}
__device__ __forceinline__ void cp16(uint32_t dst, const void* src) {
    asm volatile("cp.async.cg.shared.global [%0], [%1], 16;"
                 :: "r"(dst), "l"(src));
}
__device__ __forceinline__ void cp_commit() {
    asm volatile("cp.async.commit_group;" ::: "memory");
}
__device__ __forceinline__ void ldsm_x4(uint4& r, uint32_t addr) {
    asm volatile("ldmatrix.sync.aligned.m8n8.x4.shared.b16 {%0,%1,%2,%3}, [%4];"
                 : "=r"(r.x), "=r"(r.y), "=r"(r.z), "=r"(r.w) : "r"(addr));
}
__device__ __forceinline__ void ldsm_x2(uint2& r, uint32_t addr) {
    asm volatile("ldmatrix.sync.aligned.m8n8.x2.shared.b16 {%0,%1}, [%2];"
                 : "=r"(r.x), "=r"(r.y) : "r"(addr));
}
__device__ __forceinline__ void ldsm_x2t(uint2& r, uint32_t addr) {
    asm volatile("ldmatrix.sync.aligned.m8n8.x2.trans.shared.b16 {%0,%1}, [%2];"
                 : "=r"(r.x), "=r"(r.y) : "r"(addr));
}
__device__ __forceinline__ void mma16816(float* d, const uint4& a, const uint2& b) {
    asm volatile(
        "mma.sync.aligned.m16n8k16.row.col.f32.bf16.bf16.f32 "
        "{%0,%1,%2,%3}, {%4,%5,%6,%7}, {%8,%9}, {%0,%1,%2,%3};"
        : "+f"(d[0]), "+f"(d[1]), "+f"(d[2]), "+f"(d[3])
        : "r"(a.x), "r"(a.y), "r"(a.z), "r"(a.w), "r"(b.x), "r"(b.y));
}
__device__ __forceinline__ float ex2f(float x) {
    float r; asm("ex2.approx.f32 %0, %1;" : "=f"(r) : "f"(x)); return r;
}
__device__ __forceinline__ uint32_t packbf(float lo, float hi) {
    __nv_bfloat162 t = __floats2bfloat162_rn(lo, hi);
    return *(uint32_t*)&t;
}

// ---------------------------------------------------------------------------
// RoPE cos/sin table
// ---------------------------------------------------------------------------
__global__ void rope_table_kernel() {
    int idx = blockIdx.x * blockDim.x + threadIdx.x;
    if (idx >= Sc * RHALF) return;
    int s = idx / RHALF;
    int i = idx % RHALF;
    double inv_freq = exp(-(double)(2 * i) / 64.0 * log(10000.0));
    double ang = (double)s * inv_freq;
    g_cos[idx] = (float)cos(ang);
    g_sin[idx] = (float)sin(ang);
}

// ---------------------------------------------------------------------------
// fp32 -> (bf16 hi, bf16 lo) split
// ---------------------------------------------------------------------------
__global__ void split_bf16_kernel(const float* __restrict__ src,
                                  __nv_bfloat16* __restrict__ hi,
                                  __nv_bfloat16* __restrict__ lo, int n4) {
    int i = blockIdx.x * blockDim.x + threadIdx.x;
    if (i >= n4) return;
    float4 v = ((const float4*)src)[i];
    __nv_bfloat16 h0 = __float2bfloat16_rn(v.x);
    __nv_bfloat16 h1 = __float2bfloat16_rn(v.y);
    __nv_bfloat16 h2 = __float2bfloat16_rn(v.z);
    __nv_bfloat16 h3 = __float2bfloat16_rn(v.w);
    __nv_bfloat16 l0 = __float2bfloat16_rn(v.x - __bfloat162float(h0));
    __nv_bfloat16 l1 = __float2bfloat16_rn(v.y - __bfloat162float(h1));
    __nv_bfloat16 l2 = __float2bfloat16_rn(v.z - __bfloat162float(h2));
    __nv_bfloat16 l3 = __float2bfloat16_rn(v.w - __bfloat162float(h3));
    __nv_bfloat162* hp = (__nv_bfloat162*)hi;
    __nv_bfloat162* lp = (__nv_bfloat162*)lo;
    hp[2 * i]     = __nv_bfloat162(h0, h1);
    hp[2 * i + 1] = __nv_bfloat162(h2, h3);
    lp[2 * i]     = __nv_bfloat162(l0, l1);
    lp[2 * i + 1] = __nv_bfloat162(l2, l3);
}

// ---------------------------------------------------------------------------
// Warp-mma split-bf16 GEMM, fused 3-term, 3-stage cp.async pipeline.
// C = Ahi@Bhi^T + Ahi@Blo^T + Alo@Bhi^T + bias
// 128x128 CTA tile, BK=64, 8 warps (each 64x32). K=1024 -> 16 chunks.
// Per stage: Ahi | Alo | Bhi | Blo tiles (128x64 bf16 each, 144B pitch).
// ---------------------------------------------------------------------------
constexpr int GP_PITCH = 144;
constexpr int GP_TILE  = 128 * GP_PITCH;        // 18432
constexpr int GP_ALO   = GP_TILE;
constexpr int GP_BHI   = 2 * GP_TILE;
constexpr int GP_BLO   = 3 * GP_TILE;
constexpr int GP_STAGE = 4 * GP_TILE;           // 73728
constexpr int GP_SMEM  = 3 * GP_STAGE;          // 221184

__global__ __launch_bounds__(256) void gemm_mma_bf16x3(
    const __nv_bfloat16* __restrict__ Ahi, const __nv_bfloat16* __restrict__ Alo,
    const __nv_bfloat16* __restrict__ Bhi, const __nv_bfloat16* __restrict__ Blo,
    const float* __restrict__ bias, float* __restrict__ C, int Ndim)
{
    extern __shared__ char smg[];
    const uint32_t sb = smem_to_u32(smg);
    const int tid = threadIdx.x;
    const int lane = tid & 31;
    const int wid = tid >> 5;
    const int rowBase = blockIdx.y * 128;
    const int colBase = blockIdx.x * 128;
    const int wm = (wid >> 2) * 64;
    const int wn = (wid & 3) * 32;

    float acc[4][4][4];
#pragma unroll
    for (int mi = 0; mi < 4; mi++)
#pragma unroll
        for (int ni = 0; ni < 4; ni++)
#pragma unroll
            for (int e = 0; e < 4; e++) acc[mi][ni][e] = 0.f;

    // load chunk k (Ahi/Alo/Bhi/Blo 128x64 tiles) into stage k%3
    auto issue = [&](int k) {
        const int k0 = k * 64;
        const uint32_t dst = sb + (uint32_t)(k % 3) * GP_STAGE;
#pragma unroll
        for (int u = 0; u < 4; u++) {
            int lin = u * 256 + tid;
            int r = lin >> 3, seg = lin & 7;
            uint32_t so = r * GP_PITCH + seg * 16;
            size_t goA = (size_t)(rowBase + r) * GK + k0 + seg * 8;
            size_t goB = (size_t)(colBase + r) * GK + k0 + seg * 8;
            cp16(dst + so, Ahi + goA);
            cp16(dst + GP_ALO + so, Alo + goA);
            cp16(dst + GP_BHI + so, Bhi + goB);
            cp16(dst + GP_BLO + so, Blo + goB);
        }
        cp_commit();
    };

    issue(0);
    issue(1);
    for (int k = 0; k < 16; k++) {
        if (k < 15) asm volatile("cp.async.wait_group 1;" ::: "memory");
        else        asm volatile("cp.async.wait_group 0;" ::: "memory");
        __syncthreads();
        if (k + 2 < 16) issue(k + 2);

        const uint32_t St = sb + (uint32_t)(k % 3) * GP_STAGE;
#pragma unroll
        for (int ks = 0; ks < 4; ks++) {
            uint4 ah[4], al[4];
            uint2 bh[4], bl[4];
            const uint32_t aro = (wm + (lane & 15)) * GP_PITCH
                               + (ks * 16 + (lane >> 4) * 8) * 2;
#pragma unroll
            for (int mi = 0; mi < 4; mi++) {
                ldsm_x4(ah[mi], St + aro + mi * 16 * GP_PITCH);
                ldsm_x4(al[mi], St + GP_ALO + aro + mi * 16 * GP_PITCH);
            }
            const uint32_t bro = (wn + (lane & 7)) * GP_PITCH
                               + (ks * 16 + ((lane >> 3) & 1) * 8) * 2;
#pragma unroll
            for (int ni = 0; ni < 4; ni++) {
                ldsm_x2(bh[ni], St + GP_BHI + bro + ni * 8 * GP_PITCH);
                ldsm_x2(bl[ni], St + GP_BLO + bro + ni * 8 * GP_PITCH);
            }
#pragma unroll
            for (int mi = 0; mi < 4; mi++)
#pragma unroll
                for (int ni = 0; ni < 4; ni++) {
                    mma16816(acc[mi][ni], ah[mi], bh[ni]);
                    mma16816(acc[mi][ni], ah[mi], bl[ni]);
                    mma16816(acc[mi][ni], al[mi], bh[ni]);
                }
        }
    }

#pragma unroll
    for (int mi = 0; mi < 4; mi++) {
#pragma unroll
        for (int ni = 0; ni < 4; ni++) {
            int r0 = rowBase + wm + mi * 16 + (lane >> 2);
            int col = colBase + wn + ni * 8 + (lane & 3) * 2;
            float b0 = bias[col], b1 = bias[col + 1];
            float2 v0 = make_float2(acc[mi][ni][0] + b0, acc[mi][ni][1] + b1);
            float2 v1 = make_float2(acc[mi][ni][2] + b0, acc[mi][ni][3] + b1);
            *(float2*)&C[(size_t)r0 * Ndim + col] = v0;
            *(float2*)&C[(size_t)(r0 + 8) * Ndim + col] = v1;
        }
    }
}

// ---------------------------------------------------------------------------
// Split QKV -> [B,H,S,HD], RoPE on Q/K, emit bf16 hi/lo directly.
// ---------------------------------------------------------------------------
__global__ void split_rope_kernel() {
    int idx = blockIdx.x * blockDim.x + threadIdx.x;
    int i = idx & 31;
    int h = (idx >> 5) & 15;
    int s = (idx >> 9) & (Sc - 1);
    int b = idx >> 20;

    int row = b * Sc + s;
    const float* src = g_qkv + (size_t)row * NQKV + h * HDc + 2 * i;
    float q0 = src[0],        q1 = src[1];
    float k0 = src[Ec],       k1 = src[Ec + 1];
    float v0 = src[2 * Ec],   v1 = src[2 * Ec + 1];

    float c  = g_cos[s * RHALF + i];
    float sn = g_sin[s * RHALF + i];

    float qa = q0 * c - q1 * sn, qb = q1 * c + q0 * sn;
    float ka = k0 * c - k1 * sn, kb = k1 * c + k0 * sn;

    size_t dst = (((size_t)(b * Hc + h)) * Sc + s) * HDc + 2 * i;

    __nv_bfloat162 qh = __floats2bfloat162_rn(qa, qb);
    __nv_bfloat162 kh = __floats2bfloat162_rn(ka, kb);
    __nv_bfloat162 vh = __floats2bfloat162_rn(v0, v1);
    __nv_bfloat162 ql = __floats2bfloat162_rn(qa - __low2float(qh), qb - __high2float(qh));
    __nv_bfloat162 kl = __floats2bfloat162_rn(ka - __low2float(kh), kb - __high2float(kh));
    __nv_bfloat162 vl = __floats2bfloat162_rn(v0 - __low2float(vh), v1 - __high2float(vh));

    *(__nv_bfloat162*)&g_qhi[dst] = qh;  *(__nv_bfloat162*)&g_qlo[dst] = ql;
    *(__nv_bfloat162*)&g_khi[dst] = kh;  *(__nv_bfloat162*)&g_klo[dst] = kl;
    *(__nv_bfloat162*)&g_vhi[dst] = vh;  *(__nv_bfloat162*)&g_vlo[dst] = vl;
}

// ---------------------------------------------------------------------------
// Tensor-core flash attention (split bf16, fp32 softmax). Unchanged (round 4).
// ---------------------------------------------------------------------------
constexpr int AT_PITCH = 144;
constexpr int AT_QHI = 0;
constexpr int AT_QLO = 128 * AT_PITCH;            // 18432
constexpr int AT_KV  = 2 * 128 * AT_PITCH;        // 36864
constexpr int AT_KVBUF = 4 * 64 * AT_PITCH;       // 36864 per buffer
constexpr int AT_KLO = 64 * AT_PITCH;
constexpr int AT_VHI = 2 * 64 * AT_PITCH;
constexpr int AT_VLO = 3 * 64 * AT_PITCH;
constexpr int AT_MSK = AT_KV + 2 * AT_KVBUF;      // 110592
constexpr int AT_SMEM = AT_MSK + 2 * 64 * 4;      // 111104

__global__ __launch_bounds__(256) void attn_mma_kernel(const int* __restrict__ mask)
{
    extern __shared__ char smA[];
    const uint32_t sb = smem_to_u32(smA);
    float* smask = (float*)(smA + AT_MSK);

    const int tid = threadIdx.x;
    const int lane = tid & 31;
    const int wid = tid >> 5;
    const int bh = blockIdx.y;
    const int b = bh >> 4, h = bh & 15;
    const int q0 = blockIdx.x * 128;

    const size_t base = (size_t)bh * Sc * HDc;
    const __nv_bfloat16* Qh = g_qhi + base + (size_t)q0 * HDc;
    const __nv_bfloat16* Ql = g_qlo + base + (size_t)q0 * HDc;
    const __nv_bfloat16* Kh = g_khi + base;
    const __nv_bfloat16* Kl = g_klo + base;
    const __nv_bfloat16* Vh = g_vhi + base;
    const __nv_bfloat16* Vl = g_vlo + base;
    const int* mg = mask + b * Sc;

#pragma unroll
    for (int u = 0; u < 4; u++) {
        int lin = u * 256 + tid;
        int r = lin >> 3, seg = lin & 7;
        cp16(sb + AT_QHI + r * AT_PITCH + seg * 16, Qh + (size_t)r * HDc + seg * 8);
        cp16(sb + AT_QLO + r * AT_PITCH + seg * 16, Ql + (size_t)r * HDc + seg * 8);
    }

    auto issueKV = [&](int it) {
        const uint32_t dst = sb + AT_KV + (uint32_t)(it & 1) * AT_KVBUF;
        const size_t koff = (size_t)it * 64 * HDc;
#pragma unroll
        for (int u = 0; u < 2; u++) {
            int lin = u * 256 + tid;
            int r = lin >> 3, seg = lin & 7;
            size_t off = koff + (size_t)r * HDc + seg * 8;
            uint32_t so = r * AT_PITCH + seg * 16;
            cp16(dst + so, Kh + off);
            cp16(dst + AT_KLO + so, Kl + off);
            cp16(dst + AT_VHI + so, Vh + off);
            cp16(dst + AT_VLO + so, Vl + off);
        }
        if (tid < 64) smask[(it & 1) * 64 + tid] = mg[it * 64 + tid] ? 0.f : -1e30f;
        cp_commit();
    };

    issueKV(0);
    issueKV(1);
    asm volatile("cp.async.wait_group 1;" ::: "memory");
    __syncthreads();

    uint4 qh[4], ql[4];
#pragma unroll
    for (int ks = 0; ks < 4; ks++) {
        uint32_t ro = (wid * 16 + (lane & 15)) * AT_PITCH + (ks * 16 + (lane >> 4) * 8) * 2;
        ldsm_x4(qh[ks], sb + AT_QHI + ro);
        ldsm_x4(ql[ks], sb + AT_QLO + ro);
    }

    float accO[8][4];
#pragma unroll
    for (int nd = 0; nd < 8; nd++)
#pragma unroll
        for (int e = 0; e < 4; e++) accO[nd][e] = 0.f;
    float m0 = -1e30f, m1 = -1e30f, l0 = 0.f, l1 = 0.f;
    const float scale = 0.125f;
    const float LOG2E = 1.4426950408889634f;

    for (int it = 0; it < 32; it++) {
        if (it > 0) {
            if (it == 31) asm volatile("cp.async.wait_group 0;" ::: "memory");
            else          asm volatile("cp.async.wait_group 1;" ::: "memory");
            __syncthreads();
        }
        const uint32_t Kb = sb + AT_KV + (uint32_t)(it & 1) * AT_KVBUF;
        const int mbuf = (it & 1) * 64;

        float s[8][4];
#pragma unroll
        for (int ni = 0; ni < 8; ni++)
#pragma unroll
            for (int e = 0; e < 4; e++) s[ni][e] = 0.f;
#pragma unroll
        for (int ks = 0; ks < 4; ks++) {
            uint2 bkh[8], bkl[8];
            uint32_t co = (ks * 16 + ((lane >> 3) & 1) * 8) * 2;
#pragma unroll
            for (int ni = 0; ni < 8; ni++) {
                uint32_t ro = (ni * 8 + (lane & 7)) * AT_PITCH + co;
                ldsm_x2(bkh[ni], Kb + ro);
                ldsm_x2(bkl[ni], Kb + AT_KLO + ro);
            }
#pragma unroll
            for (int ni = 0; ni < 8; ni++) {
                mma16816(s[ni], qh[ks], bkh[ni]);
                mma16816(s[ni], qh[ks], bkl[ni]);
                mma16816(s[ni], ql[ks], bkh[ni]);
            }
        }

#pragma unroll
        for (int ni = 0; ni < 8; ni++) {
            float b0 = smask[mbuf + ni * 8 + (lane & 3) * 2];
            float b1 = smask[mbuf + ni * 8 + (lane & 3) * 2 + 1];
            s[ni][0] = s[ni][0] * scale + b0;
            s[ni][1] = s[ni][1] * scale + b1;
            s[ni][2] = s[ni][2] * scale + b0;
            s[ni][3] = s[ni][3] * scale + b1;
        }

        float mx0 = -1e30f, mx1 = -1e30f;
#pragma unroll
        for (int ni = 0; ni < 8; ni++) {
            mx0 = fmaxf(mx0, fmaxf(s[ni][0], s[ni][1]));
            mx1 = fmaxf(mx1, fmaxf(s[ni][2], s[ni][3]));
        }
        mx0 = fmaxf(mx0, __shfl_xor_sync(0xffffffffu, mx0, 1));
        mx0 = fmaxf(mx0, __shfl_xor_sync(0xffffffffu, mx0, 2));
        mx1 = fmaxf(mx1, __shfl_xor_sync(0xffffffffu, mx1, 1));
        mx1 = fmaxf(mx1, __shfl_xor_sync(0xffffffffu, mx1, 2));
        float mn0 = fmaxf(m0, mx0), mn1 = fmaxf(m1, mx1);
        float al0 = ex2f((m0 - mn0) * LOG2E);
        float al1 = ex2f((m1 - mn1) * LOG2E);
        float sum0 = 0.f, sum1 = 0.f;
#pragma unroll
        for (int ni = 0; ni < 8; ni++) {
            s[ni][0] = ex2f((s[ni][0] - mn0) * LOG2E);
            s[ni][1] = ex2f((s[ni][1] - mn0) * LOG2E);
            s[ni][2] = ex2f((s[ni][2] - mn1) * LOG2E);
            s[ni][3] = ex2f((s[ni][3] - mn1) * LOG2E);
            sum0 += s[ni][0] + s[ni][1];
            sum1 += s[ni][2] + s[ni][3];
        }
        sum0 += __shfl_xor_sync(0xffffffffu, sum0, 1);
        sum0 += __shfl_xor_sync(0xffffffffu, sum0, 2);
        sum1 += __shfl_xor_sync(0xffffffffu, sum1, 1);
        sum1 += __shfl_xor_sync(0xffffffffu, sum1, 2);
        l0 = l0 * al0 + sum0;
        l1 = l1 * al1 + sum1;
        m0 = mn0; m1 = mn1;
#pragma unroll
        for (int nd = 0; nd < 8; nd++) {
            accO[nd][0] *= al0; accO[nd][1] *= al0;
            accO[nd][2] *= al1; accO[nd][3] *= al1;
        }

        uint4 aph[4], apl[4];
#pragma unroll
        for (int ks2 = 0; ks2 < 4; ks2++) {
            const float* p0 = s[2 * ks2];
            const float* p1 = s[2 * ks2 + 1];
            aph[ks2].x = packbf(p0[0], p0[1]);
            aph[ks2].y = packbf(p0[2], p0[3]);
            aph[ks2].z = packbf(p1[0], p1[1]);
            aph[ks2].w = packbf(p1[2], p1[3]);
            __nv_bfloat162 h;
            h = *(__nv_bfloat162*)&aph[ks2].x;
            apl[ks2].x = packbf(p0[0] - __low2float(h), p0[1] - __high2float(h));
            h = *(__nv_bfloat162*)&aph[ks2].y;
            apl[ks2].y = packbf(p0[2] - __low2float(h), p0[3] - __high2float(h));
            h = *(__nv_bfloat162*)&aph[ks2].z;
            apl[ks2].z = packbf(p1[0] - __low2float(h), p1[1] - __high2float(h));
            h = *(__nv_bfloat162*)&aph[ks2].w;
            apl[ks2].w = packbf(p1[2] - __low2float(h), p1[3] - __high2float(h));
        }

#pragma unroll
        for (int ks2 = 0; ks2 < 4; ks2++) {
            uint2 bvh[8], bvl[8];
            uint32_t rbase = (ks2 * 16 + (lane & 15)) * AT_PITCH;
#pragma unroll
            for (int nd = 0; nd < 8; nd++) {
                ldsm_x2t(bvh[nd], Kb + AT_VHI + rbase + nd * 16);
                ldsm_x2t(bvl[nd], Kb + AT_VLO + rbase + nd * 16);
            }
#pragma unroll
            for (int nd = 0; nd < 8; nd++) {
                mma16816(accO[nd], aph[ks2], bvh[nd]);
                mma16816(accO[nd], apl[ks2], bvh[nd]);
                mma16816(accO[nd], aph[ks2], bvl[nd]);
            }
        }

        __syncthreads();
        if (it + 2 < 32) issueKV(it + 2);
    }

    float inv0 = 1.f / l0, inv1 = 1.f / l1;
    int r0 = q0 + wid * 16 + (lane >> 2);
    int colb = h * HDc + (lane & 3) * 2;
#pragma unroll
    for (int nd = 0; nd < 8; nd++) {
        float c00 = accO[nd][0] * inv0, c01 = accO[nd][1] * inv0;
        float c10 = accO[nd][2] * inv1, c11 = accO[nd][3] * inv1;
        size_t i0 = (size_t)(b * Sc + r0) * Ec + colb + nd * 8;
        size_t i1 = (size_t)(b * Sc + r0 + 8) * Ec + colb + nd * 8;
        __nv_bfloat162 h0 = __floats2bfloat162_rn(c00, c01);
        __nv_bfloat162 h1 = __floats2bfloat162_rn(c10, c11);
        __nv_bfloat162 l0v = __floats2bfloat162_rn(c00 - __low2float(h0), c01 - __high2float(h0));
        __nv_bfloat162 l1v = __floats2bfloat162_rn(c10 - __low2float(h1), c11 - __high2float(h1));
        *(__nv_bfloat162*)&g_ctx_hi[i0] = h0;
        *(__nv_bfloat162*)&g_ctx_lo[i0] = l0v;
        *(__nv_bfloat162*)&g_ctx_hi[i1] = h1;
        *(__nv_bfloat162*)&g_ctx_lo[i1] = l1v;
    }
}

// ---------------------------------------------------------------------------
extern "C" void kernel_launch(void* const* d_in, const int* in_sizes, int n_in,
                              void* d_out, int out_size)
{
    const float* x     = (const float*)d_in[0];
    const int*   mask  = (const int*)d_in[1];
    const float* qkv_w = (const float*)d_in[2];
    const float* qkv_b = (const float*)d_in[3];
    const float* out_w = (const float*)d_in[4];
    const float* out_b = (const float*)d_in[5];
    float* out = (float*)d_out;

    float* qkv_ptr = nullptr;
    cudaGetSymbolAddress((void**)&qkv_ptr, g_qkv);
    __nv_bfloat16 *xhi, *xlo, *whi, *wlo, *owhi, *owlo, *chi, *clo;
    cudaGetSymbolAddress((void**)&xhi,  g_xhi);
    cudaGetSymbolAddress((void**)&xlo,  g_xlo);
    cudaGetSymbolAddress((void**)&whi,  g_wqkv_hi);
    cudaGetSymbolAddress((void**)&wlo,  g_wqkv_lo);
    cudaGetSymbolAddress((void**)&owhi, g_wout_hi);
    cudaGetSymbolAddress((void**)&owlo, g_wout_lo);
    cudaGetSymbolAddress((void**)&chi,  g_ctx_hi);
    cudaGetSymbolAddress((void**)&clo,  g_ctx_lo);

    cudaFuncSetAttribute(gemm_mma_bf16x3,
                         cudaFuncAttributeMaxDynamicSharedMemorySize, GP_SMEM);
    cudaFuncSetAttribute(attn_mma_kernel,
                         cudaFuncAttributeMaxDynamicSharedMemorySize, AT_SMEM);

    // 1. RoPE tables
    rope_table_kernel<<<(Sc * RHALF + 255) / 256, 256>>>();

    // 2. Split inputs/weights into bf16 hi/lo
    split_bf16_kernel<<<(Mc * Ec / 4 + 255) / 256, 256>>>(x, xhi, xlo, Mc * Ec / 4);
    split_bf16_kernel<<<(NQKV * Ec / 4 + 255) / 256, 256>>>(qkv_w, whi, wlo, NQKV * Ec / 4);
    split_bf16_kernel<<<(Ec * Ec / 4 + 255) / 256, 256>>>(out_w, owhi, owlo, Ec * Ec / 4);

    // 3. QKV projection (fused-term warp-mma)
    gemm_mma_bf16x3<<<dim3(NQKV / 128, Mc / 128), 256, GP_SMEM>>>(
        xhi, xlo, whi, wlo, qkv_b, qkv_ptr, NQKV);

    // 4. Split + RoPE -> bf16 hi/lo q/k/v
    split_rope_kernel<<<(Bc * Sc * Hc * RHALF) / 256, 256>>>();

    // 5. Tensor-core flash attention -> ctx hi/lo
    attn_mma_kernel<<<dim3(Sc / 128, Bc * Hc), 256, AT_SMEM>>>(mask);

    // 6. Output projection (fused-term warp-mma)
    gemm_mma_bf16x3<<<dim3(Ec / 128, Mc / 128), 256, GP_SMEM>>>(
        chi, clo, owhi, owlo, out_b, out, Ec);
}

// round 7
// speedup vs baseline: 2.9555x; 1.0117x over previous
#include <cuda_runtime.h>
#include <cuda_bf16.h>
#include <cstdint>
#include <cmath>

// Problem constants
constexpr int Bc  = 2;
constexpr int Sc  = 2048;
constexpr int Ec  = 1024;
constexpr int Hc  = 16;
constexpr int HDc = 64;
constexpr int Mc  = Bc * Sc;        // 4096 rows
constexpr int NQKV = 3 * Ec;        // 3072
constexpr int RHALF = 32;           // rotary pairs per head (ROT=64)
constexpr int GK = 1024;            // K dim of both projection GEMMs

// Scratch (static device globals; no allocation)
__device__ float g_qkv[(size_t)Mc * NQKV];
__device__ float g_cos[Sc * RHALF];
__device__ float g_sin[Sc * RHALF];

// bf16 split buffers
__device__ __nv_bfloat16 g_xhi[(size_t)Mc * Ec];
__device__ __nv_bfloat16 g_xlo[(size_t)Mc * Ec];
__device__ __nv_bfloat16 g_wqkv_hi[(size_t)NQKV * Ec];
__device__ __nv_bfloat16 g_wqkv_lo[(size_t)NQKV * Ec];
__device__ __nv_bfloat16 g_wout_hi[(size_t)Ec * Ec];
__device__ __nv_bfloat16 g_wout_lo[(size_t)Ec * Ec];
__device__ __nv_bfloat16 g_ctx_hi[(size_t)Mc * Ec];
__device__ __nv_bfloat16 g_ctx_lo[(size_t)Mc * Ec];

// split q/k/v in [B,H,S,HD] layout
constexpr size_t QKV_ELEMS = (size_t)Bc * Hc * Sc * HDc;
__device__ __nv_bfloat16 g_qhi[QKV_ELEMS];
__device__ __nv_bfloat16 g_qlo[QKV_ELEMS];
__device__ __nv_bfloat16 g_khi[QKV_ELEMS];
__device__ __nv_bfloat16 g_klo[QKV_ELEMS];
__device__ __nv_bfloat16 g_vhi[QKV_ELEMS];
__device__ __nv_bfloat16 g_vlo[QKV_ELEMS];

// ---------------------------------------------------------------------------
// Portable (compute_103-safe) tensor-core helpers
// ---------------------------------------------------------------------------
__device__ __forceinline__ uint32_t smem_to_u32(const void* p) {
    uint32_t a;
    asm("{ .reg .u64 t; cvta.to.shared.u64 t, %1; cvt.u32.u64 %0, t; }"
        : "=r"(a) : "l"(p));
    return a;
}
__device__ __forceinline__ void cp16(uint32_t dst, const void* src) {
    asm volatile("cp.async.cg.shared.global [%0], [%1], 16;"
                 :: "r"(dst), "l"(src));
}
__device__ __forceinline__ void cp_commit() {
    asm volatile("cp.async.commit_group;" ::: "memory");
}
__device__ __forceinline__ void ldsm_x4(uint4& r, uint32_t addr) {
    asm volatile("ldmatrix.sync.aligned.m8n8.x4.shared.b16 {%0,%1,%2,%3}, [%4];"
                 : "=r"(r.x), "=r"(r.y), "=r"(r.z), "=r"(r.w) : "r"(addr));
}
__device__ __forceinline__ void ldsm_x2(uint2& r, uint32_t addr) {
    asm volatile("ldmatrix.sync.aligned.m8n8.x2.shared.b16 {%0,%1}, [%2];"
                 : "=r"(r.x), "=r"(r.y) : "r"(addr));
}
__device__ __forceinline__ void ldsm_x2t(uint2& r, uint32_t addr) {
    asm volatile("ldmatrix.sync.aligned.m8n8.x2.trans.shared.b16 {%0,%1}, [%2];"
                 : "=r"(r.x), "=r"(r.y) : "r"(addr));
}
__device__ __forceinline__ void mma16816(float* d, const uint4& a, const uint2& b) {
    asm volatile(
        "mma.sync.aligned.m16n8k16.row.col.f32.bf16.bf16.f32 "
        "{%0,%1,%2,%3}, {%4,%5,%6,%7}, {%8,%9}, {%0,%1,%2,%3};"
        : "+f"(d[0]), "+f"(d[1]), "+f"(d[2]), "+f"(d[3])
        : "r"(a.x), "r"(a.y), "r"(a.z), "r"(a.w), "r"(b.x), "r"(b.y));
}
__device__ __forceinline__ float ex2f(float x) {
    float r; asm("ex2.approx.f32 %0, %1;" : "=f"(r) : "f"(x)); return r;
}
__device__ __forceinline__ uint32_t packbf(float lo, float hi) {
    __nv_bfloat162 t = __floats2bfloat162_rn(lo, hi);
    return *(uint32_t*)&t;
}

// ---------------------------------------------------------------------------
// RoPE cos/sin table
// ---------------------------------------------------------------------------
__global__ void rope_table_kernel() {
    int idx = blockIdx.x * blockDim.x + threadIdx.x;
    if (idx >= Sc * RHALF) return;
    int s = idx / RHALF;
    int i = idx % RHALF;
    double inv_freq = exp(-(double)(2 * i) / 64.0 * log(10000.0));
    double ang = (double)s * inv_freq;
    g_cos[idx] = (float)cos(ang);
    g_sin[idx] = (float)sin(ang);
}

// ---------------------------------------------------------------------------
// fp32 -> (bf16 hi, bf16 lo) split
// ---------------------------------------------------------------------------
__global__ void split_bf16_kernel(const float* __restrict__ src,
                                  __nv_bfloat16* __restrict__ hi,
                                  __nv_bfloat16* __restrict__ lo, int n4) {
    int i = blockIdx.x * blockDim.x + threadIdx.x;
    if (i >= n4) return;
    float4 v = ((const float4*)src)[i];
    __nv_bfloat16 h0 = __float2bfloat16_rn(v.x);
    __nv_bfloat16 h1 = __float2bfloat16_rn(v.y);
    __nv_bfloat16 h2 = __float2bfloat16_rn(v.z);
    __nv_bfloat16 h3 = __float2bfloat16_rn(v.w);
    __nv_bfloat16 l0 = __float2bfloat16_rn(v.x - __bfloat162float(h0));
    __nv_bfloat16 l1 = __float2bfloat16_rn(v.y - __bfloat162float(h1));
    __nv_bfloat16 l2 = __float2bfloat16_rn(v.z - __bfloat162float(h2));
    __nv_bfloat16 l3 = __float2bfloat16_rn(v.w - __bfloat162float(h3));
    __nv_bfloat162* hp = (__nv_bfloat162*)hi;
    __nv_bfloat162* lp = (__nv_bfloat162*)lo;
    hp[2 * i]     = __nv_bfloat162(h0, h1);
    hp[2 * i + 1] = __nv_bfloat162(h2, h3);
    lp[2 * i]     = __nv_bfloat162(l0, l1);
    lp[2 * i + 1] = __nv_bfloat162(l2, l3);
}

// ---------------------------------------------------------------------------
// Warp-mma split-bf16 GEMM, fused 3-term, 2-stage pipeline, 2 CTAs/SM.
// C = Ahi@Bhi^T + Ahi@Blo^T + Alo@Bhi^T + bias
// 128x128 CTA tile, BK=32, 8 warps (each 64x32). K=1024 -> 32 chunks.
// Per stage: Ahi | Alo | Bhi | Blo tiles (128x32 bf16, 80B pitch = 64B + pad).
// 80 KB smem -> 2 CTAs/SM. SAFE pipeline ordering: issue(k+1) BEFORE waiting
// on chunk k (writes the opposite stage), trailing sync before reuse.
// ---------------------------------------------------------------------------
constexpr int GP_PITCH = 80;
constexpr int GP_TILE  = 128 * GP_PITCH;        // 10240
constexpr int GP_ALO   = GP_TILE;
constexpr int GP_BHI   = 2 * GP_TILE;
constexpr int GP_BLO   = 3 * GP_TILE;
constexpr int GP_STAGE = 4 * GP_TILE;           // 40960
constexpr int GP_SMEM  = 2 * GP_STAGE;          // 81920

__global__ __launch_bounds__(256, 2) void gemm_mma_bf16x3(
    const __nv_bfloat16* __restrict__ Ahi, const __nv_bfloat16* __restrict__ Alo,
    const __nv_bfloat16* __restrict__ Bhi, const __nv_bfloat16* __restrict__ Blo,
    const float* __restrict__ bias, float* __restrict__ C, int Ndim)
{
    extern __shared__ char smg[];
    const uint32_t sb = smem_to_u32(smg);
    const int tid = threadIdx.x;
    const int lane = tid & 31;
    const int wid = tid >> 5;
    const int rowBase = blockIdx.y * 128;
    const int colBase = blockIdx.x * 128;
    const int wm = (wid >> 2) * 64;
    const int wn = (wid & 3) * 32;

    float acc[4][4][4];
#pragma unroll
    for (int mi = 0; mi < 4; mi++)
#pragma unroll
        for (int ni = 0; ni < 4; ni++)
#pragma unroll
            for (int e = 0; e < 4; e++) acc[mi][ni][e] = 0.f;

    // load chunk k (Ahi/Alo/Bhi/Blo 128x32 tiles) into stage k&1
    auto issue = [&](int k) {
        const int k0 = k * 32;
        const uint32_t dst = sb + (uint32_t)(k & 1) * GP_STAGE;
#pragma unroll
        for (int u = 0; u < 2; u++) {
            int lin = u * 256 + tid;
            int r = lin >> 2, seg = lin & 3;
            uint32_t so = r * GP_PITCH + seg * 16;
            size_t goA = (size_t)(rowBase + r) * GK + k0 + seg * 8;
            size_t goB = (size_t)(colBase + r) * GK + k0 + seg * 8;
            cp16(dst + so, Ahi + goA);
            cp16(dst + GP_ALO + so, Alo + goA);
            cp16(dst + GP_BHI + so, Bhi + goB);
            cp16(dst + GP_BLO + so, Blo + goB);
        }
        cp_commit();
    };

    issue(0);
    for (int k = 0; k < 32; k++) {
        if (k + 1 < 32) {
            issue(k + 1);                                   // writes stage (k+1)&1
            asm volatile("cp.async.wait_group 1;" ::: "memory");  // chunk k ready
        } else {
            asm volatile("cp.async.wait_group 0;" ::: "memory");
        }
        __syncthreads();

        const uint32_t St = sb + (uint32_t)(k & 1) * GP_STAGE;
#pragma unroll
        for (int ks = 0; ks < 2; ks++) {
            uint4 ah[4], al[4];
            uint2 bh[4], bl[4];
            const uint32_t aro = (wm + (lane & 15)) * GP_PITCH
                               + (ks * 16 + (lane >> 4) * 8) * 2;
#pragma unroll
            for (int mi = 0; mi < 4; mi++) {
                ldsm_x4(ah[mi], St + aro + mi * 16 * GP_PITCH);
                ldsm_x4(al[mi], St + GP_ALO + aro + mi * 16 * GP_PITCH);
            }
            const uint32_t bro = (wn + (lane & 7)) * GP_PITCH
                               + (ks * 16 + ((lane >> 3) & 1) * 8) * 2;
#pragma unroll
            for (int ni = 0; ni < 4; ni++) {
                ldsm_x2(bh[ni], St + GP_BHI + bro + ni * 8 * GP_PITCH);
                ldsm_x2(bl[ni], St + GP_BLO + bro + ni * 8 * GP_PITCH);
            }
#pragma unroll
            for (int mi = 0; mi < 4; mi++)
#pragma unroll
                for (int ni = 0; ni < 4; ni++) {
                    mma16816(acc[mi][ni], ah[mi], bh[ni]);
                    mma16816(acc[mi][ni], ah[mi], bl[ni]);
                    mma16816(acc[mi][ni], al[mi], bh[ni]);
                }
        }
        __syncthreads();   // stage k&1 fully consumed before issue(k+2) reuses it
    }

#pragma unroll
    for (int mi = 0; mi < 4; mi++) {
#pragma unroll
        for (int ni = 0; ni < 4; ni++) {
            int r0 = rowBase + wm + mi * 16 + (lane >> 2);
            int col = colBase + wn + ni * 8 + (lane & 3) * 2;
            float b0 = bias[col], b1 = bias[col + 1];
            float2 v0 = make_float2(acc[mi][ni][0] + b0, acc[mi][ni][1] + b1);
            float2 v1 = make_float2(acc[mi][ni][2] + b0, acc[mi][ni][3] + b1);
            *(float2*)&C[(size_t)r0 * Ndim + col] = v0;
            *(float2*)&C[(size_t)(r0 + 8) * Ndim + col] = v1;
        }
    }
}

// ---------------------------------------------------------------------------
// Split QKV -> [B,H,S,HD], RoPE on Q/K, emit bf16 hi/lo directly.
// ---------------------------------------------------------------------------
__global__ void split_rope_kernel() {
    int idx = blockIdx.x * blockDim.x + threadIdx.x;
    int i = idx & 31;
    int h = (idx >> 5) & 15;
    int s = (idx >> 9) & (Sc - 1);
    int b = idx >> 20;

    int row = b * Sc + s;
    const float* src = g_qkv + (size_t)row * NQKV + h * HDc + 2 * i;
    float q0 = src[0],        q1 = src[1];
    float k0 = src[Ec],       k1 = src[Ec + 1];
    float v0 = src[2 * Ec],   v1 = src[2 * Ec + 1];

    float c  = g_cos[s * RHALF + i];
    float sn = g_sin[s * RHALF + i];

    float qa = q0 * c - q1 * sn, qb = q1 * c + q0 * sn;
    float ka = k0 * c - k1 * sn, kb = k1 * c + k0 * sn;

    size_t dst = (((size_t)(b * Hc + h)) * Sc + s) * HDc + 2 * i;

    __nv_bfloat162 qh = __floats2bfloat162_rn(qa, qb);
    __nv_bfloat162 kh = __floats2bfloat162_rn(ka, kb);
    __nv_bfloat162 vh = __floats2bfloat162_rn(v0, v1);
    __nv_bfloat162 ql = __floats2bfloat162_rn(qa - __low2float(qh), qb - __high2float(qh));
    __nv_bfloat162 kl = __floats2bfloat162_rn(ka - __low2float(kh), kb - __high2float(kh));
    __nv_bfloat162 vl = __floats2bfloat162_rn(v0 - __low2float(vh), v1 - __high2float(vh));

    *(__nv_bfloat162*)&g_qhi[dst] = qh;  *(__nv_bfloat162*)&g_qlo[dst] = ql;
    *(__nv_bfloat162*)&g_khi[dst] = kh;  *(__nv_bfloat162*)&g_klo[dst] = kl;
    *(__nv_bfloat162*)&g_vhi[dst] = vh;  *(__nv_bfloat162*)&g_vlo[dst] = vl;
}

// ---------------------------------------------------------------------------
// Tensor-core flash attention (split bf16, fp32 softmax). Unchanged (round 4).
// ---------------------------------------------------------------------------
constexpr int AT_PITCH = 144;
constexpr int AT_QHI = 0;
constexpr int AT_QLO = 128 * AT_PITCH;            // 18432
constexpr int AT_KV  = 2 * 128 * AT_PITCH;        // 36864
constexpr int AT_KVBUF = 4 * 64 * AT_PITCH;       // 36864 per buffer
constexpr int AT_KLO = 64 * AT_PITCH;
constexpr int AT_VHI = 2 * 64 * AT_PITCH;
constexpr int AT_VLO = 3 * 64 * AT_PITCH;
constexpr int AT_MSK = AT_KV + 2 * AT_KVBUF;      // 110592
constexpr int AT_SMEM = AT_MSK + 2 * 64 * 4;      // 111104

__global__ __launch_bounds__(256) void attn_mma_kernel(const int* __restrict__ mask)
{
    extern __shared__ char smA[];
    const uint32_t sb = smem_to_u32(smA);
    float* smask = (float*)(smA + AT_MSK);

    const int tid = threadIdx.x;
    const int lane = tid & 31;
    const int wid = tid >> 5;
    const int bh = blockIdx.y;
    const int b = bh >> 4, h = bh & 15;
    const int q0 = blockIdx.x * 128;

    const size_t base = (size_t)bh * Sc * HDc;
    const __nv_bfloat16* Qh = g_qhi + base + (size_t)q0 * HDc;
    const __nv_bfloat16* Ql = g_qlo + base + (size_t)q0 * HDc;
    const __nv_bfloat16* Kh = g_khi + base;
    const __nv_bfloat16* Kl = g_klo + base;
    const __nv_bfloat16* Vh = g_vhi + base;
    const __nv_bfloat16* Vl = g_vlo + base;
    const int* mg = mask + b * Sc;

#pragma unroll
    for (int u = 0; u < 4; u++) {
        int lin = u * 256 + tid;
        int r = lin >> 3, seg = lin & 7;
        cp16(sb + AT_QHI + r * AT_PITCH + seg * 16, Qh + (size_t)r * HDc + seg * 8);
        cp16(sb + AT_QLO + r * AT_PITCH + seg * 16, Ql + (size_t)r * HDc + seg * 8);
    }

    auto issueKV = [&](int it) {
        const uint32_t dst = sb + AT_KV + (uint32_t)(it & 1) * AT_KVBUF;
        const size_t koff = (size_t)it * 64 * HDc;
#pragma unroll
        for (int u = 0; u < 2; u++) {
            int lin = u * 256 + tid;
            int r = lin >> 3, seg = lin & 7;
            size_t off = koff + (size_t)r * HDc + seg * 8;
            uint32_t so = r * AT_PITCH + seg * 16;
            cp16(dst + so, Kh + off);
            cp16(dst + AT_KLO + so, Kl + off);
            cp16(dst + AT_VHI + so, Vh + off);
            cp16(dst + AT_VLO + so, Vl + off);
        }
        if (tid < 64) smask[(it & 1) * 64 + tid] = mg[it * 64 + tid] ? 0.f : -1e30f;
        cp_commit();
    };

    issueKV(0);
    issueKV(1);
    asm volatile("cp.async.wait_group 1;" ::: "memory");
    __syncthreads();

    uint4 qh[4], ql[4];
#pragma unroll
    for (int ks = 0; ks < 4; ks++) {
        uint32_t ro = (wid * 16 + (lane & 15)) * AT_PITCH + (ks * 16 + (lane >> 4) * 8) * 2;
        ldsm_x4(qh[ks], sb + AT_QHI + ro);
        ldsm_x4(ql[ks], sb + AT_QLO + ro);
    }

    float accO[8][4];
#pragma unroll
    for (int nd = 0; nd < 8; nd++)
#pragma unroll
        for (int e = 0; e < 4; e++) accO[nd][e] = 0.f;
    float m0 = -1e30f, m1 = -1e30f, l0 = 0.f, l1 = 0.f;
    const float scale = 0.125f;
    const float LOG2E = 1.4426950408889634f;

    for (int it = 0; it < 32; it++) {
        if (it > 0) {
            if (it == 31) asm volatile("cp.async.wait_group 0;" ::: "memory");
            else          asm volatile("cp.async.wait_group 1;" ::: "memory");
            __syncthreads();
        }
        const uint32_t Kb = sb + AT_KV + (uint32_t)(it & 1) * AT_KVBUF;
        const int mbuf = (it & 1) * 64;

        float s[8][4];
#pragma unroll
        for (int ni = 0; ni < 8; ni++)
#pragma unroll
            for (int e = 0; e < 4; e++) s[ni][e] = 0.f;
#pragma unroll
        for (int ks = 0; ks < 4; ks++) {
            uint2 bkh[8], bkl[8];
            uint32_t co = (ks * 16 + ((lane >> 3) & 1) * 8) * 2;
#pragma unroll
            for (int ni = 0; ni < 8; ni++) {
                uint32_t ro = (ni * 8 + (lane & 7)) * AT_PITCH + co;
                ldsm_x2(bkh[ni], Kb + ro);
                ldsm_x2(bkl[ni], Kb + AT_KLO + ro);
            }
#pragma unroll
            for (int ni = 0; ni < 8; ni++) {
                mma16816(s[ni], qh[ks], bkh[ni]);
                mma16816(s[ni], qh[ks], bkl[ni]);
                mma16816(s[ni], ql[ks], bkh[ni]);
            }
        }

#pragma unroll
        for (int ni = 0; ni < 8; ni++) {
            float b0 = smask[mbuf + ni * 8 + (lane & 3) * 2];
            float b1 = smask[mbuf + ni * 8 + (lane & 3) * 2 + 1];
            s[ni][0] = s[ni][0] * scale + b0;
            s[ni][1] = s[ni][1] * scale + b1;
            s[ni][2] = s[ni][2] * scale + b0;
            s[ni][3] = s[ni][3] * scale + b1;
        }

        float mx0 = -1e30f, mx1 = -1e30f;
#pragma unroll
        for (int ni = 0; ni < 8; ni++) {
            mx0 = fmaxf(mx0, fmaxf(s[ni][0], s[ni][1]));
            mx1 = fmaxf(mx1, fmaxf(s[ni][2], s[ni][3]));
        }
        mx0 = fmaxf(mx0, __shfl_xor_sync(0xffffffffu, mx0, 1));
        mx0 = fmaxf(mx0, __shfl_xor_sync(0xffffffffu, mx0, 2));
        mx1 = fmaxf(mx1, __shfl_xor_sync(0xffffffffu, mx1, 1));
        mx1 = fmaxf(mx1, __shfl_xor_sync(0xffffffffu, mx1, 2));
        float mn0 = fmaxf(m0, mx0), mn1 = fmaxf(m1, mx1);
        float al0 = ex2f((m0 - mn0) * LOG2E);
        float al1 = ex2f((m1 - mn1) * LOG2E);
        float sum0 = 0.f, sum1 = 0.f;
#pragma unroll
        for (int ni = 0; ni < 8; ni++) {
            s[ni][0] = ex2f((s[ni][0] - mn0) * LOG2E);
            s[ni][1] = ex2f((s[ni][1] - mn0) * LOG2E);
            s[ni][2] = ex2f((s[ni][2] - mn1) * LOG2E);
            s[ni][3] = ex2f((s[ni][3] - mn1) * LOG2E);
            sum0 += s[ni][0] + s[ni][1];
            sum1 += s[ni][2] + s[ni][3];
        }
        sum0 += __shfl_xor_sync(0xffffffffu, sum0, 1);
        sum0 += __shfl_xor_sync(0xffffffffu, sum0, 2);
        sum1 += __shfl_xor_sync(0xffffffffu, sum1, 1);
        sum1 += __shfl_xor_sync(0xffffffffu, sum1, 2);
        l0 = l0 * al0 + sum0;
        l1 = l1 * al1 + sum1;
        m0 = mn0; m1 = mn1;
#pragma unroll
        for (int nd = 0; nd < 8; nd++) {
            accO[nd][0] *= al0; accO[nd][1] *= al0;
            accO[nd][2] *= al1; accO[nd][3] *= al1;
        }

        uint4 aph[4], apl[4];
#pragma unroll
        for (int ks2 = 0; ks2 < 4; ks2++) {
            const float* p0 = s[2 * ks2];
            const float* p1 = s[2 * ks2 + 1];
            aph[ks2].x = packbf(p0[0], p0[1]);
            aph[ks2].y = packbf(p0[2], p0[3]);
            aph[ks2].z = packbf(p1[0], p1[1]);
            aph[ks2].w = packbf(p1[2], p1[3]);
            __nv_bfloat162 h;
            h = *(__nv_bfloat162*)&aph[ks2].x;
            apl[ks2].x = packbf(p0[0] - __low2float(h), p0[1] - __high2float(h));
            h = *(__nv_bfloat162*)&aph[ks2].y;
            apl[ks2].y = packbf(p0[2] - __low2float(h), p0[3] - __high2float(h));
            h = *(__nv_bfloat162*)&aph[ks2].z;
            apl[ks2].z = packbf(p1[0] - __low2float(h), p1[1] - __high2float(h));
            h = *(__nv_bfloat162*)&aph[ks2].w;
            apl[ks2].w = packbf(p1[2] - __low2float(h), p1[3] - __high2float(h));
        }

#pragma unroll
        for (int ks2 = 0; ks2 < 4; ks2++) {
            uint2 bvh[8], bvl[8];
            uint32_t rbase = (ks2 * 16 + (lane & 15)) * AT_PITCH;
#pragma unroll
            for (int nd = 0; nd < 8; nd++) {
                ldsm_x2t(bvh[nd], Kb + AT_VHI + rbase + nd * 16);
                ldsm_x2t(bvl[nd], Kb + AT_VLO + rbase + nd * 16);
            }
#pragma unroll
            for (int nd = 0; nd < 8; nd++) {
                mma16816(accO[nd], aph[ks2], bvh[nd]);
                mma16816(accO[nd], apl[ks2], bvh[nd]);
                mma16816(accO[nd], aph[ks2], bvl[nd]);
            }
        }

        __syncthreads();
        if (it + 2 < 32) issueKV(it + 2);
    }

    float inv0 = 1.f / l0, inv1 = 1.f / l1;
    int r0 = q0 + wid * 16 + (lane >> 2);
    int colb = h * HDc + (lane & 3) * 2;
#pragma unroll
    for (int nd = 0; nd < 8; nd++) {
        float c00 = accO[nd][0] * inv0, c01 = accO[nd][1] * inv0;
        float c10 = accO[nd][2] * inv1, c11 = accO[nd][3] * inv1;
        size_t i0 = (size_t)(b * Sc + r0) * Ec + colb + nd * 8;
        size_t i1 = (size_t)(b * Sc + r0 + 8) * Ec + colb + nd * 8;
        __nv_bfloat162 h0 = __floats2bfloat162_rn(c00, c01);
        __nv_bfloat162 h1 = __floats2bfloat162_rn(c10, c11);
        __nv_bfloat162 l0v = __floats2bfloat162_rn(c00 - __low2float(h0), c01 - __high2float(h0));
        __nv_bfloat162 l1v = __floats2bfloat162_rn(c10 - __low2float(h1), c11 - __high2float(h1));
        *(__nv_bfloat162*)&g_ctx_hi[i0] = h0;
        *(__nv_bfloat162*)&g_ctx_lo[i0] = l0v;
        *(__nv_bfloat162*)&g_ctx_hi[i1] = h1;
        *(__nv_bfloat162*)&g_ctx_lo[i1] = l1v;
    }
}

// ---------------------------------------------------------------------------
extern "C" void kernel_launch(void* const* d_in, const int* in_sizes, int n_in,
                              void* d_out, int out_size)
{
    const float* x     = (const float*)d_in[0];
    const int*   mask  = (const int*)d_in[1];
    const float* qkv_w = (const float*)d_in[2];
    const float* qkv_b = (const float*)d_in[3];
    const float* out_w = (const float*)d_in[4];
    const float* out_b = (const float*)d_in[5];
    float* out = (float*)d_out;

    float* qkv_ptr = nullptr;
    cudaGetSymbolAddress((void**)&qkv_ptr, g_qkv);
    __nv_bfloat16 *xhi, *xlo, *whi, *wlo, *owhi, *owlo, *chi, *clo;
    cudaGetSymbolAddress((void**)&xhi,  g_xhi);
    cudaGetSymbolAddress((void**)&xlo,  g_xlo);
    cudaGetSymbolAddress((void**)&whi,  g_wqkv_hi);
    cudaGetSymbolAddress((void**)&wlo,  g_wqkv_lo);
    cudaGetSymbolAddress((void**)&owhi, g_wout_hi);
    cudaGetSymbolAddress((void**)&owlo, g_wout_lo);
    cudaGetSymbolAddress((void**)&chi,  g_ctx_hi);
    cudaGetSymbolAddress((void**)&clo,  g_ctx_lo);

    cudaFuncSetAttribute(gemm_mma_bf16x3,
                         cudaFuncAttributeMaxDynamicSharedMemorySize, GP_SMEM);
    cudaFuncSetAttribute(attn_mma_kernel,
                         cudaFuncAttributeMaxDynamicSharedMemorySize, AT_SMEM);

    // 1. RoPE tables
    rope_table_kernel<<<(Sc * RHALF + 255) / 256, 256>>>();

    // 2. Split inputs/weights into bf16 hi/lo
    split_bf16_kernel<<<(Mc * Ec / 4 + 255) / 256, 256>>>(x, xhi, xlo, Mc * Ec / 4);
    split_bf16_kernel<<<(NQKV * Ec / 4 + 255) / 256, 256>>>(qkv_w, whi, wlo, NQKV * Ec / 4);
    split_bf16_kernel<<<(Ec * Ec / 4 + 255) / 256, 256>>>(out_w, owhi, owlo, Ec * Ec / 4);

    // 3. QKV projection (fused-term warp-mma, 2 CTAs/SM)
    gemm_mma_bf16x3<<<dim3(NQKV / 128, Mc / 128), 256, GP_SMEM>>>(
        xhi, xlo, whi, wlo, qkv_b, qkv_ptr, NQKV);

    // 4. Split + RoPE -> bf16 hi/lo q/k/v
    split_rope_kernel<<<(Bc * Sc * Hc * RHALF) / 256, 256>>>();

    // 5. Tensor-core flash attention -> ctx hi/lo
    attn_mma_kernel<<<dim3(Sc / 128, Bc * Hc), 256, AT_SMEM>>>(mask);

    // 6. Output projection (fused-term warp-mma, 2 CTAs/SM)
    gemm_mma_bf16x3<<<dim3(Ec / 128, Mc / 128), 256, GP_SMEM>>>(
        chi, clo, owhi, owlo, out_b, out, Ec);
}

// round 8
// speedup vs baseline: 3.9685x; 1.3427x over previous
#include <cuda_runtime.h>
#include <cuda_fp16.h>
#include <cstdint>
#include <cmath>

// Problem constants
constexpr int Bc  = 2;
constexpr int Sc  = 2048;
constexpr int Ec  = 1024;
constexpr int Hc  = 16;
constexpr int HDc = 64;
constexpr int Mc  = Bc * Sc;        // 4096 rows
constexpr int NQKV = 3 * Ec;        // 3072
constexpr int RHALF = 32;           // rotary pairs per head (ROT=64)
constexpr int GK = 1024;            // K dim of both projection GEMMs

// Scratch (static device globals; no allocation)
__device__ float g_qkv[(size_t)Mc * NQKV];
__device__ float g_cos[Sc * RHALF];
__device__ float g_sin[Sc * RHALF];

// fp16 buffers (split: hi/lo where needed; plain otherwise)
__device__ __half g_xhi[(size_t)Mc * Ec];
__device__ __half g_xlo[(size_t)Mc * Ec];
__device__ __half g_wqkv[(size_t)NQKV * Ec];
__device__ __half g_wout[(size_t)Ec * Ec];
__device__ __half g_ctx_hi[(size_t)Mc * Ec];
__device__ __half g_ctx_lo[(size_t)Mc * Ec];

// q split / k plain / v split, [B,H,S,HD] layout
constexpr size_t QKV_ELEMS = (size_t)Bc * Hc * Sc * HDc;
__device__ __half g_qh[QKV_ELEMS];
__device__ __half g_ql[QKV_ELEMS];
__device__ __half g_k16[QKV_ELEMS];
__device__ __half g_vh[QKV_ELEMS];
__device__ __half g_vl[QKV_ELEMS];

// ---------------------------------------------------------------------------
// Portable (compute_103-safe) tensor-core helpers
// ---------------------------------------------------------------------------
__device__ __forceinline__ uint32_t smem_to_u32(const void* p) {
    uint32_t a;
    asm("{ .reg .u64 t; cvta.to.shared.u64 t, %1; cvt.u32.u64 %0, t; }"
        : "=r"(a) : "l"(p));
    return a;
}
__device__ __forceinline__ void cp16(uint32_t dst, const void* src) {
    asm volatile("cp.async.cg.shared.global [%0], [%1], 16;"
                 :: "r"(dst), "l"(src));
}
__device__ __forceinline__ void cp_commit() {
    asm volatile("cp.async.commit_group;" ::: "memory");
}
__device__ __forceinline__ void ldsm_x4(uint4& r, uint32_t addr) {
    asm volatile("ldmatrix.sync.aligned.m8n8.x4.shared.b16 {%0,%1,%2,%3}, [%4];"
                 : "=r"(r.x), "=r"(r.y), "=r"(r.z), "=r"(r.w) : "r"(addr));
}
__device__ __forceinline__ void ldsm_x2(uint2& r, uint32_t addr) {
    asm volatile("ldmatrix.sync.aligned.m8n8.x2.shared.b16 {%0,%1}, [%2];"
                 : "=r"(r.x), "=r"(r.y) : "r"(addr));
}
__device__ __forceinline__ void ldsm_x2t(uint2& r, uint32_t addr) {
    asm volatile("ldmatrix.sync.aligned.m8n8.x2.trans.shared.b16 {%0,%1}, [%2];"
                 : "=r"(r.x), "=r"(r.y) : "r"(addr));
}
// fp16 inputs, fp32 accumulate
__device__ __forceinline__ void mmah(float* d, const uint4& a, const uint2& b) {
    asm volatile(
        "mma.sync.aligned.m16n8k16.row.col.f32.f16.f16.f32 "
        "{%0,%1,%2,%3}, {%4,%5,%6,%7}, {%8,%9}, {%0,%1,%2,%3};"
        : "+f"(d[0]), "+f"(d[1]), "+f"(d[2]), "+f"(d[3])
        : "r"(a.x), "r"(a.y), "r"(a.z), "r"(a.w), "r"(b.x), "r"(b.y));
}
__device__ __forceinline__ float ex2f(float x) {
    float r; asm("ex2.approx.f32 %0, %1;" : "=f"(r) : "f"(x)); return r;
}
__device__ __forceinline__ uint32_t packh(float lo, float hi) {
    __half2 t = __floats2half2_rn(lo, hi);
    return *(uint32_t*)&t;
}

// ---------------------------------------------------------------------------
// RoPE cos/sin table
// ---------------------------------------------------------------------------
__global__ void rope_table_kernel() {
    int idx = blockIdx.x * blockDim.x + threadIdx.x;
    if (idx >= Sc * RHALF) return;
    int s = idx / RHALF;
    int i = idx % RHALF;
    double inv_freq = exp(-(double)(2 * i) / 64.0 * log(10000.0));
    double ang = (double)s * inv_freq;
    g_cos[idx] = (float)cos(ang);
    g_sin[idx] = (float)sin(ang);
}

// ---------------------------------------------------------------------------
// fp32 -> (fp16 hi, fp16 lo) split  /  fp32 -> fp16 plain
// ---------------------------------------------------------------------------
__global__ void split_f16_pair_kernel(const float* __restrict__ src,
                                      __half* __restrict__ hi,
                                      __half* __restrict__ lo, int n4) {
    int i = blockIdx.x * blockDim.x + threadIdx.x;
    if (i >= n4) return;
    float4 v = ((const float4*)src)[i];
    __half h0 = __float2half_rn(v.x), h1 = __float2half_rn(v.y);
    __half h2 = __float2half_rn(v.z), h3 = __float2half_rn(v.w);
    __half l0 = __float2half_rn(v.x - __half2float(h0));
    __half l1 = __float2half_rn(v.y - __half2float(h1));
    __half l2 = __float2half_rn(v.z - __half2float(h2));
    __half l3 = __float2half_rn(v.w - __half2float(h3));
    __half2* hp = (__half2*)hi;
    __half2* lp = (__half2*)lo;
    hp[2 * i]     = __half2(h0, h1);
    hp[2 * i + 1] = __half2(h2, h3);
    lp[2 * i]     = __half2(l0, l1);
    lp[2 * i + 1] = __half2(l2, l3);
}

__global__ void cvt_f16_kernel(const float* __restrict__ src,
                               __half* __restrict__ dst, int n4) {
    int i = blockIdx.x * blockDim.x + threadIdx.x;
    if (i >= n4) return;
    float4 v = ((const float4*)src)[i];
    __half2* dp = (__half2*)dst;
    dp[2 * i]     = __floats2half2_rn(v.x, v.y);
    dp[2 * i + 1] = __floats2half2_rn(v.z, v.w);
}

// ---------------------------------------------------------------------------
// Warp-mma fp16 2-term GEMM: C = (Ahi + Alo) @ B16^T + bias
// 128x128 CTA tile, BK=32, 8 warps (64x32 each). K=1024 -> 32 chunks.
// Per stage: Ahi | Alo | B tiles (128x32 fp16, 80B pitch). 60 KB smem.
// Proven-safe pipeline ordering (round 7): issue(k+1) before wait(k).
// ---------------------------------------------------------------------------
constexpr int GP_PITCH = 80;
constexpr int GP_TILE  = 128 * GP_PITCH;        // 10240
constexpr int GP_ALO   = GP_TILE;
constexpr int GP_B     = 2 * GP_TILE;
constexpr int GP_STAGE = 3 * GP_TILE;           // 30720
constexpr int GP_SMEM  = 2 * GP_STAGE;          // 61440

__global__ __launch_bounds__(256, 2) void gemm_mma_f16x2(
    const __half* __restrict__ Ahi, const __half* __restrict__ Alo,
    const __half* __restrict__ B16,
    const float* __restrict__ bias, float* __restrict__ C, int Ndim)
{
    extern __shared__ char smg[];
    const uint32_t sb = smem_to_u32(smg);
    const int tid = threadIdx.x;
    const int lane = tid & 31;
    const int wid = tid >> 5;
    const int rowBase = blockIdx.y * 128;
    const int colBase = blockIdx.x * 128;
    const int wm = (wid >> 2) * 64;
    const int wn = (wid & 3) * 32;

    float acc[4][4][4];
#pragma unroll
    for (int mi = 0; mi < 4; mi++)
#pragma unroll
        for (int ni = 0; ni < 4; ni++)
#pragma unroll
            for (int e = 0; e < 4; e++) acc[mi][ni][e] = 0.f;

    auto issue = [&](int k) {
        const int k0 = k * 32;
        const uint32_t dst = sb + (uint32_t)(k & 1) * GP_STAGE;
#pragma unroll
        for (int u = 0; u < 2; u++) {
            int lin = u * 256 + tid;
            int r = lin >> 2, seg = lin & 3;
            uint32_t so = r * GP_PITCH + seg * 16;
            size_t goA = (size_t)(rowBase + r) * GK + k0 + seg * 8;
            size_t goB = (size_t)(colBase + r) * GK + k0 + seg * 8;
            cp16(dst + so, Ahi + goA);
            cp16(dst + GP_ALO + so, Alo + goA);
            cp16(dst + GP_B + so, B16 + goB);
        }
        cp_commit();
    };

    issue(0);
    for (int k = 0; k < 32; k++) {
        if (k + 1 < 32) {
            issue(k + 1);
            asm volatile("cp.async.wait_group 1;" ::: "memory");
        } else {
            asm volatile("cp.async.wait_group 0;" ::: "memory");
        }
        __syncthreads();

        const uint32_t St = sb + (uint32_t)(k & 1) * GP_STAGE;
#pragma unroll
        for (int ks = 0; ks < 2; ks++) {
            uint4 ah[4], al[4];
            uint2 b[4];
            const uint32_t aro = (wm + (lane & 15)) * GP_PITCH
                               + (ks * 16 + (lane >> 4) * 8) * 2;
#pragma unroll
            for (int mi = 0; mi < 4; mi++) {
                ldsm_x4(ah[mi], St + aro + mi * 16 * GP_PITCH);
                ldsm_x4(al[mi], St + GP_ALO + aro + mi * 16 * GP_PITCH);
            }
            const uint32_t bro = (wn + (lane & 7)) * GP_PITCH
                               + (ks * 16 + ((lane >> 3) & 1) * 8) * 2;
#pragma unroll
            for (int ni = 0; ni < 4; ni++)
                ldsm_x2(b[ni], St + GP_B + bro + ni * 8 * GP_PITCH);
#pragma unroll
            for (int mi = 0; mi < 4; mi++)
#pragma unroll
                for (int ni = 0; ni < 4; ni++) {
                    mmah(acc[mi][ni], ah[mi], b[ni]);
                    mmah(acc[mi][ni], al[mi], b[ni]);
                }
        }
        __syncthreads();
    }

#pragma unroll
    for (int mi = 0; mi < 4; mi++) {
#pragma unroll
        for (int ni = 0; ni < 4; ni++) {
            int r0 = rowBase + wm + mi * 16 + (lane >> 2);
            int col = colBase + wn + ni * 8 + (lane & 3) * 2;
            float b0 = bias[col], b1 = bias[col + 1];
            float2 v0 = make_float2(acc[mi][ni][0] + b0, acc[mi][ni][1] + b1);
            float2 v1 = make_float2(acc[mi][ni][2] + b0, acc[mi][ni][3] + b1);
            *(float2*)&C[(size_t)r0 * Ndim + col] = v0;
            *(float2*)&C[(size_t)(r0 + 8) * Ndim + col] = v1;
        }
    }
}

// ---------------------------------------------------------------------------
// Split QKV -> [B,H,S,HD], RoPE on Q/K; emit q hi/lo, k plain, v hi/lo (fp16)
// ---------------------------------------------------------------------------
__global__ void split_rope_kernel() {
    int idx = blockIdx.x * blockDim.x + threadIdx.x;
    int i = idx & 31;
    int h = (idx >> 5) & 15;
    int s = (idx >> 9) & (Sc - 1);
    int b = idx >> 20;

    int row = b * Sc + s;
    const float* src = g_qkv + (size_t)row * NQKV + h * HDc + 2 * i;
    float q0 = src[0],        q1 = src[1];
    float k0 = src[Ec],       k1 = src[Ec + 1];
    float v0 = src[2 * Ec],   v1 = src[2 * Ec + 1];

    float c  = g_cos[s * RHALF + i];
    float sn = g_sin[s * RHALF + i];

    float qa = q0 * c - q1 * sn, qb = q1 * c + q0 * sn;
    float ka = k0 * c - k1 * sn, kb = k1 * c + k0 * sn;

    size_t dst = (((size_t)(b * Hc + h)) * Sc + s) * HDc + 2 * i;

    __half2 qh2 = __floats2half2_rn(qa, qb);
    __half2 vh2 = __floats2half2_rn(v0, v1);
    __half2 ql2 = __floats2half2_rn(qa - __low2float(qh2), qb - __high2float(qh2));
    __half2 vl2 = __floats2half2_rn(v0 - __low2float(vh2), v1 - __high2float(vh2));

    *(__half2*)&g_qh[dst]  = qh2;
    *(__half2*)&g_ql[dst]  = ql2;
    *(__half2*)&g_k16[dst] = __floats2half2_rn(ka, kb);
    *(__half2*)&g_vh[dst]  = vh2;
    *(__half2*)&g_vl[dst]  = vl2;
}

// ---------------------------------------------------------------------------
// Tensor-core flash attention, fp16 2-term:
//   S = (Qhi + Qlo) K^T ;  O += P (Vhi + Vlo)   (fp32 accum/softmax)
// 128 q-rows/CTA, 64-key tiles, 8 warps, HD=64. ~92 KB smem -> 2 CTAs/SM.
// ---------------------------------------------------------------------------
constexpr int AT_PITCH = 144;
constexpr int AT_QHI = 0;
constexpr int AT_QLO = 128 * AT_PITCH;            // 18432
constexpr int AT_KV  = 2 * 128 * AT_PITCH;        // 36864
constexpr int AT_VHI = 64 * AT_PITCH;             // offsets within buffer
constexpr int AT_VLO = 2 * 64 * AT_PITCH;
constexpr int AT_KVBUF = 3 * 64 * AT_PITCH;       // 27648 per buffer
constexpr int AT_MSK = AT_KV + 2 * AT_KVBUF;      // 92160
constexpr int AT_SMEM = AT_MSK + 2 * 64 * 4;      // 92672

__global__ __launch_bounds__(256) void attn_mma_kernel(const int* __restrict__ mask)
{
    extern __shared__ char smA[];
    const uint32_t sb = smem_to_u32(smA);
    float* smask = (float*)(smA + AT_MSK);

    const int tid = threadIdx.x;
    const int lane = tid & 31;
    const int wid = tid >> 5;
    const int bh = blockIdx.y;
    const int b = bh >> 4, h = bh & 15;
    const int q0 = blockIdx.x * 128;

    const size_t base = (size_t)bh * Sc * HDc;
    const __half* Qh = g_qh + base + (size_t)q0 * HDc;
    const __half* Ql = g_ql + base + (size_t)q0 * HDc;
    const __half* Kg = g_k16 + base;
    const __half* Vh = g_vh + base;
    const __half* Vl = g_vl + base;
    const int* mg = mask + b * Sc;

    // Q tiles -> smem
#pragma unroll
    for (int u = 0; u < 4; u++) {
        int lin = u * 256 + tid;
        int r = lin >> 3, seg = lin & 7;
        cp16(sb + AT_QHI + r * AT_PITCH + seg * 16, Qh + (size_t)r * HDc + seg * 8);
        cp16(sb + AT_QLO + r * AT_PITCH + seg * 16, Ql + (size_t)r * HDc + seg * 8);
    }

    auto issueKV = [&](int it) {
        const uint32_t dst = sb + AT_KV + (uint32_t)(it & 1) * AT_KVBUF;
        const size_t koff = (size_t)it * 64 * HDc;
#pragma unroll
        for (int u = 0; u < 2; u++) {
            int lin = u * 256 + tid;
            int r = lin >> 3, seg = lin & 7;
            size_t off = koff + (size_t)r * HDc + seg * 8;
            uint32_t so = r * AT_PITCH + seg * 16;
            cp16(dst + so, Kg + off);
            cp16(dst + AT_VHI + so, Vh + off);
            cp16(dst + AT_VLO + so, Vl + off);
        }
        if (tid < 64) smask[(it & 1) * 64 + tid] = mg[it * 64 + tid] ? 0.f : -1e30f;
        cp_commit();
    };

    issueKV(0);
    issueKV(1);
    asm volatile("cp.async.wait_group 1;" ::: "memory");
    __syncthreads();

    // Q fragments held in registers
    uint4 qh[4], ql[4];
#pragma unroll
    for (int ks = 0; ks < 4; ks++) {
        uint32_t ro = (wid * 16 + (lane & 15)) * AT_PITCH + (ks * 16 + (lane >> 4) * 8) * 2;
        ldsm_x4(qh[ks], sb + AT_QHI + ro);
        ldsm_x4(ql[ks], sb + AT_QLO + ro);
    }

    float accO[8][4];
#pragma unroll
    for (int nd = 0; nd < 8; nd++)
#pragma unroll
        for (int e = 0; e < 4; e++) accO[nd][e] = 0.f;
    float m0 = -1e30f, m1 = -1e30f, l0 = 0.f, l1 = 0.f;
    const float scale = 0.125f;
    const float LOG2E = 1.4426950408889634f;

    for (int it = 0; it < 32; it++) {
        if (it > 0) {
            if (it == 31) asm volatile("cp.async.wait_group 0;" ::: "memory");
            else          asm volatile("cp.async.wait_group 1;" ::: "memory");
            __syncthreads();
        }
        const uint32_t Kb = sb + AT_KV + (uint32_t)(it & 1) * AT_KVBUF;
        const int mbuf = (it & 1) * 64;

        // ---- S = Q K^T (2-term fp16) ----
        float s[8][4];
#pragma unroll
        for (int ni = 0; ni < 8; ni++)
#pragma unroll
            for (int e = 0; e < 4; e++) s[ni][e] = 0.f;
#pragma unroll
        for (int ks = 0; ks < 4; ks++) {
            uint2 bk[8];
            uint32_t co = (ks * 16 + ((lane >> 3) & 1) * 8) * 2;
#pragma unroll
            for (int ni = 0; ni < 8; ni++)
                ldsm_x2(bk[ni], Kb + (ni * 8 + (lane & 7)) * AT_PITCH + co);
#pragma unroll
            for (int ni = 0; ni < 8; ni++) {
                mmah(s[ni], qh[ks], bk[ni]);
                mmah(s[ni], ql[ks], bk[ni]);
            }
        }

        // ---- scale + mask ----
#pragma unroll
        for (int ni = 0; ni < 8; ni++) {
            float b0 = smask[mbuf + ni * 8 + (lane & 3) * 2];
            float b1 = smask[mbuf + ni * 8 + (lane & 3) * 2 + 1];
            s[ni][0] = s[ni][0] * scale + b0;
            s[ni][1] = s[ni][1] * scale + b1;
            s[ni][2] = s[ni][2] * scale + b0;
            s[ni][3] = s[ni][3] * scale + b1;
        }

        // ---- online softmax (rows lane>>2 and +8) ----
        float mx0 = -1e30f, mx1 = -1e30f;
#pragma unroll
        for (int ni = 0; ni < 8; ni++) {
            mx0 = fmaxf(mx0, fmaxf(s[ni][0], s[ni][1]));
            mx1 = fmaxf(mx1, fmaxf(s[ni][2], s[ni][3]));
        }
        mx0 = fmaxf(mx0, __shfl_xor_sync(0xffffffffu, mx0, 1));
        mx0 = fmaxf(mx0, __shfl_xor_sync(0xffffffffu, mx0, 2));
        mx1 = fmaxf(mx1, __shfl_xor_sync(0xffffffffu, mx1, 1));
        mx1 = fmaxf(mx1, __shfl_xor_sync(0xffffffffu, mx1, 2));
        float mn0 = fmaxf(m0, mx0), mn1 = fmaxf(m1, mx1);
        float al0 = ex2f((m0 - mn0) * LOG2E);
        float al1 = ex2f((m1 - mn1) * LOG2E);
        float sum0 = 0.f, sum1 = 0.f;
#pragma unroll
        for (int ni = 0; ni < 8; ni++) {
            s[ni][0] = ex2f((s[ni][0] - mn0) * LOG2E);
            s[ni][1] = ex2f((s[ni][1] - mn0) * LOG2E);
            s[ni][2] = ex2f((s[ni][2] - mn1) * LOG2E);
            s[ni][3] = ex2f((s[ni][3] - mn1) * LOG2E);
            sum0 += s[ni][0] + s[ni][1];
            sum1 += s[ni][2] + s[ni][3];
        }
        sum0 += __shfl_xor_sync(0xffffffffu, sum0, 1);
        sum0 += __shfl_xor_sync(0xffffffffu, sum0, 2);
        sum1 += __shfl_xor_sync(0xffffffffu, sum1, 1);
        sum1 += __shfl_xor_sync(0xffffffffu, sum1, 2);
        l0 = l0 * al0 + sum0;
        l1 = l1 * al1 + sum1;
        m0 = mn0; m1 = mn1;
#pragma unroll
        for (int nd = 0; nd < 8; nd++) {
            accO[nd][0] *= al0; accO[nd][1] *= al0;
            accO[nd][2] *= al1; accO[nd][3] *= al1;
        }

        // ---- P fragments (plain fp16) from S accumulators ----
        uint4 ap[4];
#pragma unroll
        for (int ks2 = 0; ks2 < 4; ks2++) {
            const float* p0 = s[2 * ks2];
            const float* p1 = s[2 * ks2 + 1];
            ap[ks2].x = packh(p0[0], p0[1]);
            ap[ks2].y = packh(p0[2], p0[3]);
            ap[ks2].z = packh(p1[0], p1[1]);
            ap[ks2].w = packh(p1[2], p1[3]);
        }

        // ---- O += P (Vhi + Vlo), V^T via ldmatrix.trans ----
#pragma unroll
        for (int ks2 = 0; ks2 < 4; ks2++) {
            uint2 bvh[8], bvl[8];
            uint32_t rbase = (ks2 * 16 + (lane & 15)) * AT_PITCH;
#pragma unroll
            for (int nd = 0; nd < 8; nd++) {
                ldsm_x2t(bvh[nd], Kb + AT_VHI + rbase + nd * 16);
                ldsm_x2t(bvl[nd], Kb + AT_VLO + rbase + nd * 16);
            }
#pragma unroll
            for (int nd = 0; nd < 8; nd++) {
                mmah(accO[nd], ap[ks2], bvh[nd]);
                mmah(accO[nd], ap[ks2], bvl[nd]);
            }
        }

        __syncthreads();
        if (it + 2 < 32) issueKV(it + 2);
    }

    // ---- epilogue: normalize, split ctx to fp16 hi/lo ----
    float inv0 = 1.f / l0, inv1 = 1.f / l1;
    int r0 = q0 + wid * 16 + (lane >> 2);
    int colb = h * HDc + (lane & 3) * 2;
#pragma unroll
    for (int nd = 0; nd < 8; nd++) {
        float c00 = accO[nd][0] * inv0, c01 = accO[nd][1] * inv0;
        float c10 = accO[nd][2] * inv1, c11 = accO[nd][3] * inv1;
        size_t i0 = (size_t)(b * Sc + r0) * Ec + colb + nd * 8;
        size_t i1 = (size_t)(b * Sc + r0 + 8) * Ec + colb + nd * 8;
        __half2 h0 = __floats2half2_rn(c00, c01);
        __half2 h1 = __floats2half2_rn(c10, c11);
        __half2 l0v = __floats2half2_rn(c00 - __low2float(h0), c01 - __high2float(h0));
        __half2 l1v = __floats2half2_rn(c10 - __low2float(h1), c11 - __high2float(h1));
        *(__half2*)&g_ctx_hi[i0] = h0;
        *(__half2*)&g_ctx_lo[i0] = l0v;
        *(__half2*)&g_ctx_hi[i1] = h1;
        *(__half2*)&g_ctx_lo[i1] = l1v;
    }
}

// ---------------------------------------------------------------------------
extern "C" void kernel_launch(void* const* d_in, const int* in_sizes, int n_in,
                              void* d_out, int out_size)
{
    const float* x     = (const float*)d_in[0];
    const int*   mask  = (const int*)d_in[1];
    const float* qkv_w = (const float*)d_in[2];
    const float* qkv_b = (const float*)d_in[3];
    const float* out_w = (const float*)d_in[4];
    const float* out_b = (const float*)d_in[5];
    float* out = (float*)d_out;

    float* qkv_ptr = nullptr;
    cudaGetSymbolAddress((void**)&qkv_ptr, g_qkv);
    __half *xhi, *xlo, *w16, *ow16, *chi, *clo;
    cudaGetSymbolAddress((void**)&xhi,  g_xhi);
    cudaGetSymbolAddress((void**)&xlo,  g_xlo);
    cudaGetSymbolAddress((void**)&w16,  g_wqkv);
    cudaGetSymbolAddress((void**)&ow16, g_wout);
    cudaGetSymbolAddress((void**)&chi,  g_ctx_hi);
    cudaGetSymbolAddress((void**)&clo,  g_ctx_lo);

    cudaFuncSetAttribute(gemm_mma_f16x2,
                         cudaFuncAttributeMaxDynamicSharedMemorySize, GP_SMEM);
    cudaFuncSetAttribute(attn_mma_kernel,
                         cudaFuncAttributeMaxDynamicSharedMemorySize, AT_SMEM);

    // 1. RoPE tables
    rope_table_kernel<<<(Sc * RHALF + 255) / 256, 256>>>();

    // 2. Convert/split inputs + weights to fp16
    split_f16_pair_kernel<<<(Mc * Ec / 4 + 255) / 256, 256>>>(x, xhi, xlo, Mc * Ec / 4);
    cvt_f16_kernel<<<(NQKV * Ec / 4 + 255) / 256, 256>>>(qkv_w, w16, NQKV * Ec / 4);
    cvt_f16_kernel<<<(Ec * Ec / 4 + 255) / 256, 256>>>(out_w, ow16, Ec * Ec / 4);

    // 3. QKV projection (fp16 2-term warp-mma)
    gemm_mma_f16x2<<<dim3(NQKV / 128, Mc / 128), 256, GP_SMEM>>>(
        xhi, xlo, w16, qkv_b, qkv_ptr, NQKV);

    // 4. Split + RoPE -> fp16 q hi/lo, k, v hi/lo
    split_rope_kernel<<<(Bc * Sc * Hc * RHALF) / 256, 256>>>();

    // 5. Tensor-core flash attention (fp16 2-term) -> ctx hi/lo
    attn_mma_kernel<<<dim3(Sc / 128, Bc * Hc), 256, AT_SMEM>>>(mask);

    // 6. Output projection (fp16 2-term warp-mma)
    gemm_mma_f16x2<<<dim3(Ec / 128, Mc / 128), 256, GP_SMEM>>>(
        chi, clo, ow16, out_b, out, Ec);
}

// round 9
// speedup vs baseline: 6.5374x; 1.6473x over previous
#include <cuda_runtime.h>
#include <cuda_fp16.h>
#include <cstdint>
#include <cmath>

// Problem constants
constexpr int Bc  = 2;
constexpr int Sc  = 2048;
constexpr int Ec  = 1024;
constexpr int Hc  = 16;
constexpr int HDc = 64;
constexpr int Mc  = Bc * Sc;        // 4096 rows
constexpr int NQKV = 3 * Ec;        // 3072
constexpr int RHALF = 32;           // rotary pairs per head (ROT=64)
constexpr int GK = 1024;            // K dim of both projection GEMMs

// Scratch (static device globals; no allocation)
__device__ float g_qkv[(size_t)Mc * NQKV];
__device__ float g_cos[Sc * RHALF];
__device__ float g_sin[Sc * RHALF];

// fp16 buffers (plain, 1-term everywhere; fp32 accumulation preserves sums)
__device__ __half g_x16[(size_t)Mc * Ec];
__device__ __half g_wqkv[(size_t)NQKV * Ec];
__device__ __half g_wout[(size_t)Ec * Ec];
__device__ __half g_ctx16[(size_t)Mc * Ec];

// q/k/v fp16 in [B,H,S,HD] layout
constexpr size_t QKV_ELEMS = (size_t)Bc * Hc * Sc * HDc;
__device__ __half g_q16[QKV_ELEMS];
__device__ __half g_k16[QKV_ELEMS];
__device__ __half g_v16[QKV_ELEMS];

// ---------------------------------------------------------------------------
// Portable (compute_103-safe) tensor-core helpers
// ---------------------------------------------------------------------------
__device__ __forceinline__ uint32_t smem_to_u32(const void* p) {
    uint32_t a;
    asm("{ .reg .u64 t; cvta.to.shared.u64 t, %1; cvt.u32.u64 %0, t; }"
        : "=r"(a) : "l"(p));
    return a;
}
__device__ __forceinline__ void cp16(uint32_t dst, const void* src) {
    asm volatile("cp.async.cg.shared.global [%0], [%1], 16;"
                 :: "r"(dst), "l"(src));
}
__device__ __forceinline__ void cp_commit() {
    asm volatile("cp.async.commit_group;" ::: "memory");
}
__device__ __forceinline__ void ldsm_x4(uint4& r, uint32_t addr) {
    asm volatile("ldmatrix.sync.aligned.m8n8.x4.shared.b16 {%0,%1,%2,%3}, [%4];"
                 : "=r"(r.x), "=r"(r.y), "=r"(r.z), "=r"(r.w) : "r"(addr));
}
__device__ __forceinline__ void ldsm_x2(uint2& r, uint32_t addr) {
    asm volatile("ldmatrix.sync.aligned.m8n8.x2.shared.b16 {%0,%1}, [%2];"
                 : "=r"(r.x), "=r"(r.y) : "r"(addr));
}
__device__ __forceinline__ void ldsm_x2t(uint2& r, uint32_t addr) {
    asm volatile("ldmatrix.sync.aligned.m8n8.x2.trans.shared.b16 {%0,%1}, [%2];"
                 : "=r"(r.x), "=r"(r.y) : "r"(addr));
}
// fp16 inputs, fp32 accumulate
__device__ __forceinline__ void mmah(float* d, const uint4& a, const uint2& b) {
    asm volatile(
        "mma.sync.aligned.m16n8k16.row.col.f32.f16.f16.f32 "
        "{%0,%1,%2,%3}, {%4,%5,%6,%7}, {%8,%9}, {%0,%1,%2,%3};"
        : "+f"(d[0]), "+f"(d[1]), "+f"(d[2]), "+f"(d[3])
        : "r"(a.x), "r"(a.y), "r"(a.z), "r"(a.w), "r"(b.x), "r"(b.y));
}
__device__ __forceinline__ float ex2f(float x) {
    float r; asm("ex2.approx.f32 %0, %1;" : "=f"(r) : "f"(x)); return r;
}
__device__ __forceinline__ uint32_t packh(float lo, float hi) {
    __half2 t = __floats2half2_rn(lo, hi);
    return *(uint32_t*)&t;
}

// ---------------------------------------------------------------------------
// RoPE cos/sin table
// ---------------------------------------------------------------------------
__global__ void rope_table_kernel() {
    int idx = blockIdx.x * blockDim.x + threadIdx.x;
    if (idx >= Sc * RHALF) return;
    int s = idx / RHALF;
    int i = idx % RHALF;
    double inv_freq = exp(-(double)(2 * i) / 64.0 * log(10000.0));
    double ang = (double)s * inv_freq;
    g_cos[idx] = (float)cos(ang);
    g_sin[idx] = (float)sin(ang);
}

// ---------------------------------------------------------------------------
// fp32 -> fp16 convert
// ---------------------------------------------------------------------------
__global__ void cvt_f16_kernel(const float* __restrict__ src,
                               __half* __restrict__ dst, int n4) {
    int i = blockIdx.x * blockDim.x + threadIdx.x;
    if (i >= n4) return;
    float4 v = ((const float4*)src)[i];
    __half2* dp = (__half2*)dst;
    dp[2 * i]     = __floats2half2_rn(v.x, v.y);
    dp[2 * i + 1] = __floats2half2_rn(v.z, v.w);
}

// ---------------------------------------------------------------------------
// Warp-mma fp16 GEMM: C = A16 @ B16^T + bias   (fp32 accumulators)
// 128x128 CTA tile, BK=32, 8 warps (64x32 each). K=1024 -> 32 chunks.
// Per stage: A | B tiles (128x32 fp16, 80B pitch). 40 KB smem, 2-stage.
// Proven-safe pipeline ordering: issue(k+1) before wait(k), trailing sync.
// ---------------------------------------------------------------------------
constexpr int GP_PITCH = 80;
constexpr int GP_TILE  = 128 * GP_PITCH;        // 10240
constexpr int GP_B     = GP_TILE;
constexpr int GP_STAGE = 2 * GP_TILE;           // 20480
constexpr int GP_SMEM  = 2 * GP_STAGE;          // 40960

__global__ __launch_bounds__(256, 2) void gemm_mma_f16(
    const __half* __restrict__ A16, const __half* __restrict__ B16,
    const float* __restrict__ bias, float* __restrict__ C, int Ndim)
{
    extern __shared__ char smg[];
    const uint32_t sb = smem_to_u32(smg);
    const int tid = threadIdx.x;
    const int lane = tid & 31;
    const int wid = tid >> 5;
    const int rowBase = blockIdx.y * 128;
    const int colBase = blockIdx.x * 128;
    const int wm = (wid >> 2) * 64;
    const int wn = (wid & 3) * 32;

    float acc[4][4][4];
#pragma unroll
    for (int mi = 0; mi < 4; mi++)
#pragma unroll
        for (int ni = 0; ni < 4; ni++)
#pragma unroll
            for (int e = 0; e < 4; e++) acc[mi][ni][e] = 0.f;

    auto issue = [&](int k) {
        const int k0 = k * 32;
        const uint32_t dst = sb + (uint32_t)(k & 1) * GP_STAGE;
#pragma unroll
        for (int u = 0; u < 2; u++) {
            int lin = u * 256 + tid;
            int r = lin >> 2, seg = lin & 3;
            uint32_t so = r * GP_PITCH + seg * 16;
            cp16(dst + so, A16 + (size_t)(rowBase + r) * GK + k0 + seg * 8);
            cp16(dst + GP_B + so, B16 + (size_t)(colBase + r) * GK + k0 + seg * 8);
        }
        cp_commit();
    };

    issue(0);
    for (int k = 0; k < 32; k++) {
        if (k + 1 < 32) {
            issue(k + 1);
            asm volatile("cp.async.wait_group 1;" ::: "memory");
        } else {
            asm volatile("cp.async.wait_group 0;" ::: "memory");
        }
        __syncthreads();

        const uint32_t St = sb + (uint32_t)(k & 1) * GP_STAGE;
#pragma unroll
        for (int ks = 0; ks < 2; ks++) {
            uint4 a[4];
            uint2 b[4];
            const uint32_t aro = (wm + (lane & 15)) * GP_PITCH
                               + (ks * 16 + (lane >> 4) * 8) * 2;
#pragma unroll
            for (int mi = 0; mi < 4; mi++)
                ldsm_x4(a[mi], St + aro + mi * 16 * GP_PITCH);
            const uint32_t bro = (wn + (lane & 7)) * GP_PITCH
                               + (ks * 16 + ((lane >> 3) & 1) * 8) * 2;
#pragma unroll
            for (int ni = 0; ni < 4; ni++)
                ldsm_x2(b[ni], St + GP_B + bro + ni * 8 * GP_PITCH);
#pragma unroll
            for (int mi = 0; mi < 4; mi++)
#pragma unroll
                for (int ni = 0; ni < 4; ni++)
                    mmah(acc[mi][ni], a[mi], b[ni]);
        }
        __syncthreads();
    }

#pragma unroll
    for (int mi = 0; mi < 4; mi++) {
#pragma unroll
        for (int ni = 0; ni < 4; ni++) {
            int r0 = rowBase + wm + mi * 16 + (lane >> 2);
            int col = colBase + wn + ni * 8 + (lane & 3) * 2;
            float b0 = bias[col], b1 = bias[col + 1];
            float2 v0 = make_float2(acc[mi][ni][0] + b0, acc[mi][ni][1] + b1);
            float2 v1 = make_float2(acc[mi][ni][2] + b0, acc[mi][ni][3] + b1);
            *(float2*)&C[(size_t)r0 * Ndim + col] = v0;
            *(float2*)&C[(size_t)(r0 + 8) * Ndim + col] = v1;
        }
    }
}

// ---------------------------------------------------------------------------
// Split QKV -> [B,H,S,HD], RoPE on Q/K; emit fp16 q/k/v.
// ---------------------------------------------------------------------------
__global__ void split_rope_kernel() {
    int idx = blockIdx.x * blockDim.x + threadIdx.x;
    int i = idx & 31;
    int h = (idx >> 5) & 15;
    int s = (idx >> 9) & (Sc - 1);
    int b = idx >> 20;

    int row = b * Sc + s;
    const float* src = g_qkv + (size_t)row * NQKV + h * HDc + 2 * i;
    float q0 = src[0],        q1 = src[1];
    float k0 = src[Ec],       k1 = src[Ec + 1];
    float v0 = src[2 * Ec],   v1 = src[2 * Ec + 1];

    float c  = g_cos[s * RHALF + i];
    float sn = g_sin[s * RHALF + i];

    float qa = q0 * c - q1 * sn, qb = q1 * c + q0 * sn;
    float ka = k0 * c - k1 * sn, kb = k1 * c + k0 * sn;

    size_t dst = (((size_t)(b * Hc + h)) * Sc + s) * HDc + 2 * i;
    *(__half2*)&g_q16[dst] = __floats2half2_rn(qa, qb);
    *(__half2*)&g_k16[dst] = __floats2half2_rn(ka, kb);
    *(__half2*)&g_v16[dst] = __floats2half2_rn(v0, v1);
}

// ---------------------------------------------------------------------------
// Tensor-core flash attention, plain fp16 operands, fp32 accum/softmax.
// 128 q-rows/CTA, 64-key tiles, 8 warps, HD=64. ~55 KB smem.
// ---------------------------------------------------------------------------
constexpr int AT_PITCH = 144;
constexpr int AT_Q   = 0;
constexpr int AT_KV  = 128 * AT_PITCH;            // 18432
constexpr int AT_V   = 64 * AT_PITCH;             // offset within buffer
constexpr int AT_KVBUF = 2 * 64 * AT_PITCH;       // 18432 per buffer
constexpr int AT_MSK = AT_KV + 2 * AT_KVBUF;      // 55296
constexpr int AT_SMEM = AT_MSK + 2 * 64 * 4;      // 55808

__global__ __launch_bounds__(256) void attn_mma_kernel(const int* __restrict__ mask)
{
    extern __shared__ char smA[];
    const uint32_t sb = smem_to_u32(smA);
    float* smask = (float*)(smA + AT_MSK);

    const int tid = threadIdx.x;
    const int lane = tid & 31;
    const int wid = tid >> 5;
    const int bh = blockIdx.y;
    const int b = bh >> 4, h = bh & 15;
    const int q0 = blockIdx.x * 128;

    const size_t base = (size_t)bh * Sc * HDc;
    const __half* Qg = g_q16 + base + (size_t)q0 * HDc;
    const __half* Kg = g_k16 + base;
    const __half* Vg = g_v16 + base;
    const int* mg = mask + b * Sc;

    // Q tile -> smem
#pragma unroll
    for (int u = 0; u < 4; u++) {
        int lin = u * 256 + tid;
        int r = lin >> 3, seg = lin & 7;
        cp16(sb + AT_Q + r * AT_PITCH + seg * 16, Qg + (size_t)r * HDc + seg * 8);
    }

    auto issueKV = [&](int it) {
        const uint32_t dst = sb + AT_KV + (uint32_t)(it & 1) * AT_KVBUF;
        const size_t koff = (size_t)it * 64 * HDc;
#pragma unroll
        for (int u = 0; u < 2; u++) {
            int lin = u * 256 + tid;
            int r = lin >> 3, seg = lin & 7;
            size_t off = koff + (size_t)r * HDc + seg * 8;
            uint32_t so = r * AT_PITCH + seg * 16;
            cp16(dst + so, Kg + off);
            cp16(dst + AT_V + so, Vg + off);
        }
        if (tid < 64) smask[(it & 1) * 64 + tid] = mg[it * 64 + tid] ? 0.f : -1e30f;
        cp_commit();
    };

    issueKV(0);
    issueKV(1);
    asm volatile("cp.async.wait_group 1;" ::: "memory");
    __syncthreads();

    // Q fragments held in registers
    uint4 qf[4];
#pragma unroll
    for (int ks = 0; ks < 4; ks++) {
        uint32_t ro = (wid * 16 + (lane & 15)) * AT_PITCH + (ks * 16 + (lane >> 4) * 8) * 2;
        ldsm_x4(qf[ks], sb + AT_Q + ro);
    }

    float accO[8][4];
#pragma unroll
    for (int nd = 0; nd < 8; nd++)
#pragma unroll
        for (int e = 0; e < 4; e++) accO[nd][e] = 0.f;
    float m0 = -1e30f, m1 = -1e30f, l0 = 0.f, l1 = 0.f;
    const float scale = 0.125f;
    const float LOG2E = 1.4426950408889634f;

    for (int it = 0; it < 32; it++) {
        if (it > 0) {
            if (it == 31) asm volatile("cp.async.wait_group 0;" ::: "memory");
            else          asm volatile("cp.async.wait_group 1;" ::: "memory");
            __syncthreads();
        }
        const uint32_t Kb = sb + AT_KV + (uint32_t)(it & 1) * AT_KVBUF;
        const int mbuf = (it & 1) * 64;

        // ---- S = Q K^T ----
        float s[8][4];
#pragma unroll
        for (int ni = 0; ni < 8; ni++)
#pragma unroll
            for (int e = 0; e < 4; e++) s[ni][e] = 0.f;
#pragma unroll
        for (int ks = 0; ks < 4; ks++) {
            uint2 bk[8];
            uint32_t co = (ks * 16 + ((lane >> 3) & 1) * 8) * 2;
#pragma unroll
            for (int ni = 0; ni < 8; ni++)
                ldsm_x2(bk[ni], Kb + (ni * 8 + (lane & 7)) * AT_PITCH + co);
#pragma unroll
            for (int ni = 0; ni < 8; ni++)
                mmah(s[ni], qf[ks], bk[ni]);
        }

        // ---- scale + mask ----
#pragma unroll
        for (int ni = 0; ni < 8; ni++) {
            float b0 = smask[mbuf + ni * 8 + (lane & 3) * 2];
            float b1 = smask[mbuf + ni * 8 + (lane & 3) * 2 + 1];
            s[ni][0] = s[ni][0] * scale + b0;
            s[ni][1] = s[ni][1] * scale + b1;
            s[ni][2] = s[ni][2] * scale + b0;
            s[ni][3] = s[ni][3] * scale + b1;
        }

        // ---- online softmax (rows lane>>2 and +8) ----
        float mx0 = -1e30f, mx1 = -1e30f;
#pragma unroll
        for (int ni = 0; ni < 8; ni++) {
            mx0 = fmaxf(mx0, fmaxf(s[ni][0], s[ni][1]));
            mx1 = fmaxf(mx1, fmaxf(s[ni][2], s[ni][3]));
        }
        mx0 = fmaxf(mx0, __shfl_xor_sync(0xffffffffu, mx0, 1));
        mx0 = fmaxf(mx0, __shfl_xor_sync(0xffffffffu, mx0, 2));
        mx1 = fmaxf(mx1, __shfl_xor_sync(0xffffffffu, mx1, 1));
        mx1 = fmaxf(mx1, __shfl_xor_sync(0xffffffffu, mx1, 2));
        float mn0 = fmaxf(m0, mx0), mn1 = fmaxf(m1, mx1);
        float al0 = ex2f((m0 - mn0) * LOG2E);
        float al1 = ex2f((m1 - mn1) * LOG2E);
        float sum0 = 0.f, sum1 = 0.f;
#pragma unroll
        for (int ni = 0; ni < 8; ni++) {
            s[ni][0] = ex2f((s[ni][0] - mn0) * LOG2E);
            s[ni][1] = ex2f((s[ni][1] - mn0) * LOG2E);
            s[ni][2] = ex2f((s[ni][2] - mn1) * LOG2E);
            s[ni][3] = ex2f((s[ni][3] - mn1) * LOG2E);
            sum0 += s[ni][0] + s[ni][1];
            sum1 += s[ni][2] + s[ni][3];
        }
        sum0 += __shfl_xor_sync(0xffffffffu, sum0, 1);
        sum0 += __shfl_xor_sync(0xffffffffu, sum0, 2);
        sum1 += __shfl_xor_sync(0xffffffffu, sum1, 1);
        sum1 += __shfl_xor_sync(0xffffffffu, sum1, 2);
        l0 = l0 * al0 + sum0;
        l1 = l1 * al1 + sum1;
        m0 = mn0; m1 = mn1;
#pragma unroll
        for (int nd = 0; nd < 8; nd++) {
            accO[nd][0] *= al0; accO[nd][1] *= al0;
            accO[nd][2] *= al1; accO[nd][3] *= al1;
        }

        // ---- P fragments (fp16) from S accumulators (register identity) ----
        uint4 ap[4];
#pragma unroll
        for (int ks2 = 0; ks2 < 4; ks2++) {
            const float* p0 = s[2 * ks2];
            const float* p1 = s[2 * ks2 + 1];
            ap[ks2].x = packh(p0[0], p0[1]);
            ap[ks2].y = packh(p0[2], p0[3]);
            ap[ks2].z = packh(p1[0], p1[1]);
            ap[ks2].w = packh(p1[2], p1[3]);
        }

        // ---- O += P V, V^T via ldmatrix.trans ----
#pragma unroll
        for (int ks2 = 0; ks2 < 4; ks2++) {
            uint2 bv[8];
            uint32_t rbase = (ks2 * 16 + (lane & 15)) * AT_PITCH;
#pragma unroll
            for (int nd = 0; nd < 8; nd++)
                ldsm_x2t(bv[nd], Kb + AT_V + rbase + nd * 16);
#pragma unroll
            for (int nd = 0; nd < 8; nd++)
                mmah(accO[nd], ap[ks2], bv[nd]);
        }

        __syncthreads();
        if (it + 2 < 32) issueKV(it + 2);
    }

    // ---- epilogue: normalize, write ctx fp16 ----
    float inv0 = 1.f / l0, inv1 = 1.f / l1;
    int r0 = q0 + wid * 16 + (lane >> 2);
    int colb = h * HDc + (lane & 3) * 2;
#pragma unroll
    for (int nd = 0; nd < 8; nd++) {
        float c00 = accO[nd][0] * inv0, c01 = accO[nd][1] * inv0;
        float c10 = accO[nd][2] * inv1, c11 = accO[nd][3] * inv1;
        size_t i0 = (size_t)(b * Sc + r0) * Ec + colb + nd * 8;
        size_t i1 = (size_t)(b * Sc + r0 + 8) * Ec + colb + nd * 8;
        *(__half2*)&g_ctx16[i0] = __floats2half2_rn(c00, c01);
        *(__half2*)&g_ctx16[i1] = __floats2half2_rn(c10, c11);
    }
}

// ---------------------------------------------------------------------------
extern "C" void kernel_launch(void* const* d_in, const int* in_sizes, int n_in,
                              void* d_out, int out_size)
{
    const float* x     = (const float*)d_in[0];
    const int*   mask  = (const int*)d_in[1];
    const float* qkv_w = (const float*)d_in[2];
    const float* qkv_b = (const float*)d_in[3];
    const float* out_w = (const float*)d_in[4];
    const float* out_b = (const float*)d_in[5];
    float* out = (float*)d_out;

    float* qkv_ptr = nullptr;
    cudaGetSymbolAddress((void**)&qkv_ptr, g_qkv);
    __half *x16, *w16, *ow16, *c16;
    cudaGetSymbolAddress((void**)&x16,  g_x16);
    cudaGetSymbolAddress((void**)&w16,  g_wqkv);
    cudaGetSymbolAddress((void**)&ow16, g_wout);
    cudaGetSymbolAddress((void**)&c16,  g_ctx16);

    cudaFuncSetAttribute(gemm_mma_f16,
                         cudaFuncAttributeMaxDynamicSharedMemorySize, GP_SMEM);
    cudaFuncSetAttribute(attn_mma_kernel,
                         cudaFuncAttributeMaxDynamicSharedMemorySize, AT_SMEM);

    // 1. RoPE tables
    rope_table_kernel<<<(Sc * RHALF + 255) / 256, 256>>>();

    // 2. Convert inputs + weights to fp16
    cvt_f16_kernel<<<(Mc * Ec / 4 + 255) / 256, 256>>>(x, x16, Mc * Ec / 4);
    cvt_f16_kernel<<<(NQKV * Ec / 4 + 255) / 256, 256>>>(qkv_w, w16, NQKV * Ec / 4);
    cvt_f16_kernel<<<(Ec * Ec / 4 + 255) / 256, 256>>>(out_w, ow16, Ec * Ec / 4);

    // 3. QKV projection (fp16 warp-mma)
    gemm_mma_f16<<<dim3(NQKV / 128, Mc / 128), 256, GP_SMEM>>>(
        x16, w16, qkv_b, qkv_ptr, NQKV);

    // 4. Split + RoPE -> fp16 q/k/v
    split_rope_kernel<<<(Bc * Sc * Hc * RHALF) / 256, 256>>>();

    // 5. Tensor-core flash attention -> ctx fp16
    attn_mma_kernel<<<dim3(Sc / 128, Bc * Hc), 256, AT_SMEM>>>(mask);

    // 6. Output projection (fp16 warp-mma)
    gemm_mma_f16<<<dim3(Ec / 128, Mc / 128), 256, GP_SMEM>>>(
        c16, ow16, out_b, out, Ec);
}

// round 10
// speedup vs baseline: 7.0928x; 1.0850x over previous
#include <cuda_runtime.h>
#include <cuda_fp16.h>
#include <cstdint>
#include <cmath>

// Problem constants
constexpr int Bc  = 2;
constexpr int Sc  = 2048;
constexpr int Ec  = 1024;
constexpr int Hc  = 16;
constexpr int HDc = 64;
constexpr int Mc  = Bc * Sc;        // 4096 rows
constexpr int NQKV = 3 * Ec;        // 3072
constexpr int RHALF = 32;           // rotary pairs per head (ROT=64)
constexpr int GK = 1024;            // K dim of both projection GEMMs

// Scratch (static device globals; no allocation)
__device__ float g_cos[Sc * RHALF];
__device__ float g_sin[Sc * RHALF];

// fp16 buffers
__device__ __half g_x16[(size_t)Mc * Ec];
__device__ __half g_wqkv[(size_t)NQKV * Ec];
__device__ __half g_wout[(size_t)Ec * Ec];
__device__ __half g_ctx16[(size_t)Mc * Ec];

// q/k/v fp16 in [B,H,S,HD] layout (written directly by the QKV GEMM epilogue)
constexpr size_t QKV_ELEMS = (size_t)Bc * Hc * Sc * HDc;
__device__ __half g_q16[QKV_ELEMS];
__device__ __half g_k16[QKV_ELEMS];
__device__ __half g_v16[QKV_ELEMS];

// ---------------------------------------------------------------------------
// Portable (compute_103-safe) tensor-core helpers
// ---------------------------------------------------------------------------
__device__ __forceinline__ uint32_t smem_to_u32(const void* p) {
    uint32_t a;
    asm("{ .reg .u64 t; cvta.to.shared.u64 t, %1; cvt.u32.u64 %0, t; }"
        : "=r"(a) : "l"(p));
    return a;
}
__device__ __forceinline__ void cp16(uint32_t dst, const void* src) {
    asm volatile("cp.async.cg.shared.global [%0], [%1], 16;"
                 :: "r"(dst), "l"(src));
}
__device__ __forceinline__ void cp_commit() {
    asm volatile("cp.async.commit_group;" ::: "memory");
}
__device__ __forceinline__ void ldsm_x4(uint4& r, uint32_t addr) {
    asm volatile("ldmatrix.sync.aligned.m8n8.x4.shared.b16 {%0,%1,%2,%3}, [%4];"
                 : "=r"(r.x), "=r"(r.y), "=r"(r.z), "=r"(r.w) : "r"(addr));
}
__device__ __forceinline__ void ldsm_x2(uint2& r, uint32_t addr) {
    asm volatile("ldmatrix.sync.aligned.m8n8.x2.shared.b16 {%0,%1}, [%2];"
                 : "=r"(r.x), "=r"(r.y) : "r"(addr));
}
__device__ __forceinline__ void ldsm_x2t(uint2& r, uint32_t addr) {
    asm volatile("ldmatrix.sync.aligned.m8n8.x2.trans.shared.b16 {%0,%1}, [%2];"
                 : "=r"(r.x), "=r"(r.y) : "r"(addr));
}
__device__ __forceinline__ void mmah(float* d, const uint4& a, const uint2& b) {
    asm volatile(
        "mma.sync.aligned.m16n8k16.row.col.f32.f16.f16.f32 "
        "{%0,%1,%2,%3}, {%4,%5,%6,%7}, {%8,%9}, {%0,%1,%2,%3};"
        : "+f"(d[0]), "+f"(d[1]), "+f"(d[2]), "+f"(d[3])
        : "r"(a.x), "r"(a.y), "r"(a.z), "r"(a.w), "r"(b.x), "r"(b.y));
}
__device__ __forceinline__ float ex2f(float x) {
    float r; asm("ex2.approx.f32 %0, %1;" : "=f"(r) : "f"(x)); return r;
}
__device__ __forceinline__ uint32_t packh(float lo, float hi) {
    __half2 t = __floats2half2_rn(lo, hi);
    return *(uint32_t*)&t;
}

// ---------------------------------------------------------------------------
// Prep: fp32->fp16 converts for x / qkv_w / out_w + RoPE table, one launch.
// ---------------------------------------------------------------------------
constexpr int PN1 = Mc * Ec / 4;        // 262144
constexpr int PN2 = NQKV * Ec / 4;      // 786432
constexpr int PN3 = Ec * Ec / 4;        // 262144
constexpr int PTOT = PN1 + PN2 + PN3;   // 1310720

__global__ void prep_kernel(const float* __restrict__ x,
                            const float* __restrict__ qkv_w,
                            const float* __restrict__ out_w) {
    int idx = blockIdx.x * blockDim.x + threadIdx.x;

    if (idx < Sc * RHALF) {
        int s = idx / RHALF;
        int i = idx % RHALF;
        double inv_freq = exp(-(double)(2 * i) / 64.0 * log(10000.0));
        double ang = (double)s * inv_freq;
        g_cos[idx] = (float)cos(ang);
        g_sin[idx] = (float)sin(ang);
    }
    if (idx >= PTOT) return;

    const float* src;
    __half2* dp;
    int i4;
    if (idx < PN1)            { src = x;     dp = (__half2*)g_x16;  i4 = idx; }
    else if (idx < PN1 + PN2) { src = qkv_w; dp = (__half2*)g_wqkv; i4 = idx - PN1; }
    else                      { src = out_w; dp = (__half2*)g_wout; i4 = idx - PN1 - PN2; }

    float4 v = ((const float4*)src)[i4];
    dp[2 * i4]     = __floats2half2_rn(v.x, v.y);
    dp[2 * i4 + 1] = __floats2half2_rn(v.z, v.w);
}

// ---------------------------------------------------------------------------
// Warp-mma fp16 GEMM: 128x128 CTA tile, BK=64, 3-stage cp.async, 2 CTAs/SM.
// 8 warps (64x32 each). K=1024 -> 16 chunks. Stage = A|B (128x64 fp16,
// 144B pitch) = 36.9 KB; 3 stages = 110.6 KB.
// MODE 0: C fp32 = A@B^T + bias (out projection)
// MODE 1: QKV epilogue — bias + RoPE, write q/k/v fp16 in [B,H,S,HD].
// ---------------------------------------------------------------------------
constexpr int GQ_PITCH = 144;
constexpr int GQ_TILE  = 128 * GQ_PITCH;        // 18432
constexpr int GQ_B     = GQ_TILE;
constexpr int GQ_STAGE = 2 * GQ_TILE;           // 36864
constexpr int GQ_SMEM  = 3 * GQ_STAGE;          // 110592

template <int MODE>
__global__ __launch_bounds__(256, 2) void gemm_mma_f16(
    const __half* __restrict__ A16, const __half* __restrict__ B16,
    const float* __restrict__ bias, float* __restrict__ C, int Ndim)
{
    extern __shared__ char smg[];
    const uint32_t sb = smem_to_u32(smg);
    const int tid = threadIdx.x;
    const int lane = tid & 31;
    const int wid = tid >> 5;
    const int rowBase = blockIdx.y * 128;
    const int colBase = blockIdx.x * 128;
    const int wm = (wid >> 2) * 64;
    const int wn = (wid & 3) * 32;

    float acc[4][4][4];
#pragma unroll
    for (int mi = 0; mi < 4; mi++)
#pragma unroll
        for (int ni = 0; ni < 4; ni++)
#pragma unroll
            for (int e = 0; e < 4; e++) acc[mi][ni][e] = 0.f;

    // load chunk k (A/B 128x64 fp16 tiles) into stage k%3
    auto issue = [&](int k) {
        const int k0 = k * 64;
        const uint32_t dst = sb + (uint32_t)(k % 3) * GQ_STAGE;
#pragma unroll
        for (int u = 0; u < 4; u++) {
            int lin = u * 256 + tid;
            int r = lin >> 3, seg = lin & 7;
            uint32_t so = r * GQ_PITCH + seg * 16;
            cp16(dst + so, A16 + (size_t)(rowBase + r) * GK + k0 + seg * 8);
            cp16(dst + GQ_B + so, B16 + (size_t)(colBase + r) * GK + k0 + seg * 8);
        }
        cp_commit();
    };

    issue(0);
    issue(1);
    for (int k = 0; k < 16; k++) {
        if (k < 15) asm volatile("cp.async.wait_group 1;" ::: "memory");
        else        asm volatile("cp.async.wait_group 0;" ::: "memory");
        __syncthreads();            // all threads past compute(k-1)
        if (k + 2 < 16) issue(k + 2);   // writes stage (k+2)%3 (held chunk k-1)

        const uint32_t St = sb + (uint32_t)(k % 3) * GQ_STAGE;
#pragma unroll
        for (int ks = 0; ks < 4; ks++) {
            uint4 a[4];
            uint2 b[4];
            const uint32_t aro = (wm + (lane & 15)) * GQ_PITCH
                               + (ks * 16 + (lane >> 4) * 8) * 2;
#pragma unroll
            for (int mi = 0; mi < 4; mi++)
                ldsm_x4(a[mi], St + aro + mi * 16 * GQ_PITCH);
            const uint32_t bro = (wn + (lane & 7)) * GQ_PITCH
                               + (ks * 16 + ((lane >> 3) & 1) * 8) * 2;
#pragma unroll
            for (int ni = 0; ni < 4; ni++)
                ldsm_x2(b[ni], St + GQ_B + bro + ni * 8 * GQ_PITCH);
#pragma unroll
            for (int mi = 0; mi < 4; mi++)
#pragma unroll
                for (int ni = 0; ni < 4; ni++)
                    mmah(acc[mi][ni], a[mi], b[ni]);
        }
    }

#pragma unroll
    for (int mi = 0; mi < 4; mi++) {
#pragma unroll
        for (int ni = 0; ni < 4; ni++) {
            int r0 = rowBase + wm + mi * 16 + (lane >> 2);
            int col = colBase + wn + ni * 8 + (lane & 3) * 2;
            float b0 = bias[col], b1 = bias[col + 1];
            float v00 = acc[mi][ni][0] + b0, v01 = acc[mi][ni][1] + b1;   // row r0
            float v10 = acc[mi][ni][2] + b0, v11 = acc[mi][ni][3] + b1;   // row r0+8

            if (MODE == 0) {
                *(float2*)&C[(size_t)r0 * Ndim + col] = make_float2(v00, v01);
                *(float2*)&C[(size_t)(r0 + 8) * Ndim + col] = make_float2(v10, v11);
            } else {
                // QKV epilogue: col in [0,3072) = [q|k|v], apply RoPE to q/k.
                int seg = col >> 10;             // 0=q 1=k 2=v
                int h = (col >> 6) & 15;
                int d = col & 63;
                int i = d >> 1;
                __half* dstBuf = (seg == 0) ? g_q16 : (seg == 1) ? g_k16 : g_v16;
#pragma unroll
                for (int rr = 0; rr < 2; rr++) {
                    int r = r0 + rr * 8;
                    float va = rr ? v10 : v00;
                    float vb = rr ? v11 : v01;
                    int bb = r >> 11;
                    int s = r & 2047;
                    size_t dst = (((size_t)(bb * Hc + h)) * Sc + s) * HDc + d;
                    if (seg == 2) {
                        *(__half2*)&dstBuf[dst] = __floats2half2_rn(va, vb);
                    } else {
                        float c  = g_cos[s * RHALF + i];
                        float sn = g_sin[s * RHALF + i];
                        *(__half2*)&dstBuf[dst] =
                            __floats2half2_rn(va * c - vb * sn, vb * c + va * sn);
                    }
                }
            }
        }
    }
}

// ---------------------------------------------------------------------------
// Tensor-core flash attention, plain fp16 operands, fp32 accum/softmax.
// 128 q-rows/CTA, 64-key tiles, 8 warps, HD=64. ~55 KB smem. (round-9 proven)
// ---------------------------------------------------------------------------
constexpr int AT_PITCH = 144;
constexpr int AT_Q   = 0;
constexpr int AT_KV  = 128 * AT_PITCH;            // 18432
constexpr int AT_V   = 64 * AT_PITCH;             // offset within buffer
constexpr int AT_KVBUF = 2 * 64 * AT_PITCH;       // 18432 per buffer
constexpr int AT_MSK = AT_KV + 2 * AT_KVBUF;      // 55296
constexpr int AT_SMEM = AT_MSK + 2 * 64 * 4;      // 55808

__global__ __launch_bounds__(256) void attn_mma_kernel(const int* __restrict__ mask)
{
    extern __shared__ char smA[];
    const uint32_t sb = smem_to_u32(smA);
    float* smask = (float*)(smA + AT_MSK);

    const int tid = threadIdx.x;
    const int lane = tid & 31;
    const int wid = tid >> 5;
    const int bh = blockIdx.y;
    const int b = bh >> 4, h = bh & 15;
    const int q0 = blockIdx.x * 128;

    const size_t base = (size_t)bh * Sc * HDc;
    const __half* Qg = g_q16 + base + (size_t)q0 * HDc;
    const __half* Kg = g_k16 + base;
    const __half* Vg = g_v16 + base;
    const int* mg = mask + b * Sc;

#pragma unroll
    for (int u = 0; u < 4; u++) {
        int lin = u * 256 + tid;
        int r = lin >> 3, seg = lin & 7;
        cp16(sb + AT_Q + r * AT_PITCH + seg * 16, Qg + (size_t)r * HDc + seg * 8);
    }

    auto issueKV = [&](int it) {
        const uint32_t dst = sb + AT_KV + (uint32_t)(it & 1) * AT_KVBUF;
        const size_t koff = (size_t)it * 64 * HDc;
#pragma unroll
        for (int u = 0; u < 2; u++) {
            int lin = u * 256 + tid;
            int r = lin >> 3, seg = lin & 7;
            size_t off = koff + (size_t)r * HDc + seg * 8;
            uint32_t so = r * AT_PITCH + seg * 16;
            cp16(dst + so, Kg + off);
            cp16(dst + AT_V + so, Vg + off);
        }
        if (tid < 64) smask[(it & 1) * 64 + tid] = mg[it * 64 + tid] ? 0.f : -1e30f;
        cp_commit();
    };

    issueKV(0);
    issueKV(1);
    asm volatile("cp.async.wait_group 1;" ::: "memory");
    __syncthreads();

    uint4 qf[4];
#pragma unroll
    for (int ks = 0; ks < 4; ks++) {
        uint32_t ro = (wid * 16 + (lane & 15)) * AT_PITCH + (ks * 16 + (lane >> 4) * 8) * 2;
        ldsm_x4(qf[ks], sb + AT_Q + ro);
    }

    float accO[8][4];
#pragma unroll
    for (int nd = 0; nd < 8; nd++)
#pragma unroll
        for (int e = 0; e < 4; e++) accO[nd][e] = 0.f;
    float m0 = -1e30f, m1 = -1e30f, l0 = 0.f, l1 = 0.f;
    const float scale = 0.125f;
    const float LOG2E = 1.4426950408889634f;

    for (int it = 0; it < 32; it++) {
        if (it > 0) {
            if (it == 31) asm volatile("cp.async.wait_group 0;" ::: "memory");
            else          asm volatile("cp.async.wait_group 1;" ::: "memory");
            __syncthreads();
        }
        const uint32_t Kb = sb + AT_KV + (uint32_t)(it & 1) * AT_KVBUF;
        const int mbuf = (it & 1) * 64;

        float s[8][4];
#pragma unroll
        for (int ni = 0; ni < 8; ni++)
#pragma unroll
            for (int e = 0; e < 4; e++) s[ni][e] = 0.f;
#pragma unroll
        for (int ks = 0; ks < 4; ks++) {
            uint2 bk[8];
            uint32_t co = (ks * 16 + ((lane >> 3) & 1) * 8) * 2;
#pragma unroll
            for (int ni = 0; ni < 8; ni++)
                ldsm_x2(bk[ni], Kb + (ni * 8 + (lane & 7)) * AT_PITCH + co);
#pragma unroll
            for (int ni = 0; ni < 8; ni++)
                mmah(s[ni], qf[ks], bk[ni]);
        }

#pragma unroll
        for (int ni = 0; ni < 8; ni++) {
            float b0 = smask[mbuf + ni * 8 + (lane & 3) * 2];
            float b1 = smask[mbuf + ni * 8 + (lane & 3) * 2 + 1];
            s[ni][0] = s[ni][0] * scale + b0;
            s[ni][1] = s[ni][1] * scale + b1;
            s[ni][2] = s[ni][2] * scale + b0;
            s[ni][3] = s[ni][3] * scale + b1;
        }

        float mx0 = -1e30f, mx1 = -1e30f;
#pragma unroll
        for (int ni = 0; ni < 8; ni++) {
            mx0 = fmaxf(mx0, fmaxf(s[ni][0], s[ni][1]));
            mx1 = fmaxf(mx1, fmaxf(s[ni][2], s[ni][3]));
        }
        mx0 = fmaxf(mx0, __shfl_xor_sync(0xffffffffu, mx0, 1));
        mx0 = fmaxf(mx0, __shfl_xor_sync(0xffffffffu, mx0, 2));
        mx1 = fmaxf(mx1, __shfl_xor_sync(0xffffffffu, mx1, 1));
        mx1 = fmaxf(mx1, __shfl_xor_sync(0xffffffffu, mx1, 2));
        float mn0 = fmaxf(m0, mx0), mn1 = fmaxf(m1, mx1);
        float al0 = ex2f((m0 - mn0) * LOG2E);
        float al1 = ex2f((m1 - mn1) * LOG2E);
        float sum0 = 0.f, sum1 = 0.f;
#pragma unroll
        for (int ni = 0; ni < 8; ni++) {
            s[ni][0] = ex2f((s[ni][0] - mn0) * LOG2E);
            s[ni][1] = ex2f((s[ni][1] - mn0) * LOG2E);
            s[ni][2] = ex2f((s[ni][2] - mn1) * LOG2E);
            s[ni][3] = ex2f((s[ni][3] - mn1) * LOG2E);
            sum0 += s[ni][0] + s[ni][1];
            sum1 += s[ni][2] + s[ni][3];
        }
        sum0 += __shfl_xor_sync(0xffffffffu, sum0, 1);
        sum0 += __shfl_xor_sync(0xffffffffu, sum0, 2);
        sum1 += __shfl_xor_sync(0xffffffffu, sum1, 1);
        sum1 += __shfl_xor_sync(0xffffffffu, sum1, 2);
        l0 = l0 * al0 + sum0;
        l1 = l1 * al1 + sum1;
        m0 = mn0; m1 = mn1;
#pragma unroll
        for (int nd = 0; nd < 8; nd++) {
            accO[nd][0] *= al0; accO[nd][1] *= al0;
            accO[nd][2] *= al1; accO[nd][3] *= al1;
        }

        uint4 ap[4];
#pragma unroll
        for (int ks2 = 0; ks2 < 4; ks2++) {
            const float* p0 = s[2 * ks2];
            const float* p1 = s[2 * ks2 + 1];
            ap[ks2].x = packh(p0[0], p0[1]);
            ap[ks2].y = packh(p0[2], p0[3]);
            ap[ks2].z = packh(p1[0], p1[1]);
            ap[ks2].w = packh(p1[2], p1[3]);
        }

#pragma unroll
        for (int ks2 = 0; ks2 < 4; ks2++) {
            uint2 bv[8];
            uint32_t rbase = (ks2 * 16 + (lane & 15)) * AT_PITCH;
#pragma unroll
            for (int nd = 0; nd < 8; nd++)
                ldsm_x2t(bv[nd], Kb + AT_V + rbase + nd * 16);
#pragma unroll
            for (int nd = 0; nd < 8; nd++)
                mmah(accO[nd], ap[ks2], bv[nd]);
        }

        __syncthreads();
        if (it + 2 < 32) issueKV(it + 2);
    }

    float inv0 = 1.f / l0, inv1 = 1.f / l1;
    int r0 = q0 + wid * 16 + (lane >> 2);
    int colb = h * HDc + (lane & 3) * 2;
#pragma unroll
    for (int nd = 0; nd < 8; nd++) {
        float c00 = accO[nd][0] * inv0, c01 = accO[nd][1] * inv0;
        float c10 = accO[nd][2] * inv1, c11 = accO[nd][3] * inv1;
        size_t i0 = (size_t)(b * Sc + r0) * Ec + colb + nd * 8;
        size_t i1 = (size_t)(b * Sc + r0 + 8) * Ec + colb + nd * 8;
        *(__half2*)&g_ctx16[i0] = __floats2half2_rn(c00, c01);
        *(__half2*)&g_ctx16[i1] = __floats2half2_rn(c10, c11);
    }
}

// ---------------------------------------------------------------------------
extern "C" void kernel_launch(void* const* d_in, const int* in_sizes, int n_in,
                              void* d_out, int out_size)
{
    const float* x     = (const float*)d_in[0];
    const int*   mask  = (const int*)d_in[1];
    const float* qkv_w = (const float*)d_in[2];
    const float* qkv_b = (const float*)d_in[3];
    const float* out_w = (const float*)d_in[4];
    const float* out_b = (const float*)d_in[5];
    float* out = (float*)d_out;

    __half *x16, *w16, *ow16, *c16;
    cudaGetSymbolAddress((void**)&x16,  g_x16);
    cudaGetSymbolAddress((void**)&w16,  g_wqkv);
    cudaGetSymbolAddress((void**)&ow16, g_wout);
    cudaGetSymbolAddress((void**)&c16,  g_ctx16);

    cudaFuncSetAttribute(gemm_mma_f16<0>,
                         cudaFuncAttributeMaxDynamicSharedMemorySize, GQ_SMEM);
    cudaFuncSetAttribute(gemm_mma_f16<1>,
                         cudaFuncAttributeMaxDynamicSharedMemorySize, GQ_SMEM);
    cudaFuncSetAttribute(attn_mma_kernel,
                         cudaFuncAttributeMaxDynamicSharedMemorySize, AT_SMEM);

    // 1. Converts + RoPE table (one launch)
    prep_kernel<<<(PTOT + 255) / 256, 256>>>(x, qkv_w, out_w);

    // 2. QKV projection with fused bias+RoPE epilogue -> q/k/v fp16 [B,H,S,HD]
    gemm_mma_f16<1><<<dim3(NQKV / 128, Mc / 128), 256, GQ_SMEM>>>(
        x16, w16, qkv_b, nullptr, NQKV);

    // 3. Tensor-core flash attention -> ctx fp16
    attn_mma_kernel<<<dim3(Sc / 128, Bc * Hc), 256, AT_SMEM>>>(mask);

    // 4. Output projection -> fp32 out
    gemm_mma_f16<0><<<dim3(Ec / 128, Mc / 128), 256, GQ_SMEM>>>(
        c16, ow16, out_b, out, Ec);
}

// round 11
// speedup vs baseline: 7.4201x; 1.0461x over previous
#include <cuda_runtime.h>
#include <cuda_fp16.h>
#include <cstdint>
#include <cmath>

// Problem constants
constexpr int Bc  = 2;
constexpr int Sc  = 2048;
constexpr int Ec  = 1024;
constexpr int Hc  = 16;
constexpr int HDc = 64;
constexpr int Mc  = Bc * Sc;        // 4096 rows
constexpr int NQKV = 3 * Ec;        // 3072
constexpr int RHALF = 32;           // rotary pairs per head (ROT=64)
constexpr int GK = 1024;            // K dim of both projection GEMMs

// Scratch (static device globals; no allocation)
__device__ float g_cos[Sc * RHALF];
__device__ float g_sin[Sc * RHALF];

// fp16 buffers
__device__ __half g_x16[(size_t)Mc * Ec];
__device__ __half g_wqkv[(size_t)NQKV * Ec];
__device__ __half g_wout[(size_t)Ec * Ec];
__device__ __half g_ctx16[(size_t)Mc * Ec];

// q/k/v fp16 in [B,H,S,HD] layout (written directly by the QKV GEMM epilogue)
constexpr size_t QKV_ELEMS = (size_t)Bc * Hc * Sc * HDc;
__device__ __half g_q16[QKV_ELEMS];
__device__ __half g_k16[QKV_ELEMS];
__device__ __half g_v16[QKV_ELEMS];

// ---------------------------------------------------------------------------
// Portable (compute_103-safe) tensor-core helpers
// ---------------------------------------------------------------------------
__device__ __forceinline__ uint32_t smem_to_u32(const void* p) {
    uint32_t a;
    asm("{ .reg .u64 t; cvta.to.shared.u64 t, %1; cvt.u32.u64 %0, t; }"
        : "=r"(a) : "l"(p));
    return a;
}
__device__ __forceinline__ void cp16(uint32_t dst, const void* src) {
    asm volatile("cp.async.cg.shared.global [%0], [%1], 16;"
                 :: "r"(dst), "l"(src));
}
__device__ __forceinline__ void cp_commit() {
    asm volatile("cp.async.commit_group;" ::: "memory");
}
__device__ __forceinline__ void ldsm_x4(uint4& r, uint32_t addr) {
    asm volatile("ldmatrix.sync.aligned.m8n8.x4.shared.b16 {%0,%1,%2,%3}, [%4];"
                 : "=r"(r.x), "=r"(r.y), "=r"(r.z), "=r"(r.w) : "r"(addr));
}
__device__ __forceinline__ void ldsm_x4t(uint4& r, uint32_t addr) {
    asm volatile("ldmatrix.sync.aligned.m8n8.x4.trans.shared.b16 {%0,%1,%2,%3}, [%4];"
                 : "=r"(r.x), "=r"(r.y), "=r"(r.z), "=r"(r.w) : "r"(addr));
}
__device__ __forceinline__ void mmah(float* d, const uint4& a, uint32_t b0, uint32_t b1) {
    asm volatile(
        "mma.sync.aligned.m16n8k16.row.col.f32.f16.f16.f32 "
        "{%0,%1,%2,%3}, {%4,%5,%6,%7}, {%8,%9}, {%0,%1,%2,%3};"
        : "+f"(d[0]), "+f"(d[1]), "+f"(d[2]), "+f"(d[3])
        : "r"(a.x), "r"(a.y), "r"(a.z), "r"(a.w), "r"(b0), "r"(b1));
}
__device__ __forceinline__ float ex2f(float x) {
    float r; asm("ex2.approx.f32 %0, %1;" : "=f"(r) : "f"(x)); return r;
}
__device__ __forceinline__ uint32_t packh(float lo, float hi) {
    __half2 t = __floats2half2_rn(lo, hi);
    return *(uint32_t*)&t;
}

// ---------------------------------------------------------------------------
// Prep: fp32->fp16 converts for x / qkv_w / out_w + RoPE table, one launch.
// ---------------------------------------------------------------------------
constexpr int PN1 = Mc * Ec / 4;        // 262144
constexpr int PN2 = NQKV * Ec / 4;      // 786432
constexpr int PN3 = Ec * Ec / 4;        // 262144
constexpr int PTOT = PN1 + PN2 + PN3;   // 1310720

__global__ void prep_kernel(const float* __restrict__ x,
                            const float* __restrict__ qkv_w,
                            const float* __restrict__ out_w) {
    int idx = blockIdx.x * blockDim.x + threadIdx.x;

    if (idx < Sc * RHALF) {
        int s = idx / RHALF;
        int i = idx % RHALF;
        double inv_freq = exp(-(double)(2 * i) / 64.0 * log(10000.0));
        double ang = (double)s * inv_freq;
        g_cos[idx] = (float)cos(ang);
        g_sin[idx] = (float)sin(ang);
    }
    if (idx >= PTOT) return;

    const float* src;
    __half2* dp;
    int i4;
    if (idx < PN1)            { src = x;     dp = (__half2*)g_x16;  i4 = idx; }
    else if (idx < PN1 + PN2) { src = qkv_w; dp = (__half2*)g_wqkv; i4 = idx - PN1; }
    else                      { src = out_w; dp = (__half2*)g_wout; i4 = idx - PN1 - PN2; }

    float4 v = ((const float4*)src)[i4];
    dp[2 * i4]     = __floats2half2_rn(v.x, v.y);
    dp[2 * i4 + 1] = __floats2half2_rn(v.z, v.w);
}

// ---------------------------------------------------------------------------
// Warp-mma fp16 GEMM: 128x128 CTA tile, BK=64, 3-stage cp.async, 2 CTAs/SM.
// 8 warps (64x32 each). K=1024 -> 16 chunks.
// B fragments loaded as n-tile PAIRS via ldmatrix.x4 (2 loads/k-step not 4).
// MODE 0: C fp32 = A@B^T + bias (out projection)
// MODE 1: QKV epilogue — bias + RoPE, write q/k/v fp16 in [B,H,S,HD].
// ---------------------------------------------------------------------------
constexpr int GQ_PITCH = 144;
constexpr int GQ_TILE  = 128 * GQ_PITCH;        // 18432
constexpr int GQ_B     = GQ_TILE;
constexpr int GQ_STAGE = 2 * GQ_TILE;           // 36864
constexpr int GQ_SMEM  = 3 * GQ_STAGE;          // 110592

template <int MODE>
__global__ __launch_bounds__(256, 2) void gemm_mma_f16(
    const __half* __restrict__ A16, const __half* __restrict__ B16,
    const float* __restrict__ bias, float* __restrict__ C, int Ndim)
{
    extern __shared__ char smg[];
    const uint32_t sb = smem_to_u32(smg);
    const int tid = threadIdx.x;
    const int lane = tid & 31;
    const int wid = tid >> 5;
    const int rowBase = blockIdx.y * 128;
    const int colBase = blockIdx.x * 128;
    const int wm = (wid >> 2) * 64;
    const int wn = (wid & 3) * 32;

    float acc[4][4][4];
#pragma unroll
    for (int mi = 0; mi < 4; mi++)
#pragma unroll
        for (int ni = 0; ni < 4; ni++)
#pragma unroll
            for (int e = 0; e < 4; e++) acc[mi][ni][e] = 0.f;

    auto issue = [&](int k) {
        const int k0 = k * 64;
        const uint32_t dst = sb + (uint32_t)(k % 3) * GQ_STAGE;
#pragma unroll
        for (int u = 0; u < 4; u++) {
            int lin = u * 256 + tid;
            int r = lin >> 3, seg = lin & 7;
            uint32_t so = r * GQ_PITCH + seg * 16;
            cp16(dst + so, A16 + (size_t)(rowBase + r) * GK + k0 + seg * 8);
            cp16(dst + GQ_B + so, B16 + (size_t)(colBase + r) * GK + k0 + seg * 8);
        }
        cp_commit();
    };

    issue(0);
    issue(1);
    for (int k = 0; k < 16; k++) {
        if (k < 15) asm volatile("cp.async.wait_group 1;" ::: "memory");
        else        asm volatile("cp.async.wait_group 0;" ::: "memory");
        __syncthreads();
        if (k + 2 < 16) issue(k + 2);   // writes stage (k+2)%3 (safe: 3 stages)

        const uint32_t St = sb + (uint32_t)(k % 3) * GQ_STAGE;
#pragma unroll
        for (int ks = 0; ks < 4; ks++) {
            uint4 a[4];
            uint4 bb[2];
            const uint32_t aro = (wm + (lane & 15)) * GQ_PITCH
                               + (ks * 16 + (lane >> 4) * 8) * 2;
#pragma unroll
            for (int mi = 0; mi < 4; mi++)
                ldsm_x4(a[mi], St + aro + mi * 16 * GQ_PITCH);
            // B: two n-tiles per ldsm_x4 (lanes 16-31 address the +8 n-tile)
            const uint32_t bro = (wn + (lane & 7) + (lane >> 4) * 8) * GQ_PITCH
                               + (ks * 16 + ((lane >> 3) & 1) * 8) * 2;
#pragma unroll
            for (int nj = 0; nj < 2; nj++)
                ldsm_x4(bb[nj], St + GQ_B + bro + nj * 16 * GQ_PITCH);
#pragma unroll
            for (int mi = 0; mi < 4; mi++) {
                mmah(acc[mi][0], a[mi], bb[0].x, bb[0].y);
                mmah(acc[mi][1], a[mi], bb[0].z, bb[0].w);
                mmah(acc[mi][2], a[mi], bb[1].x, bb[1].y);
                mmah(acc[mi][3], a[mi], bb[1].z, bb[1].w);
            }
        }
    }

#pragma unroll
    for (int mi = 0; mi < 4; mi++) {
#pragma unroll
        for (int ni = 0; ni < 4; ni++) {
            int r0 = rowBase + wm + mi * 16 + (lane >> 2);
            int col = colBase + wn + ni * 8 + (lane & 3) * 2;
            float b0 = bias[col], b1 = bias[col + 1];
            float v00 = acc[mi][ni][0] + b0, v01 = acc[mi][ni][1] + b1;   // row r0
            float v10 = acc[mi][ni][2] + b0, v11 = acc[mi][ni][3] + b1;   // row r0+8

            if (MODE == 0) {
                *(float2*)&C[(size_t)r0 * Ndim + col] = make_float2(v00, v01);
                *(float2*)&C[(size_t)(r0 + 8) * Ndim + col] = make_float2(v10, v11);
            } else {
                int seg = col >> 10;             // 0=q 1=k 2=v
                int h = (col >> 6) & 15;
                int d = col & 63;
                int i = d >> 1;
                __half* dstBuf = (seg == 0) ? g_q16 : (seg == 1) ? g_k16 : g_v16;
#pragma unroll
                for (int rr = 0; rr < 2; rr++) {
                    int r = r0 + rr * 8;
                    float va = rr ? v10 : v00;
                    float vb = rr ? v11 : v01;
                    int bb2 = r >> 11;
                    int s = r & 2047;
                    size_t dst = (((size_t)(bb2 * Hc + h)) * Sc + s) * HDc + d;
                    if (seg == 2) {
                        *(__half2*)&dstBuf[dst] = __floats2half2_rn(va, vb);
                    } else {
                        float c  = g_cos[s * RHALF + i];
                        float sn = g_sin[s * RHALF + i];
                        *(__half2*)&dstBuf[dst] =
                            __floats2half2_rn(va * c - vb * sn, vb * c + va * sn);
                    }
                }
            }
        }
    }
}

// ---------------------------------------------------------------------------
// Tensor-core flash attention, plain fp16, fp32 accum/softmax.
// 128 q-rows/CTA, 64-key tiles, 8 warps, HD=64. ~55 KB smem.
// K fragments: key-tile pairs via ldsm_x4; V: d-tile pairs via ldsm_x4.trans.
// ---------------------------------------------------------------------------
constexpr int AT_PITCH = 144;
constexpr int AT_Q   = 0;
constexpr int AT_KV  = 128 * AT_PITCH;            // 18432
constexpr int AT_V   = 64 * AT_PITCH;             // offset within buffer
constexpr int AT_KVBUF = 2 * 64 * AT_PITCH;       // 18432 per buffer
constexpr int AT_MSK = AT_KV + 2 * AT_KVBUF;      // 55296
constexpr int AT_SMEM = AT_MSK + 2 * 64 * 4;      // 55808

__global__ __launch_bounds__(256) void attn_mma_kernel(const int* __restrict__ mask)
{
    extern __shared__ char smA[];
    const uint32_t sb = smem_to_u32(smA);
    float* smask = (float*)(smA + AT_MSK);

    const int tid = threadIdx.x;
    const int lane = tid & 31;
    const int wid = tid >> 5;
    const int bh = blockIdx.y;
    const int b = bh >> 4, h = bh & 15;
    const int q0 = blockIdx.x * 128;

    const size_t base = (size_t)bh * Sc * HDc;
    const __half* Qg = g_q16 + base + (size_t)q0 * HDc;
    const __half* Kg = g_k16 + base;
    const __half* Vg = g_v16 + base;
    const int* mg = mask + b * Sc;

#pragma unroll
    for (int u = 0; u < 4; u++) {
        int lin = u * 256 + tid;
        int r = lin >> 3, seg = lin & 7;
        cp16(sb + AT_Q + r * AT_PITCH + seg * 16, Qg + (size_t)r * HDc + seg * 8);
    }

    auto issueKV = [&](int it) {
        const uint32_t dst = sb + AT_KV + (uint32_t)(it & 1) * AT_KVBUF;
        const size_t koff = (size_t)it * 64 * HDc;
#pragma unroll
        for (int u = 0; u < 2; u++) {
            int lin = u * 256 + tid;
            int r = lin >> 3, seg = lin & 7;
            size_t off = koff + (size_t)r * HDc + seg * 8;
            uint32_t so = r * AT_PITCH + seg * 16;
            cp16(dst + so, Kg + off);
            cp16(dst + AT_V + so, Vg + off);
        }
        if (tid < 64) smask[(it & 1) * 64 + tid] = mg[it * 64 + tid] ? 0.f : -1e30f;
        cp_commit();
    };

    issueKV(0);
    issueKV(1);
    asm volatile("cp.async.wait_group 1;" ::: "memory");
    __syncthreads();

    uint4 qf[4];
#pragma unroll
    for (int ks = 0; ks < 4; ks++) {
        uint32_t ro = (wid * 16 + (lane & 15)) * AT_PITCH + (ks * 16 + (lane >> 4) * 8) * 2;
        ldsm_x4(qf[ks], sb + AT_Q + ro);
    }

    float accO[8][4];
#pragma unroll
    for (int nd = 0; nd < 8; nd++)
#pragma unroll
        for (int e = 0; e < 4; e++) accO[nd][e] = 0.f;
    float m0 = -1e30f, m1 = -1e30f, l0 = 0.f, l1 = 0.f;
    const float scale = 0.125f;
    const float LOG2E = 1.4426950408889634f;

    for (int it = 0; it < 32; it++) {
        if (it > 0) {
            if (it == 31) asm volatile("cp.async.wait_group 0;" ::: "memory");
            else          asm volatile("cp.async.wait_group 1;" ::: "memory");
            __syncthreads();
        }
        const uint32_t Kb = sb + AT_KV + (uint32_t)(it & 1) * AT_KVBUF;
        const int mbuf = (it & 1) * 64;

        // ---- S = Q K^T (key-tile pairs via ldsm_x4) ----
        float s[8][4];
#pragma unroll
        for (int ni = 0; ni < 8; ni++)
#pragma unroll
            for (int e = 0; e < 4; e++) s[ni][e] = 0.f;
#pragma unroll
        for (int ks = 0; ks < 4; ks++) {
            uint4 bk[4];
            uint32_t ro = ((lane & 7) + (lane >> 4) * 8) * AT_PITCH
                        + (ks * 16 + ((lane >> 3) & 1) * 8) * 2;
#pragma unroll
            for (int nj = 0; nj < 4; nj++)
                ldsm_x4(bk[nj], Kb + ro + nj * 16 * AT_PITCH);
#pragma unroll
            for (int nj = 0; nj < 4; nj++) {
                mmah(s[2 * nj],     qf[ks], bk[nj].x, bk[nj].y);
                mmah(s[2 * nj + 1], qf[ks], bk[nj].z, bk[nj].w);
            }
        }

        // ---- scale + mask ----
#pragma unroll
        for (int ni = 0; ni < 8; ni++) {
            float b0 = smask[mbuf + ni * 8 + (lane & 3) * 2];
            float b1 = smask[mbuf + ni * 8 + (lane & 3) * 2 + 1];
            s[ni][0] = s[ni][0] * scale + b0;
            s[ni][1] = s[ni][1] * scale + b1;
            s[ni][2] = s[ni][2] * scale + b0;
            s[ni][3] = s[ni][3] * scale + b1;
        }

        // ---- online softmax ----
        float mx0 = -1e30f, mx1 = -1e30f;
#pragma unroll
        for (int ni = 0; ni < 8; ni++) {
            mx0 = fmaxf(mx0, fmaxf(s[ni][0], s[ni][1]));
            mx1 = fmaxf(mx1, fmaxf(s[ni][2], s[ni][3]));
        }
        mx0 = fmaxf(mx0, __shfl_xor_sync(0xffffffffu, mx0, 1));
        mx0 = fmaxf(mx0, __shfl_xor_sync(0xffffffffu, mx0, 2));
        mx1 = fmaxf(mx1, __shfl_xor_sync(0xffffffffu, mx1, 1));
        mx1 = fmaxf(mx1, __shfl_xor_sync(0xffffffffu, mx1, 2));
        float mn0 = fmaxf(m0, mx0), mn1 = fmaxf(m1, mx1);
        float al0 = ex2f((m0 - mn0) * LOG2E);
        float al1 = ex2f((m1 - mn1) * LOG2E);
        float sum0 = 0.f, sum1 = 0.f;
#pragma unroll
        for (int ni = 0; ni < 8; ni++) {
            s[ni][0] = ex2f((s[ni][0] - mn0) * LOG2E);
            s[ni][1] = ex2f((s[ni][1] - mn0) * LOG2E);
            s[ni][2] = ex2f((s[ni][2] - mn1) * LOG2E);
            s[ni][3] = ex2f((s[ni][3] - mn1) * LOG2E);
            sum0 += s[ni][0] + s[ni][1];
            sum1 += s[ni][2] + s[ni][3];
        }
        sum0 += __shfl_xor_sync(0xffffffffu, sum0, 1);
        sum0 += __shfl_xor_sync(0xffffffffu, sum0, 2);
        sum1 += __shfl_xor_sync(0xffffffffu, sum1, 1);
        sum1 += __shfl_xor_sync(0xffffffffu, sum1, 2);
        l0 = l0 * al0 + sum0;
        l1 = l1 * al1 + sum1;
        m0 = mn0; m1 = mn1;
#pragma unroll
        for (int nd = 0; nd < 8; nd++) {
            accO[nd][0] *= al0; accO[nd][1] *= al0;
            accO[nd][2] *= al1; accO[nd][3] *= al1;
        }

        // ---- P fragments (fp16) from S accumulators ----
        uint4 ap[4];
#pragma unroll
        for (int ks2 = 0; ks2 < 4; ks2++) {
            const float* p0 = s[2 * ks2];
            const float* p1 = s[2 * ks2 + 1];
            ap[ks2].x = packh(p0[0], p0[1]);
            ap[ks2].y = packh(p0[2], p0[3]);
            ap[ks2].z = packh(p1[0], p1[1]);
            ap[ks2].w = packh(p1[2], p1[3]);
        }

        // ---- O += P V (d-tile pairs via ldsm_x4.trans) ----
#pragma unroll
        for (int ks2 = 0; ks2 < 4; ks2++) {
            uint4 bv[4];
            uint32_t rbase = (ks2 * 16 + (lane & 15)) * AT_PITCH + (lane >> 4) * 16;
#pragma unroll
            for (int nd2 = 0; nd2 < 4; nd2++)
                ldsm_x4t(bv[nd2], Kb + AT_V + rbase + nd2 * 32);
#pragma unroll
            for (int nd2 = 0; nd2 < 4; nd2++) {
                mmah(accO[2 * nd2],     ap[ks2], bv[nd2].x, bv[nd2].y);
                mmah(accO[2 * nd2 + 1], ap[ks2], bv[nd2].z, bv[nd2].w);
            }
        }

        __syncthreads();
        if (it + 2 < 32) issueKV(it + 2);
    }

    float inv0 = 1.f / l0, inv1 = 1.f / l1;
    int r0 = q0 + wid * 16 + (lane >> 2);
    int colb = h * HDc + (lane & 3) * 2;
#pragma unroll
    for (int nd = 0; nd < 8; nd++) {
        float c00 = accO[nd][0] * inv0, c01 = accO[nd][1] * inv0;
        float c10 = accO[nd][2] * inv1, c11 = accO[nd][3] * inv1;
        size_t i0 = (size_t)(b * Sc + r0) * Ec + colb + nd * 8;
        size_t i1 = (size_t)(b * Sc + r0 + 8) * Ec + colb + nd * 8;
        *(__half2*)&g_ctx16[i0] = __floats2half2_rn(c00, c01);
        *(__half2*)&g_ctx16[i1] = __floats2half2_rn(c10, c11);
    }
}

// ---------------------------------------------------------------------------
extern "C" void kernel_launch(void* const* d_in, const int* in_sizes, int n_in,
                              void* d_out, int out_size)
{
    const float* x     = (const float*)d_in[0];
    const int*   mask  = (const int*)d_in[1];
    const float* qkv_w = (const float*)d_in[2];
    const float* qkv_b = (const float*)d_in[3];
    const float* out_w = (const float*)d_in[4];
    const float* out_b = (const float*)d_in[5];
    float* out = (float*)d_out;

    __half *x16, *w16, *ow16, *c16;
    cudaGetSymbolAddress((void**)&x16,  g_x16);
    cudaGetSymbolAddress((void**)&w16,  g_wqkv);
    cudaGetSymbolAddress((void**)&ow16, g_wout);
    cudaGetSymbolAddress((void**)&c16,  g_ctx16);

    cudaFuncSetAttribute(gemm_mma_f16<0>,
                         cudaFuncAttributeMaxDynamicSharedMemorySize, GQ_SMEM);
    cudaFuncSetAttribute(gemm_mma_f16<1>,
                         cudaFuncAttributeMaxDynamicSharedMemorySize, GQ_SMEM);
    cudaFuncSetAttribute(attn_mma_kernel,
                         cudaFuncAttributeMaxDynamicSharedMemorySize, AT_SMEM);

    // 1. Converts + RoPE table (one launch)
    prep_kernel<<<(PTOT + 255) / 256, 256>>>(x, qkv_w, out_w);

    // 2. QKV projection with fused bias+RoPE epilogue -> q/k/v fp16 [B,H,S,HD]
    gemm_mma_f16<1><<<dim3(NQKV / 128, Mc / 128), 256, GQ_SMEM>>>(
        x16, w16, qkv_b, nullptr, NQKV);

    // 3. Tensor-core flash attention -> ctx fp16
    attn_mma_kernel<<<dim3(Sc / 128, Bc * Hc), 256, AT_SMEM>>>(mask);

    // 4. Output projection -> fp32 out
    gemm_mma_f16<0><<<dim3(Ec / 128, Mc / 128), 256, GQ_SMEM>>>(
        c16, ow16, out_b, out, Ec);
}